// round 6
// baseline (speedup 1.0000x reference)
#include <cuda_runtime.h>
#include <math_constants.h>
#include <cstdint>

#define B_   2
#define L_   2048
#define E_   1024
#define H_   16
#define D_   64
#define DFF_ 4096
#define M_   (B_ * L_)   // 4096 tokens

// ---------------- scratch (device globals: allocation-guard safe) ----------------
__device__ float g_h[M_ * E_];
__device__ float g_qkv[(size_t)M_ * 3 * H_ * D_];
__device__ float g_ctx[M_ * H_ * D_];
__device__ float g_x[M_ * E_];
__device__ float g_gate[(size_t)M_ * DFF_];
__device__ float g_val[(size_t)M_ * DFF_];

// ---------------- rmsnorm ----------------
__global__ __launch_bounds__(256) void rmsnorm_kernel(const float* __restrict__ x,
                                                      float* __restrict__ y) {
    int row = blockIdx.x;
    float4 a = ((const float4*)(x + (size_t)row * E_))[threadIdx.x];
    float ss = a.x * a.x + a.y * a.y + a.z * a.z + a.w * a.w;
    __shared__ float red[8];
    __shared__ float sinv;
#pragma unroll
    for (int o = 16; o > 0; o >>= 1) ss += __shfl_xor_sync(0xffffffffu, ss, o);
    if ((threadIdx.x & 31) == 0) red[threadIdx.x >> 5] = ss;
    __syncthreads();
    if (threadIdx.x == 0) {
        float t = 0.f;
#pragma unroll
        for (int i = 0; i < 8; i++) t += red[i];
        sinv = rsqrtf(t * (1.0f / E_));
    }
    __syncthreads();
    float c = sinv;
    float4 o = make_float4(a.x * c, a.y * c, a.z * c, a.w * c);
    ((float4*)(y + (size_t)row * E_))[threadIdx.x] = o;
}

// ---------------- fused: x = x + rmsnorm(x);  h = rmsnorm(x) ----------------
__global__ __launch_bounds__(256) void addnorm_kernel(float* __restrict__ x,
                                                      float* __restrict__ h) {
    int row = blockIdx.x;
    float4 a = ((const float4*)(x + (size_t)row * E_))[threadIdx.x];
    __shared__ float red[8];
    __shared__ float sval;
    float ss = a.x * a.x + a.y * a.y + a.z * a.z + a.w * a.w;
#pragma unroll
    for (int o = 16; o > 0; o >>= 1) ss += __shfl_xor_sync(0xffffffffu, ss, o);
    if ((threadIdx.x & 31) == 0) red[threadIdx.x >> 5] = ss;
    __syncthreads();
    if (threadIdx.x == 0) {
        float t = 0.f;
#pragma unroll
        for (int i = 0; i < 8; i++) t += red[i];
        sval = 1.0f + rsqrtf(t * (1.0f / E_));
    }
    __syncthreads();
    float c = sval;
    a.x *= c; a.y *= c; a.z *= c; a.w *= c;
    float ss2 = a.x * a.x + a.y * a.y + a.z * a.z + a.w * a.w;
#pragma unroll
    for (int o = 16; o > 0; o >>= 1) ss2 += __shfl_xor_sync(0xffffffffu, ss2, o);
    if ((threadIdx.x & 31) == 0) red[threadIdx.x >> 5] = ss2;
    __syncthreads();
    if (threadIdx.x == 0) {
        float t = 0.f;
#pragma unroll
        for (int i = 0; i < 8; i++) t += red[i];
        sval = rsqrtf(t * (1.0f / E_));
    }
    __syncthreads();
    float inv2 = sval;
    ((float4*)(x + (size_t)row * E_))[threadIdx.x] = a;
    float4 o = make_float4(a.x * inv2, a.y * inv2, a.z * inv2, a.w * inv2);
    ((float4*)(h + (size_t)row * E_))[threadIdx.x] = o;
}

// ---------------- geglu ----------------
__global__ __launch_bounds__(256) void geglu_kernel(float* __restrict__ g,
                                                    const float* __restrict__ v) {
    int i = blockIdx.x * 256 + threadIdx.x;
    float x = g[i];
    float gel = 0.5f * x * (1.0f + erff(x * 0.70710678118654752f));
    g[i] = gel * v[i];
}

// ================= tf32 mma helpers =================
__device__ __forceinline__ uint32_t f2r(float f) { return __float_as_uint(f); }

__device__ __forceinline__ void mma_tf32(float* d, const uint32_t* a, const uint32_t* b) {
    asm volatile(
        "mma.sync.aligned.m16n8k8.row.col.f32.tf32.tf32.f32 "
        "{%0,%1,%2,%3}, {%4,%5,%6,%7}, {%8,%9}, {%0,%1,%2,%3};\n"
        : "+f"(d[0]), "+f"(d[1]), "+f"(d[2]), "+f"(d[3])
        : "r"(a[0]), "r"(a[1]), "r"(a[2]), "r"(a[3]), "r"(b[0]), "r"(b[1]));
}

__device__ __forceinline__ void ldsm4(uint32_t* r, uint32_t saddr) {
    asm volatile("ldmatrix.sync.aligned.m8n8.x4.shared.b16 {%0,%1,%2,%3}, [%4];"
                 : "=r"(r[0]), "=r"(r[1]), "=r"(r[2]), "=r"(r[3]) : "r"(saddr));
}

// ================= tf32 tensor-core GEMM (3-stage cp.async pipeline) =================
#define BM 128
#define BN 128
#define BK 32
#define NSTAGE 3
#define APAD 4
#define BPAD 8
#define ASTRIDE (BK + APAD)           // 36 floats = 144B rows
#define BSTRIDE (BN + BPAD)           // 136
#define STAGE_F (BM * ASTRIDE + BK * BSTRIDE)               // floats per stage: 8960
#define TG_SMEM (NSTAGE * STAGE_F * 4)                      // 107520 B

// B2 != nullptr => dual-output mode: blockIdx.z selects (B,C) vs (B2,C2).
__global__ __launch_bounds__(256, 2) void tgemm_kernel(
    int M, int N, int K,
    const float* __restrict__ A, const float* __restrict__ B,
    const float* __restrict__ bias, const float* __restrict__ res,
    float* __restrict__ C,
    const float* __restrict__ B2, float* __restrict__ C2) {
    extern __shared__ float sm[];

    if (B2 && blockIdx.z) { B = B2; C = C2; }

    const int tid  = threadIdx.x;
    const int bm   = blockIdx.y * BM;
    const int bn   = blockIdx.x * BN;
    const int warp = tid >> 5, lane = tid & 31;
    const int wm   = (warp >> 2) * 64;
    const int wn   = (warp & 3) * 32;
    const int fr   = lane >> 2;
    const int fc   = lane & 3;

    const int lg   = lane >> 3;
    const int lrow = ((lg & 1) << 3) + (lane & 7);
    const int lcol = (lg >> 1) << 2;

    const int ar = tid >> 3;
    const int ac = (tid & 7) * 4;
    const int br = tid >> 5;
    const int bc = (tid & 31) * 4;

    float acc[4][4][4];
#pragma unroll
    for (int i = 0; i < 4; i++)
#pragma unroll
        for (int j = 0; j < 4; j++)
#pragma unroll
            for (int k = 0; k < 4; k++) acc[i][j][k] = 0.f;

    auto issue_loads = [&](int s, int kt) {
        float* Ad = sm + s * STAGE_F;
        float* Bd = Ad + BM * ASTRIDE;
#pragma unroll
        for (int p = 0; p < 4; p++) {
            int row = p * 32 + ar;
            uint32_t dst = (uint32_t)__cvta_generic_to_shared(Ad + row * ASTRIDE + ac);
            const float* src = A + (size_t)(bm + row) * K + kt + ac;
            asm volatile("cp.async.cg.shared.global [%0], [%1], 16;\n" :: "r"(dst), "l"(src));
        }
#pragma unroll
        for (int p = 0; p < 4; p++) {
            int row = p * 8 + br;
            uint32_t dst = (uint32_t)__cvta_generic_to_shared(Bd + row * BSTRIDE + bc);
            const float* src = B + (size_t)(kt + row) * N + bn + bc;
            asm volatile("cp.async.cg.shared.global [%0], [%1], 16;\n" :: "r"(dst), "l"(src));
        }
        asm volatile("cp.async.commit_group;\n");
    };

    auto compute_tile = [&](int s) {
        const float* Ab = sm + s * STAGE_F;
        const float* Bb = Ab + BM * ASTRIDE;
        uint32_t abase = (uint32_t)__cvta_generic_to_shared(Ab + (wm + lrow) * ASTRIDE + lcol);
#pragma unroll
        for (int ks = 0; ks < 4; ks++) {
            const int k0 = ks * 8;
            uint32_t af[4][4], bf[4][2];
#pragma unroll
            for (int mi = 0; mi < 4; mi++)
                ldsm4(af[mi], abase + (mi * 16 * ASTRIDE + k0) * 4);
#pragma unroll
            for (int ni = 0; ni < 4; ni++) {
                int n = wn + ni * 8 + fr;
                bf[ni][0] = f2r(Bb[(k0 + fc) * BSTRIDE + n]);
                bf[ni][1] = f2r(Bb[(k0 + fc + 4) * BSTRIDE + n]);
            }
#pragma unroll
            for (int mi = 0; mi < 4; mi++)
#pragma unroll
                for (int ni = 0; ni < 4; ni++) mma_tf32(acc[mi][ni], af[mi], bf[ni]);
        }
    };

    const int kiters = K / BK;   // >= 32 for every call site
    issue_loads(0, 0);
    issue_loads(1, BK);

#pragma unroll 1
    for (int it = 0; it < kiters; ++it) {
        // group `it` must be complete before compute; deeper groups may be pending
        if (it + 1 < kiters) {
            asm volatile("cp.async.wait_group 1;\n");
        } else {
            asm volatile("cp.async.wait_group 0;\n");
        }
        __syncthreads();   // also guarantees stage (it+2)%3 fully consumed before refill
        if (it + 2 < kiters) issue_loads((it + 2) % NSTAGE, (it + 2) * BK);
        compute_tile(it % NSTAGE);
    }

#pragma unroll
    for (int mi = 0; mi < 4; mi++) {
#pragma unroll
        for (int ni = 0; ni < 4; ni++) {
            int gr = bm + wm + mi * 16 + fr;
            int gc = bn + wn + ni * 8 + fc * 2;
            float2 o0 = make_float2(acc[mi][ni][0], acc[mi][ni][1]);
            float2 o1 = make_float2(acc[mi][ni][2], acc[mi][ni][3]);
            if (bias) {
                float2 bv = *(const float2*)(bias + gc);
                o0.x += bv.x; o0.y += bv.y;
                o1.x += bv.x; o1.y += bv.y;
            }
            if (res) {
                float2 r0 = *(const float2*)(res + (size_t)gr * N + gc);
                float2 r1 = *(const float2*)(res + (size_t)(gr + 8) * N + gc);
                o0.x += r0.x; o0.y += r0.y;
                o1.x += r1.x; o1.y += r1.y;
            }
            *(float2*)(C + (size_t)gr * N + gc) = o0;
            *(float2*)(C + (size_t)(gr + 8) * N + gc) = o1;
        }
    }
}

// ================= tf32 tensor-core flash attention =================
#define PQ_STRIDE 68   // == 4 mod 32 -> conflict-free A-fragment/LDSM reads
#define KV_STRIDE 72   // == 8 mod 32 -> conflict-free B-fragment reads
#define ATT_SMEM ((64 * PQ_STRIDE * 2 + 64 * KV_STRIDE * 2) * 4)  // 71680 B

__global__ __launch_bounds__(128) void attn_kernel(const float* __restrict__ qkv,
                                                   float* __restrict__ ctx) {
    extern __shared__ float smr[];
    float* Qs = smr;                         // [64][68]
    float* Ps = Qs + 64 * PQ_STRIDE;         // [64][68]
    float* Ks = Ps + 64 * PQ_STRIDE;         // [64(d)][72(key)]  (transposed)
    float* Vs = Ks + 64 * KV_STRIDE;         // [64(key)][72(d)]

    const int qt = blockIdx.x, h = blockIdx.y, b = blockIdx.z;
    const int m0 = qt * 64;
    const int tid  = threadIdx.x;
    const int warp = tid >> 5, lane = tid & 31;
    const int fr = lane >> 2, fc = lane & 3;
    const int w16 = warp * 16;
    const int lg   = lane >> 3;
    const int lrow = ((lg & 1) << 3) + (lane & 7);
    const int lcol = (lg >> 1) << 2;
    const float slope = exp2f(-(1.0f + 7.0f * (float)h / 15.0f));

    for (int i = tid; i < 64 * 16; i += 128) {
        int r = i >> 4, c = (i & 15) << 2;
        float4 v = *(const float4*)(qkv + ((((size_t)(b * L_ + m0 + r) * H_ + h) * 3 + 0) * D_ + c));
        Qs[r * PQ_STRIDE + c + 0] = v.x * 0.125f;
        Qs[r * PQ_STRIDE + c + 1] = v.y * 0.125f;
        Qs[r * PQ_STRIDE + c + 2] = v.z * 0.125f;
        Qs[r * PQ_STRIDE + c + 3] = v.w * 0.125f;
    }
    __syncthreads();

    const uint32_t qbase = (uint32_t)__cvta_generic_to_shared(Qs + (w16 + lrow) * PQ_STRIDE + lcol);
    const uint32_t pbase = (uint32_t)__cvta_generic_to_shared(Ps + (w16 + lrow) * PQ_STRIDE + lcol);

    uint32_t qf[8][4];
#pragma unroll
    for (int ks = 0; ks < 8; ks++) ldsm4(qf[ks], qbase + ks * 8 * 4);

    float oacc[8][4];
#pragma unroll
    for (int i = 0; i < 8; i++)
#pragma unroll
        for (int j = 0; j < 4; j++) oacc[i][j] = 0.f;
    float mrow0 = -CUDART_INF_F, mrow1 = -CUDART_INF_F;
    float lrow0 = 0.f, lrow1 = 0.f;

    const int gi0 = m0 + w16 + fr;
    const int gi1 = gi0 + 8;

    for (int kt = 0; kt <= qt; kt++) {
        const int n0 = kt * 64;
        __syncthreads();
        for (int i = tid; i < 64 * 16; i += 128) {
            int r = i >> 4, c = (i & 15) << 2;
            size_t base = ((size_t)(b * L_ + n0 + r) * H_ + h) * 3;
            float4 kv = *(const float4*)(qkv + (base + 1) * D_ + c);
            float4 vv = *(const float4*)(qkv + (base + 2) * D_ + c);
            Ks[(c + 0) * KV_STRIDE + r] = kv.x;
            Ks[(c + 1) * KV_STRIDE + r] = kv.y;
            Ks[(c + 2) * KV_STRIDE + r] = kv.z;
            Ks[(c + 3) * KV_STRIDE + r] = kv.w;
            Vs[r * KV_STRIDE + c + 0] = vv.x;
            Vs[r * KV_STRIDE + c + 1] = vv.y;
            Vs[r * KV_STRIDE + c + 2] = vv.z;
            Vs[r * KV_STRIDE + c + 3] = vv.w;
        }
        __syncthreads();

        float sacc[8][4];
#pragma unroll
        for (int i = 0; i < 8; i++)
#pragma unroll
            for (int j = 0; j < 4; j++) sacc[i][j] = 0.f;
#pragma unroll
        for (int ks = 0; ks < 8; ks++) {
            int k0 = ks * 8;
            uint32_t bf[8][2];
#pragma unroll
            for (int ni = 0; ni < 8; ni++) {
                int n = ni * 8 + fr;
                bf[ni][0] = f2r(Ks[(k0 + fc) * KV_STRIDE + n]);
                bf[ni][1] = f2r(Ks[(k0 + fc + 4) * KV_STRIDE + n]);
            }
#pragma unroll
            for (int ni = 0; ni < 8; ni++) mma_tf32(sacc[ni], qf[ks], bf[ni]);
        }

#pragma unroll
        for (int ni = 0; ni < 8; ni++) {
            int gj = n0 + ni * 8 + 2 * fc;
            float a0 = slope * (float)(gj - gi0);
            float a1 = slope * (float)(gj + 1 - gi0);
            float a2 = slope * (float)(gj - gi1);
            float a3 = slope * (float)(gj + 1 - gi1);
            sacc[ni][0] = (gj     > gi0) ? -CUDART_INF_F : sacc[ni][0] + a0;
            sacc[ni][1] = (gj + 1 > gi0) ? -CUDART_INF_F : sacc[ni][1] + a1;
            sacc[ni][2] = (gj     > gi1) ? -CUDART_INF_F : sacc[ni][2] + a2;
            sacc[ni][3] = (gj + 1 > gi1) ? -CUDART_INF_F : sacc[ni][3] + a3;
        }

        float mx0 = -CUDART_INF_F, mx1 = -CUDART_INF_F;
#pragma unroll
        for (int ni = 0; ni < 8; ni++) {
            mx0 = fmaxf(mx0, fmaxf(sacc[ni][0], sacc[ni][1]));
            mx1 = fmaxf(mx1, fmaxf(sacc[ni][2], sacc[ni][3]));
        }
        mx0 = fmaxf(mx0, __shfl_xor_sync(0xffffffffu, mx0, 1));
        mx0 = fmaxf(mx0, __shfl_xor_sync(0xffffffffu, mx0, 2));
        mx1 = fmaxf(mx1, __shfl_xor_sync(0xffffffffu, mx1, 1));
        mx1 = fmaxf(mx1, __shfl_xor_sync(0xffffffffu, mx1, 2));
        float mn0 = fmaxf(mrow0, mx0);
        float mn1 = fmaxf(mrow1, mx1);
        float alpha0 = __expf(mrow0 - mn0);
        float alpha1 = __expf(mrow1 - mn1);
        float rs0 = 0.f, rs1 = 0.f;
#pragma unroll
        for (int ni = 0; ni < 8; ni++) {
            sacc[ni][0] = __expf(sacc[ni][0] - mn0);
            sacc[ni][1] = __expf(sacc[ni][1] - mn0);
            sacc[ni][2] = __expf(sacc[ni][2] - mn1);
            sacc[ni][3] = __expf(sacc[ni][3] - mn1);
            rs0 += sacc[ni][0] + sacc[ni][1];
            rs1 += sacc[ni][2] + sacc[ni][3];
        }
        rs0 += __shfl_xor_sync(0xffffffffu, rs0, 1);
        rs0 += __shfl_xor_sync(0xffffffffu, rs0, 2);
        rs1 += __shfl_xor_sync(0xffffffffu, rs1, 1);
        rs1 += __shfl_xor_sync(0xffffffffu, rs1, 2);
        lrow0 = lrow0 * alpha0 + rs0;
        lrow1 = lrow1 * alpha1 + rs1;
        mrow0 = mn0;
        mrow1 = mn1;
#pragma unroll
        for (int ni = 0; ni < 8; ni++) {
            oacc[ni][0] *= alpha0;
            oacc[ni][1] *= alpha0;
            oacc[ni][2] *= alpha1;
            oacc[ni][3] *= alpha1;
        }

#pragma unroll
        for (int ni = 0; ni < 8; ni++) {
            int c = ni * 8 + 2 * fc;
            *(float2*)&Ps[(w16 + fr) * PQ_STRIDE + c]     = make_float2(sacc[ni][0], sacc[ni][1]);
            *(float2*)&Ps[(w16 + fr + 8) * PQ_STRIDE + c] = make_float2(sacc[ni][2], sacc[ni][3]);
        }
        __syncwarp();

#pragma unroll
        for (int ks = 0; ks < 8; ks++) {
            int k0 = ks * 8;
            uint32_t af[4];
            ldsm4(af, pbase + k0 * 4);
#pragma unroll
            for (int ni = 0; ni < 8; ni++) {
                uint32_t bf[2];
                int n = ni * 8 + fr;
                bf[0] = f2r(Vs[(k0 + fc) * KV_STRIDE + n]);
                bf[1] = f2r(Vs[(k0 + fc + 4) * KV_STRIDE + n]);
                mma_tf32(oacc[ni], af, bf);
            }
        }
        __syncwarp();
    }

    float inv0 = 1.0f / lrow0;
    float inv1 = 1.0f / lrow1;
#pragma unroll
    for (int ni = 0; ni < 8; ni++) {
        int c = h * D_ + ni * 8 + 2 * fc;
        *(float2*)(ctx + (size_t)(b * L_ + gi0) * (H_ * D_) + c) =
            make_float2(oacc[ni][0] * inv0, oacc[ni][1] * inv0);
        *(float2*)(ctx + (size_t)(b * L_ + gi1) * (H_ * D_) + c) =
            make_float2(oacc[ni][2] * inv1, oacc[ni][3] * inv1);
    }
}

// ---------------- launch ----------------
extern "C" void kernel_launch(void* const* d_in, const int* in_sizes, int n_in,
                              void* d_out, int out_size) {
    (void)in_sizes; (void)n_in; (void)out_size;
    const float* X    = (const float*)d_in[0];
    const float* Wqkv = (const float*)d_in[2];
    const float* bqkv = (const float*)d_in[3];
    const float* Wo   = (const float*)d_in[4];
    const float* bo   = (const float*)d_in[5];
    const float* Ww   = (const float*)d_in[12];
    const float* Wv   = (const float*)d_in[13];
    const float* Wout = (const float*)d_in[14];
    float* out = (float*)d_out;

    float *h_p, *qkv_p, *ctx_p, *x_p, *g_p, *v_p;
    cudaGetSymbolAddress((void**)&h_p,   g_h);
    cudaGetSymbolAddress((void**)&qkv_p, g_qkv);
    cudaGetSymbolAddress((void**)&ctx_p, g_ctx);
    cudaGetSymbolAddress((void**)&x_p,   g_x);
    cudaGetSymbolAddress((void**)&g_p,   g_gate);
    cudaGetSymbolAddress((void**)&v_p,   g_val);

    cudaFuncSetAttribute(attn_kernel, cudaFuncAttributeMaxDynamicSharedMemorySize, ATT_SMEM);
    cudaFuncSetAttribute(tgemm_kernel, cudaFuncAttributeMaxDynamicSharedMemorySize, TG_SMEM);

    // 1. h = rmsnorm(X)
    rmsnorm_kernel<<<M_, 256>>>(X, h_p);
    // 2. qkv = h @ Wqkv + bqkv
    tgemm_kernel<<<dim3(3 * H_ * D_ / BN, M_ / BM), 256, TG_SMEM>>>(
        M_, 3 * H_ * D_, E_, h_p, Wqkv, bqkv, nullptr, qkv_p, nullptr, nullptr);
    // 3. attention (tf32 mma flash)
    attn_kernel<<<dim3(L_ / 64, H_, B_), 128, ATT_SMEM>>>(qkv_p, ctx_p);
    // 4. x = X + ctx @ Wo + bo
    tgemm_kernel<<<dim3(E_ / BN, M_ / BM), 256, TG_SMEM>>>(
        M_, E_, H_ * D_, ctx_p, Wo, bo, X, x_p, nullptr, nullptr);
    // 5+6. x = x + rmsnorm(x); h = rmsnorm(x)
    addnorm_kernel<<<M_, 256>>>(x_p, h_p);
    // 7. gate = h @ Ww ; val = h @ Wv  (single dual-output launch, z selects)
    tgemm_kernel<<<dim3(DFF_ / BN, M_ / BM, 2), 256, TG_SMEM>>>(
        M_, DFF_, E_, h_p, Ww, nullptr, nullptr, g_p, Wv, v_p);
    // 8. gate = gelu(gate) * val
    geglu_kernel<<<(M_ * DFF_) / 256, 256>>>(g_p, v_p);
    // 9. out = x + gate @ Wout
    tgemm_kernel<<<dim3(E_ / BN, M_ / BM), 256, TG_SMEM>>>(
        M_, E_, DFF_, g_p, Wout, nullptr, x_p, out, nullptr, nullptr);
}

// round 9
// speedup vs baseline: 1.2530x; 1.2530x over previous
#include <cuda_runtime.h>
#include <cuda_fp16.h>
#include <math_constants.h>
#include <cstdint>

#define B_   2
#define L_   2048
#define E_   1024
#define H_   16
#define D_   64
#define DFF_ 4096
#define M_   (B_ * L_)   // 4096 tokens
#define HD_  (H_ * D_)   // 1024

// ---------------- scratch (device globals: allocation-guard safe) ----------------
__device__ float  g_qkv[(size_t)M_ * 3 * HD_];
__device__ float  g_x[M_ * E_];
__device__ float  g_gate[(size_t)M_ * DFF_];
__device__ float  g_val[(size_t)M_ * DFF_];
__device__ __half g_h16[M_ * E_];
__device__ __half g_ctx16[M_ * HD_];
__device__ __half g_gg16[(size_t)M_ * DFF_];
// fp16 weights
__device__ __half g_wqkv16[(size_t)E_ * 3 * HD_];
__device__ __half g_wo16[(size_t)HD_ * E_];
__device__ __half g_ww16[(size_t)E_ * DFF_];
__device__ __half g_wv16[(size_t)E_ * DFF_];
__device__ __half g_wout16[(size_t)DFF_ * E_];

// __half2 bit-pattern helper (no __half2_as_uint intrinsic in this toolkit)
__device__ __forceinline__ uint32_t h2u(__half2 h) {
    return *reinterpret_cast<uint32_t*>(&h);
}

// ---------------- fp32 -> fp16 conversion ----------------
__global__ __launch_bounds__(256) void f2h_kernel(const float* __restrict__ src,
                                                  __half* __restrict__ dst) {
    int i = blockIdx.x * 256 + threadIdx.x;
    float4 v = ((const float4*)src)[i];
    uint2 o = make_uint2(h2u(__floats2half2_rn(v.x, v.y)),
                         h2u(__floats2half2_rn(v.z, v.w)));
    ((uint2*)dst)[i] = o;
}

// ---------------- rmsnorm (fp16 out) ----------------
__global__ __launch_bounds__(256) void rmsnorm_kernel(const float* __restrict__ x,
                                                      __half* __restrict__ y) {
    int row = blockIdx.x;
    float4 a = ((const float4*)(x + (size_t)row * E_))[threadIdx.x];
    float ss = a.x * a.x + a.y * a.y + a.z * a.z + a.w * a.w;
    __shared__ float red[8];
    __shared__ float sinv;
#pragma unroll
    for (int o = 16; o > 0; o >>= 1) ss += __shfl_xor_sync(0xffffffffu, ss, o);
    if ((threadIdx.x & 31) == 0) red[threadIdx.x >> 5] = ss;
    __syncthreads();
    if (threadIdx.x == 0) {
        float t = 0.f;
#pragma unroll
        for (int i = 0; i < 8; i++) t += red[i];
        sinv = rsqrtf(t * (1.0f / E_));
    }
    __syncthreads();
    float c = sinv;
    ((uint2*)(y + (size_t)row * E_))[threadIdx.x] =
        make_uint2(h2u(__floats2half2_rn(a.x * c, a.y * c)),
                   h2u(__floats2half2_rn(a.z * c, a.w * c)));
}

// ---------------- fused: x = x + rmsnorm(x); h16 = rmsnorm(x) ----------------
__global__ __launch_bounds__(256) void addnorm_kernel(float* __restrict__ x,
                                                      __half* __restrict__ h) {
    int row = blockIdx.x;
    float4 a = ((const float4*)(x + (size_t)row * E_))[threadIdx.x];
    __shared__ float red[8];
    __shared__ float sval;
    float ss = a.x * a.x + a.y * a.y + a.z * a.z + a.w * a.w;
#pragma unroll
    for (int o = 16; o > 0; o >>= 1) ss += __shfl_xor_sync(0xffffffffu, ss, o);
    if ((threadIdx.x & 31) == 0) red[threadIdx.x >> 5] = ss;
    __syncthreads();
    if (threadIdx.x == 0) {
        float t = 0.f;
#pragma unroll
        for (int i = 0; i < 8; i++) t += red[i];
        sval = 1.0f + rsqrtf(t * (1.0f / E_));
    }
    __syncthreads();
    float c = sval;
    a.x *= c; a.y *= c; a.z *= c; a.w *= c;
    float ss2 = a.x * a.x + a.y * a.y + a.z * a.z + a.w * a.w;
#pragma unroll
    for (int o = 16; o > 0; o >>= 1) ss2 += __shfl_xor_sync(0xffffffffu, ss2, o);
    if ((threadIdx.x & 31) == 0) red[threadIdx.x >> 5] = ss2;
    __syncthreads();
    if (threadIdx.x == 0) {
        float t = 0.f;
#pragma unroll
        for (int i = 0; i < 8; i++) t += red[i];
        sval = rsqrtf(t * (1.0f / E_));
    }
    __syncthreads();
    float inv2 = sval;
    ((float4*)(x + (size_t)row * E_))[threadIdx.x] = a;
    ((uint2*)(h + (size_t)row * E_))[threadIdx.x] =
        make_uint2(h2u(__floats2half2_rn(a.x * inv2, a.y * inv2)),
                   h2u(__floats2half2_rn(a.z * inv2, a.w * inv2)));
}

// ---------------- geglu (fp16 out) ----------------
__global__ __launch_bounds__(256) void geglu_kernel(const float* __restrict__ g,
                                                    const float* __restrict__ v,
                                                    __half* __restrict__ o) {
    int i = (blockIdx.x * 256 + threadIdx.x) * 4;
    float4 gv = *(const float4*)(g + i);
    float4 vv = *(const float4*)(v + i);
    float r0 = 0.5f * gv.x * (1.0f + erff(gv.x * 0.70710678118654752f)) * vv.x;
    float r1 = 0.5f * gv.y * (1.0f + erff(gv.y * 0.70710678118654752f)) * vv.y;
    float r2 = 0.5f * gv.z * (1.0f + erff(gv.z * 0.70710678118654752f)) * vv.z;
    float r3 = 0.5f * gv.w * (1.0f + erff(gv.w * 0.70710678118654752f)) * vv.w;
    *(uint2*)(o + i) = make_uint2(h2u(__floats2half2_rn(r0, r1)),
                                  h2u(__floats2half2_rn(r2, r3)));
}

// ================= mma helpers =================
__device__ __forceinline__ uint32_t f2r(float f) { return __float_as_uint(f); }

__device__ __forceinline__ void mma_tf32(float* d, const uint32_t* a, const uint32_t* b) {
    asm volatile(
        "mma.sync.aligned.m16n8k8.row.col.f32.tf32.tf32.f32 "
        "{%0,%1,%2,%3}, {%4,%5,%6,%7}, {%8,%9}, {%0,%1,%2,%3};\n"
        : "+f"(d[0]), "+f"(d[1]), "+f"(d[2]), "+f"(d[3])
        : "r"(a[0]), "r"(a[1]), "r"(a[2]), "r"(a[3]), "r"(b[0]), "r"(b[1]));
}

__device__ __forceinline__ void mma_f16(float* d, const uint32_t* a, const uint32_t* b) {
    asm volatile(
        "mma.sync.aligned.m16n8k16.row.col.f32.f16.f16.f32 "
        "{%0,%1,%2,%3}, {%4,%5,%6,%7}, {%8,%9}, {%0,%1,%2,%3};\n"
        : "+f"(d[0]), "+f"(d[1]), "+f"(d[2]), "+f"(d[3])
        : "r"(a[0]), "r"(a[1]), "r"(a[2]), "r"(a[3]), "r"(b[0]), "r"(b[1]));
}

__device__ __forceinline__ void ldsm4(uint32_t* r, uint32_t saddr) {
    asm volatile("ldmatrix.sync.aligned.m8n8.x4.shared.b16 {%0,%1,%2,%3}, [%4];"
                 : "=r"(r[0]), "=r"(r[1]), "=r"(r[2]), "=r"(r[3]) : "r"(saddr));
}
__device__ __forceinline__ void ldsm2t(uint32_t* r, uint32_t saddr) {
    asm volatile("ldmatrix.sync.aligned.m8n8.x2.trans.shared.b16 {%0,%1}, [%2];"
                 : "=r"(r[0]), "=r"(r[1]) : "r"(saddr));
}

// ================= fp16 tensor-core GEMM =================
// C[M,N]=A16[M,K]@B16[K,N] (+bias fp32)(+res fp32) -> C fp32.
// 128x128 CTA tile, BK=64 halves, 2-stage cp.async, 8 warps 2x4, 64x32 warp tile.
#define BM 128
#define BN 128
#define BK 64
#define ASTR 72                    // halves; 144B rows -> ldmatrix banks 4r (conflict-free)
#define BSTR 136                   // halves; 272B rows -> banks 4r (conflict-free)
#define ATILE_H (BM * ASTR)        // 9216
#define BTILE_H (BK * BSTR)        // 8704
#define STAGE_H (ATILE_H + BTILE_H)
#define TG_SMEM (2 * STAGE_H * 2)  // 71680 B

__global__ __launch_bounds__(256, 2) void hgemm_kernel(
    int M, int N, int K,
    const __half* __restrict__ A, const __half* __restrict__ B,
    const float* __restrict__ bias, const float* __restrict__ res,
    float* __restrict__ C,
    const __half* __restrict__ B2, float* __restrict__ C2) {
    extern __shared__ __half sm[];

    if (B2 && blockIdx.z) { B = B2; C = C2; }

    const int tid  = threadIdx.x;
    const int bm   = blockIdx.y * BM;
    const int bn   = blockIdx.x * BN;
    const int warp = tid >> 5, lane = tid & 31;
    const int wm   = (warp >> 2) * 64;
    const int wn   = (warp & 3) * 32;
    const int fr   = lane >> 2;
    const int fc   = lane & 3;
    // ldmatrix lane source mapping
    const int arow_l = ((lane >> 3) & 1) * 8 + (lane & 7);
    const int acol_l = ((lane >> 4) & 1) * 8;            // x4: k-halves 0 or 8
    const int brow_l = arow_l;                            // x2.trans: k rows (lanes 16+ ignored)

    float acc[4][4][4];
#pragma unroll
    for (int i = 0; i < 4; i++)
#pragma unroll
        for (int j = 0; j < 4; j++)
#pragma unroll
            for (int k = 0; k < 4; k++) acc[i][j][k] = 0.f;

    auto fill = [&](int s, int kt) {
        __half* Ad = sm + s * STAGE_H;
        __half* Bd = Ad + ATILE_H;
#pragma unroll
        for (int p = 0; p < 4; p++) {
            int idx = p * 256 + tid;
            int row = idx & 127, c8 = idx >> 7;           // 8 16B-chunks per 128B row
            uint32_t dst = (uint32_t)__cvta_generic_to_shared(Ad + row * ASTR + c8 * 8);
            const __half* src = A + (size_t)(bm + row) * K + kt + c8 * 8;
            asm volatile("cp.async.cg.shared.global [%0], [%1], 16;\n" :: "r"(dst), "l"(src));
        }
#pragma unroll
        for (int p = 0; p < 4; p++) {
            int idx = p * 256 + tid;
            int row = idx >> 4, c16 = idx & 15;           // 16 chunks per 256B row
            uint32_t dst = (uint32_t)__cvta_generic_to_shared(Bd + row * BSTR + c16 * 8);
            const __half* src = B + (size_t)(kt + row) * N + bn + c16 * 8;
            asm volatile("cp.async.cg.shared.global [%0], [%1], 16;\n" :: "r"(dst), "l"(src));
        }
        asm volatile("cp.async.commit_group;\n");
    };

    auto compute_tile = [&](int s) {
        const __half* Ab = sm + s * STAGE_H;
        const __half* Bb = Ab + ATILE_H;
        uint32_t abase = (uint32_t)__cvta_generic_to_shared(Ab + (wm + arow_l) * ASTR + acol_l);
        uint32_t bbase = (uint32_t)__cvta_generic_to_shared(Bb + brow_l * BSTR + wn);
#pragma unroll
        for (int ks = 0; ks < 4; ks++) {                  // k0 = ks*16 halves
            uint32_t af[4][4], bf[4][2];
#pragma unroll
            for (int mi = 0; mi < 4; mi++)
                ldsm4(af[mi], abase + (mi * 16 * ASTR + ks * 16) * 2);
#pragma unroll
            for (int ni = 0; ni < 4; ni++)
                ldsm2t(bf[ni], bbase + (ks * 16 * BSTR + ni * 8) * 2);
#pragma unroll
            for (int mi = 0; mi < 4; mi++)
#pragma unroll
                for (int ni = 0; ni < 4; ni++) mma_f16(acc[mi][ni], af[mi], bf[ni]);
        }
    };

    const int kiters = K / BK;
    fill(0, 0);
    asm volatile("cp.async.wait_group 0;\n");
    __syncthreads();

#pragma unroll 1
    for (int it = 0; it < kiters; ++it) {
        int cur = it & 1;
        if (it + 1 < kiters) fill(cur ^ 1, (it + 1) * BK);
        compute_tile(cur);
        asm volatile("cp.async.wait_group 0;\n");
        __syncthreads();
    }

#pragma unroll
    for (int mi = 0; mi < 4; mi++) {
#pragma unroll
        for (int ni = 0; ni < 4; ni++) {
            int gr = bm + wm + mi * 16 + fr;
            int gc = bn + wn + ni * 8 + fc * 2;
            float2 o0 = make_float2(acc[mi][ni][0], acc[mi][ni][1]);
            float2 o1 = make_float2(acc[mi][ni][2], acc[mi][ni][3]);
            if (bias) {
                float2 bv = *(const float2*)(bias + gc);
                o0.x += bv.x; o0.y += bv.y;
                o1.x += bv.x; o1.y += bv.y;
            }
            if (res) {
                float2 r0 = *(const float2*)(res + (size_t)gr * N + gc);
                float2 r1 = *(const float2*)(res + (size_t)(gr + 8) * N + gc);
                o0.x += r0.x; o0.y += r0.y;
                o1.x += r1.x; o1.y += r1.y;
            }
            *(float2*)(C + (size_t)gr * N + gc) = o0;
            *(float2*)(C + (size_t)(gr + 8) * N + gc) = o1;
        }
    }
}

// ================= tf32 tensor-core flash attention (R5; ctx out fp16) =================
#define PQ_STRIDE 68
#define KV_STRIDE 72
#define ATT_SMEM ((64 * PQ_STRIDE * 2 + 64 * KV_STRIDE * 2) * 4)

__global__ __launch_bounds__(128) void attn_kernel(const float* __restrict__ qkv,
                                                   __half* __restrict__ ctx) {
    extern __shared__ float smr[];
    float* Qs = smr;
    float* Ps = Qs + 64 * PQ_STRIDE;
    float* Ks = Ps + 64 * PQ_STRIDE;
    float* Vs = Ks + 64 * KV_STRIDE;

    const int qt = blockIdx.x, h = blockIdx.y, b = blockIdx.z;
    const int m0 = qt * 64;
    const int tid  = threadIdx.x;
    const int warp = tid >> 5, lane = tid & 31;
    const int fr = lane >> 2, fc = lane & 3;
    const int w16 = warp * 16;
    const int lg   = lane >> 3;
    const int lrow = ((lg & 1) << 3) + (lane & 7);
    const int lcol = (lg >> 1) << 2;
    const float slope = exp2f(-(1.0f + 7.0f * (float)h / 15.0f));

    for (int i = tid; i < 64 * 16; i += 128) {
        int r = i >> 4, c = (i & 15) << 2;
        float4 v = *(const float4*)(qkv + ((((size_t)(b * L_ + m0 + r) * H_ + h) * 3 + 0) * D_ + c));
        Qs[r * PQ_STRIDE + c + 0] = v.x * 0.125f;
        Qs[r * PQ_STRIDE + c + 1] = v.y * 0.125f;
        Qs[r * PQ_STRIDE + c + 2] = v.z * 0.125f;
        Qs[r * PQ_STRIDE + c + 3] = v.w * 0.125f;
    }
    __syncthreads();

    const uint32_t qbase = (uint32_t)__cvta_generic_to_shared(Qs + (w16 + lrow) * PQ_STRIDE + lcol);
    const uint32_t pbase = (uint32_t)__cvta_generic_to_shared(Ps + (w16 + lrow) * PQ_STRIDE + lcol);

    uint32_t qf[8][4];
#pragma unroll
    for (int ks = 0; ks < 8; ks++) ldsm4(qf[ks], qbase + ks * 8 * 4);

    float oacc[8][4];
#pragma unroll
    for (int i = 0; i < 8; i++)
#pragma unroll
        for (int j = 0; j < 4; j++) oacc[i][j] = 0.f;
    float mrow0 = -CUDART_INF_F, mrow1 = -CUDART_INF_F;
    float lrow0 = 0.f, lrow1 = 0.f;

    const int gi0 = m0 + w16 + fr;
    const int gi1 = gi0 + 8;

    for (int kt = 0; kt <= qt; kt++) {
        const int n0 = kt * 64;
        __syncthreads();
        for (int i = tid; i < 64 * 16; i += 128) {
            int r = i >> 4, c = (i & 15) << 2;
            size_t base = ((size_t)(b * L_ + n0 + r) * H_ + h) * 3;
            float4 kv = *(const float4*)(qkv + (base + 1) * D_ + c);
            float4 vv = *(const float4*)(qkv + (base + 2) * D_ + c);
            Ks[(c + 0) * KV_STRIDE + r] = kv.x;
            Ks[(c + 1) * KV_STRIDE + r] = kv.y;
            Ks[(c + 2) * KV_STRIDE + r] = kv.z;
            Ks[(c + 3) * KV_STRIDE + r] = kv.w;
            Vs[r * KV_STRIDE + c + 0] = vv.x;
            Vs[r * KV_STRIDE + c + 1] = vv.y;
            Vs[r * KV_STRIDE + c + 2] = vv.z;
            Vs[r * KV_STRIDE + c + 3] = vv.w;
        }
        __syncthreads();

        float sacc[8][4];
#pragma unroll
        for (int i = 0; i < 8; i++)
#pragma unroll
            for (int j = 0; j < 4; j++) sacc[i][j] = 0.f;
#pragma unroll
        for (int ks = 0; ks < 8; ks++) {
            int k0 = ks * 8;
            uint32_t bf[8][2];
#pragma unroll
            for (int ni = 0; ni < 8; ni++) {
                int n = ni * 8 + fr;
                bf[ni][0] = f2r(Ks[(k0 + fc) * KV_STRIDE + n]);
                bf[ni][1] = f2r(Ks[(k0 + fc + 4) * KV_STRIDE + n]);
            }
#pragma unroll
            for (int ni = 0; ni < 8; ni++) mma_tf32(sacc[ni], qf[ks], bf[ni]);
        }

#pragma unroll
        for (int ni = 0; ni < 8; ni++) {
            int gj = n0 + ni * 8 + 2 * fc;
            float a0 = slope * (float)(gj - gi0);
            float a1 = slope * (float)(gj + 1 - gi0);
            float a2 = slope * (float)(gj - gi1);
            float a3 = slope * (float)(gj + 1 - gi1);
            sacc[ni][0] = (gj     > gi0) ? -CUDART_INF_F : sacc[ni][0] + a0;
            sacc[ni][1] = (gj + 1 > gi0) ? -CUDART_INF_F : sacc[ni][1] + a1;
            sacc[ni][2] = (gj     > gi1) ? -CUDART_INF_F : sacc[ni][2] + a2;
            sacc[ni][3] = (gj + 1 > gi1) ? -CUDART_INF_F : sacc[ni][3] + a3;
        }

        float mx0 = -CUDART_INF_F, mx1 = -CUDART_INF_F;
#pragma unroll
        for (int ni = 0; ni < 8; ni++) {
            mx0 = fmaxf(mx0, fmaxf(sacc[ni][0], sacc[ni][1]));
            mx1 = fmaxf(mx1, fmaxf(sacc[ni][2], sacc[ni][3]));
        }
        mx0 = fmaxf(mx0, __shfl_xor_sync(0xffffffffu, mx0, 1));
        mx0 = fmaxf(mx0, __shfl_xor_sync(0xffffffffu, mx0, 2));
        mx1 = fmaxf(mx1, __shfl_xor_sync(0xffffffffu, mx1, 1));
        mx1 = fmaxf(mx1, __shfl_xor_sync(0xffffffffu, mx1, 2));
        float mn0 = fmaxf(mrow0, mx0);
        float mn1 = fmaxf(mrow1, mx1);
        float alpha0 = __expf(mrow0 - mn0);
        float alpha1 = __expf(mrow1 - mn1);
        float rs0 = 0.f, rs1 = 0.f;
#pragma unroll
        for (int ni = 0; ni < 8; ni++) {
            sacc[ni][0] = __expf(sacc[ni][0] - mn0);
            sacc[ni][1] = __expf(sacc[ni][1] - mn0);
            sacc[ni][2] = __expf(sacc[ni][2] - mn1);
            sacc[ni][3] = __expf(sacc[ni][3] - mn1);
            rs0 += sacc[ni][0] + sacc[ni][1];
            rs1 += sacc[ni][2] + sacc[ni][3];
        }
        rs0 += __shfl_xor_sync(0xffffffffu, rs0, 1);
        rs0 += __shfl_xor_sync(0xffffffffu, rs0, 2);
        rs1 += __shfl_xor_sync(0xffffffffu, rs1, 1);
        rs1 += __shfl_xor_sync(0xffffffffu, rs1, 2);
        lrow0 = lrow0 * alpha0 + rs0;
        lrow1 = lrow1 * alpha1 + rs1;
        mrow0 = mn0;
        mrow1 = mn1;
#pragma unroll
        for (int ni = 0; ni < 8; ni++) {
            oacc[ni][0] *= alpha0;
            oacc[ni][1] *= alpha0;
            oacc[ni][2] *= alpha1;
            oacc[ni][3] *= alpha1;
        }

#pragma unroll
        for (int ni = 0; ni < 8; ni++) {
            int c = ni * 8 + 2 * fc;
            *(float2*)&Ps[(w16 + fr) * PQ_STRIDE + c]     = make_float2(sacc[ni][0], sacc[ni][1]);
            *(float2*)&Ps[(w16 + fr + 8) * PQ_STRIDE + c] = make_float2(sacc[ni][2], sacc[ni][3]);
        }
        __syncwarp();

#pragma unroll
        for (int ks = 0; ks < 8; ks++) {
            int k0 = ks * 8;
            uint32_t af[4];
            ldsm4(af, pbase + k0 * 4);
#pragma unroll
            for (int ni = 0; ni < 8; ni++) {
                uint32_t bf[2];
                int n = ni * 8 + fr;
                bf[0] = f2r(Vs[(k0 + fc) * KV_STRIDE + n]);
                bf[1] = f2r(Vs[(k0 + fc + 4) * KV_STRIDE + n]);
                mma_tf32(oacc[ni], af, bf);
            }
        }
        __syncwarp();
    }

    float inv0 = 1.0f / lrow0;
    float inv1 = 1.0f / lrow1;
#pragma unroll
    for (int ni = 0; ni < 8; ni++) {
        int c = h * D_ + ni * 8 + 2 * fc;
        __half2 o0 = __floats2half2_rn(oacc[ni][0] * inv0, oacc[ni][1] * inv0);
        __half2 o1 = __floats2half2_rn(oacc[ni][2] * inv1, oacc[ni][3] * inv1);
        *(__half2*)(ctx + (size_t)(b * L_ + gi0) * HD_ + c) = o0;
        *(__half2*)(ctx + (size_t)(b * L_ + gi1) * HD_ + c) = o1;
    }
}

// ---------------- launch ----------------
extern "C" void kernel_launch(void* const* d_in, const int* in_sizes, int n_in,
                              void* d_out, int out_size) {
    (void)in_sizes; (void)n_in; (void)out_size;
    const float* X    = (const float*)d_in[0];
    const float* Wqkv = (const float*)d_in[2];
    const float* bqkv = (const float*)d_in[3];
    const float* Wo   = (const float*)d_in[4];
    const float* bo   = (const float*)d_in[5];
    const float* Ww   = (const float*)d_in[12];
    const float* Wv   = (const float*)d_in[13];
    const float* Wout = (const float*)d_in[14];
    float* out = (float*)d_out;

    float *qkv_p, *x_p, *g_p, *v_p;
    __half *h16, *ctx16, *gg16, *wqkv16, *wo16, *ww16, *wv16, *wout16;
    cudaGetSymbolAddress((void**)&qkv_p,  g_qkv);
    cudaGetSymbolAddress((void**)&x_p,    g_x);
    cudaGetSymbolAddress((void**)&g_p,    g_gate);
    cudaGetSymbolAddress((void**)&v_p,    g_val);
    cudaGetSymbolAddress((void**)&h16,    g_h16);
    cudaGetSymbolAddress((void**)&ctx16,  g_ctx16);
    cudaGetSymbolAddress((void**)&gg16,   g_gg16);
    cudaGetSymbolAddress((void**)&wqkv16, g_wqkv16);
    cudaGetSymbolAddress((void**)&wo16,   g_wo16);
    cudaGetSymbolAddress((void**)&ww16,   g_ww16);
    cudaGetSymbolAddress((void**)&wv16,   g_wv16);
    cudaGetSymbolAddress((void**)&wout16, g_wout16);

    cudaFuncSetAttribute(attn_kernel, cudaFuncAttributeMaxDynamicSharedMemorySize, ATT_SMEM);
    cudaFuncSetAttribute(hgemm_kernel, cudaFuncAttributeMaxDynamicSharedMemorySize, TG_SMEM);

    // 0. fp16 weight conversions
    f2h_kernel<<<(E_ * 3 * HD_) / 1024, 256>>>(Wqkv, wqkv16);
    f2h_kernel<<<(HD_ * E_) / 1024, 256>>>(Wo, wo16);
    f2h_kernel<<<(E_ * DFF_) / 1024, 256>>>(Ww, ww16);
    f2h_kernel<<<(E_ * DFF_) / 1024, 256>>>(Wv, wv16);
    f2h_kernel<<<(DFF_ * E_) / 1024, 256>>>(Wout, wout16);

    // 1. h16 = rmsnorm(X)
    rmsnorm_kernel<<<M_, 256>>>(X, h16);
    // 2. qkv = h16 @ wqkv16 + bqkv   (fp32 out, read by attention)
    hgemm_kernel<<<dim3(3 * HD_ / BN, M_ / BM), 256, TG_SMEM>>>(
        M_, 3 * HD_, E_, h16, wqkv16, bqkv, nullptr, qkv_p, nullptr, nullptr);
    // 3. attention (tf32 mma flash, ctx out fp16)
    attn_kernel<<<dim3(L_ / 64, H_, B_), 128, ATT_SMEM>>>(qkv_p, ctx16);
    // 4. x = X + ctx16 @ wo16 + bo
    hgemm_kernel<<<dim3(E_ / BN, M_ / BM), 256, TG_SMEM>>>(
        M_, E_, HD_, ctx16, wo16, bo, X, x_p, nullptr, nullptr);
    // 5+6. x = x + rmsnorm(x); h16 = rmsnorm(x)
    addnorm_kernel<<<M_, 256>>>(x_p, h16);
    // 7. gate = h16 @ ww16 ; val = h16 @ wv16  (dual-output, z selects)
    hgemm_kernel<<<dim3(DFF_ / BN, M_ / BM, 2), 256, TG_SMEM>>>(
        M_, DFF_, E_, h16, ww16, nullptr, nullptr, g_p, wv16, v_p);
    // 8. gg16 = gelu(gate) * val
    geglu_kernel<<<(M_ * DFF_) / 1024, 256>>>(g_p, v_p, gg16);
    // 9. out = x + gg16 @ wout16
    hgemm_kernel<<<dim3(E_ / BN, M_ / BM), 256, TG_SMEM>>>(
        M_, E_, DFF_, gg16, wout16, nullptr, x_p, out, nullptr, nullptr);
}

// round 10
// speedup vs baseline: 1.5199x; 1.2130x over previous
#include <cuda_runtime.h>
#include <cuda_fp16.h>
#include <math_constants.h>
#include <cstdint>

#define B_   2
#define L_   2048
#define E_   1024
#define H_   16
#define D_   64
#define DFF_ 4096
#define M_   (B_ * L_)   // 4096 tokens
#define HD_  (H_ * D_)   // 1024

// ---------------- scratch (device globals: allocation-guard safe) ----------------
__device__ float  g_x[M_ * E_];
__device__ __half g_h16[M_ * E_];
__device__ __half g_qkv16[(size_t)M_ * 3 * HD_];
__device__ __half g_ctx16[M_ * HD_];
__device__ __half g_gate16[(size_t)M_ * DFF_];
__device__ __half g_val16[(size_t)M_ * DFF_];
__device__ __half g_gg16[(size_t)M_ * DFF_];
// fp16 weights
__device__ __half g_wqkv16[(size_t)E_ * 3 * HD_];
__device__ __half g_wo16[(size_t)HD_ * E_];
__device__ __half g_ww16[(size_t)E_ * DFF_];
__device__ __half g_wv16[(size_t)E_ * DFF_];
__device__ __half g_wout16[(size_t)DFF_ * E_];

// __half2 bit-pattern helper
__device__ __forceinline__ uint32_t h2u(__half2 h) {
    return *reinterpret_cast<uint32_t*>(&h);
}

// ---------------- fp32 -> fp16 conversion ----------------
__global__ __launch_bounds__(256) void f2h_kernel(const float* __restrict__ src,
                                                  __half* __restrict__ dst) {
    int i = blockIdx.x * 256 + threadIdx.x;
    float4 v = ((const float4*)src)[i];
    uint2 o = make_uint2(h2u(__floats2half2_rn(v.x, v.y)),
                         h2u(__floats2half2_rn(v.z, v.w)));
    ((uint2*)dst)[i] = o;
}

// ---------------- rmsnorm (fp16 out) ----------------
__global__ __launch_bounds__(256) void rmsnorm_kernel(const float* __restrict__ x,
                                                      __half* __restrict__ y) {
    int row = blockIdx.x;
    float4 a = ((const float4*)(x + (size_t)row * E_))[threadIdx.x];
    float ss = a.x * a.x + a.y * a.y + a.z * a.z + a.w * a.w;
    __shared__ float red[8];
    __shared__ float sinv;
#pragma unroll
    for (int o = 16; o > 0; o >>= 1) ss += __shfl_xor_sync(0xffffffffu, ss, o);
    if ((threadIdx.x & 31) == 0) red[threadIdx.x >> 5] = ss;
    __syncthreads();
    if (threadIdx.x == 0) {
        float t = 0.f;
#pragma unroll
        for (int i = 0; i < 8; i++) t += red[i];
        sinv = rsqrtf(t * (1.0f / E_));
    }
    __syncthreads();
    float c = sinv;
    ((uint2*)(y + (size_t)row * E_))[threadIdx.x] =
        make_uint2(h2u(__floats2half2_rn(a.x * c, a.y * c)),
                   h2u(__floats2half2_rn(a.z * c, a.w * c)));
}

// ---------------- fused: x = x + rmsnorm(x); h16 = rmsnorm(x) ----------------
__global__ __launch_bounds__(256) void addnorm_kernel(float* __restrict__ x,
                                                      __half* __restrict__ h) {
    int row = blockIdx.x;
    float4 a = ((const float4*)(x + (size_t)row * E_))[threadIdx.x];
    __shared__ float red[8];
    __shared__ float sval;
    float ss = a.x * a.x + a.y * a.y + a.z * a.z + a.w * a.w;
#pragma unroll
    for (int o = 16; o > 0; o >>= 1) ss += __shfl_xor_sync(0xffffffffu, ss, o);
    if ((threadIdx.x & 31) == 0) red[threadIdx.x >> 5] = ss;
    __syncthreads();
    if (threadIdx.x == 0) {
        float t = 0.f;
#pragma unroll
        for (int i = 0; i < 8; i++) t += red[i];
        sval = 1.0f + rsqrtf(t * (1.0f / E_));
    }
    __syncthreads();
    float c = sval;
    a.x *= c; a.y *= c; a.z *= c; a.w *= c;
    float ss2 = a.x * a.x + a.y * a.y + a.z * a.z + a.w * a.w;
#pragma unroll
    for (int o = 16; o > 0; o >>= 1) ss2 += __shfl_xor_sync(0xffffffffu, ss2, o);
    if ((threadIdx.x & 31) == 0) red[threadIdx.x >> 5] = ss2;
    __syncthreads();
    if (threadIdx.x == 0) {
        float t = 0.f;
#pragma unroll
        for (int i = 0; i < 8; i++) t += red[i];
        sval = rsqrtf(t * (1.0f / E_));
    }
    __syncthreads();
    float inv2 = sval;
    ((float4*)(x + (size_t)row * E_))[threadIdx.x] = a;
    ((uint2*)(h + (size_t)row * E_))[threadIdx.x] =
        make_uint2(h2u(__floats2half2_rn(a.x * inv2, a.y * inv2)),
                   h2u(__floats2half2_rn(a.z * inv2, a.w * inv2)));
}

// ---------------- geglu (fp16 in/out) ----------------
__global__ __launch_bounds__(256) void geglu_kernel(const __half* __restrict__ g,
                                                    const __half* __restrict__ v,
                                                    __half* __restrict__ o) {
    int i = (blockIdx.x * 256 + threadIdx.x) * 4;
    uint2 gu = *(const uint2*)(g + i);
    uint2 vu = *(const uint2*)(v + i);
    float2 g0 = __half22float2(*reinterpret_cast<__half2*>(&gu.x));
    float2 g1 = __half22float2(*reinterpret_cast<__half2*>(&gu.y));
    float2 v0 = __half22float2(*reinterpret_cast<__half2*>(&vu.x));
    float2 v1 = __half22float2(*reinterpret_cast<__half2*>(&vu.y));
    float r0 = 0.5f * g0.x * (1.0f + erff(g0.x * 0.70710678118654752f)) * v0.x;
    float r1 = 0.5f * g0.y * (1.0f + erff(g0.y * 0.70710678118654752f)) * v0.y;
    float r2 = 0.5f * g1.x * (1.0f + erff(g1.x * 0.70710678118654752f)) * v1.x;
    float r3 = 0.5f * g1.y * (1.0f + erff(g1.y * 0.70710678118654752f)) * v1.y;
    *(uint2*)(o + i) = make_uint2(h2u(__floats2half2_rn(r0, r1)),
                                  h2u(__floats2half2_rn(r2, r3)));
}

// ================= mma helpers =================
__device__ __forceinline__ void mma_f16(float* d, const uint32_t* a, const uint32_t* b) {
    asm volatile(
        "mma.sync.aligned.m16n8k16.row.col.f32.f16.f16.f32 "
        "{%0,%1,%2,%3}, {%4,%5,%6,%7}, {%8,%9}, {%0,%1,%2,%3};\n"
        : "+f"(d[0]), "+f"(d[1]), "+f"(d[2]), "+f"(d[3])
        : "r"(a[0]), "r"(a[1]), "r"(a[2]), "r"(a[3]), "r"(b[0]), "r"(b[1]));
}

__device__ __forceinline__ void ldsm4(uint32_t* r, uint32_t saddr) {
    asm volatile("ldmatrix.sync.aligned.m8n8.x4.shared.b16 {%0,%1,%2,%3}, [%4];"
                 : "=r"(r[0]), "=r"(r[1]), "=r"(r[2]), "=r"(r[3]) : "r"(saddr));
}
__device__ __forceinline__ void ldsm2t(uint32_t* r, uint32_t saddr) {
    asm volatile("ldmatrix.sync.aligned.m8n8.x2.trans.shared.b16 {%0,%1}, [%2];"
                 : "=r"(r[0]), "=r"(r[1]) : "r"(saddr));
}

// ================= fp16 tensor-core GEMM =================
// C[M,N]=A16[M,K]@B16[K,N] (+bias fp32)(+res fp32) -> C fp32 OR C16 fp16.
#define BM 128
#define BN 128
#define BK 64
#define ASTR 72
#define BSTR 136
#define ATILE_H (BM * ASTR)
#define BTILE_H (BK * BSTR)
#define STAGE_H (ATILE_H + BTILE_H)
#define TG_SMEM (2 * STAGE_H * 2)  // 71680 B

__global__ __launch_bounds__(256, 2) void hgemm_kernel(
    int M, int N, int K,
    const __half* __restrict__ A, const __half* __restrict__ B,
    const float* __restrict__ bias, const float* __restrict__ res,
    float* __restrict__ C, __half* __restrict__ C16,
    const __half* __restrict__ B2, float* __restrict__ C2, __half* __restrict__ C216) {
    extern __shared__ __half sm[];

    if (blockIdx.z) { B = B2; C = C2; C16 = C216; }

    const int tid  = threadIdx.x;
    const int bm   = blockIdx.y * BM;
    const int bn   = blockIdx.x * BN;
    const int warp = tid >> 5, lane = tid & 31;
    const int wm   = (warp >> 2) * 64;
    const int wn   = (warp & 3) * 32;
    const int fr   = lane >> 2;
    const int fc   = lane & 3;
    const int arow_l = ((lane >> 3) & 1) * 8 + (lane & 7);
    const int acol_l = ((lane >> 4) & 1) * 8;
    const int brow_l = arow_l;

    float acc[4][4][4];
#pragma unroll
    for (int i = 0; i < 4; i++)
#pragma unroll
        for (int j = 0; j < 4; j++)
#pragma unroll
            for (int k = 0; k < 4; k++) acc[i][j][k] = 0.f;

    auto fill = [&](int s, int kt) {
        __half* Ad = sm + s * STAGE_H;
        __half* Bd = Ad + ATILE_H;
#pragma unroll
        for (int p = 0; p < 4; p++) {
            int idx = p * 256 + tid;
            int row = idx & 127, c8 = idx >> 7;
            uint32_t dst = (uint32_t)__cvta_generic_to_shared(Ad + row * ASTR + c8 * 8);
            const __half* src = A + (size_t)(bm + row) * K + kt + c8 * 8;
            asm volatile("cp.async.cg.shared.global [%0], [%1], 16;\n" :: "r"(dst), "l"(src));
        }
#pragma unroll
        for (int p = 0; p < 4; p++) {
            int idx = p * 256 + tid;
            int row = idx >> 4, c16 = idx & 15;
            uint32_t dst = (uint32_t)__cvta_generic_to_shared(Bd + row * BSTR + c16 * 8);
            const __half* src = B + (size_t)(kt + row) * N + bn + c16 * 8;
            asm volatile("cp.async.cg.shared.global [%0], [%1], 16;\n" :: "r"(dst), "l"(src));
        }
        asm volatile("cp.async.commit_group;\n");
    };

    auto compute_tile = [&](int s) {
        const __half* Ab = sm + s * STAGE_H;
        const __half* Bb = Ab + ATILE_H;
        uint32_t abase = (uint32_t)__cvta_generic_to_shared(Ab + (wm + arow_l) * ASTR + acol_l);
        uint32_t bbase = (uint32_t)__cvta_generic_to_shared(Bb + brow_l * BSTR + wn);
#pragma unroll
        for (int ks = 0; ks < 4; ks++) {
            uint32_t af[4][4], bf[4][2];
#pragma unroll
            for (int mi = 0; mi < 4; mi++)
                ldsm4(af[mi], abase + (mi * 16 * ASTR + ks * 16) * 2);
#pragma unroll
            for (int ni = 0; ni < 4; ni++)
                ldsm2t(bf[ni], bbase + (ks * 16 * BSTR + ni * 8) * 2);
#pragma unroll
            for (int mi = 0; mi < 4; mi++)
#pragma unroll
                for (int ni = 0; ni < 4; ni++) mma_f16(acc[mi][ni], af[mi], bf[ni]);
        }
    };

    const int kiters = K / BK;
    fill(0, 0);
    asm volatile("cp.async.wait_group 0;\n");
    __syncthreads();

#pragma unroll 1
    for (int it = 0; it < kiters; ++it) {
        int cur = it & 1;
        if (it + 1 < kiters) fill(cur ^ 1, (it + 1) * BK);
        compute_tile(cur);
        asm volatile("cp.async.wait_group 0;\n");
        __syncthreads();
    }

#pragma unroll
    for (int mi = 0; mi < 4; mi++) {
#pragma unroll
        for (int ni = 0; ni < 4; ni++) {
            int gr = bm + wm + mi * 16 + fr;
            int gc = bn + wn + ni * 8 + fc * 2;
            float2 o0 = make_float2(acc[mi][ni][0], acc[mi][ni][1]);
            float2 o1 = make_float2(acc[mi][ni][2], acc[mi][ni][3]);
            if (bias) {
                float2 bv = *(const float2*)(bias + gc);
                o0.x += bv.x; o0.y += bv.y;
                o1.x += bv.x; o1.y += bv.y;
            }
            if (res) {
                float2 r0 = *(const float2*)(res + (size_t)gr * N + gc);
                float2 r1 = *(const float2*)(res + (size_t)(gr + 8) * N + gc);
                o0.x += r0.x; o0.y += r0.y;
                o1.x += r1.x; o1.y += r1.y;
            }
            if (C16) {
                *(__half2*)(C16 + (size_t)gr * N + gc) = __floats2half2_rn(o0.x, o0.y);
                *(__half2*)(C16 + (size_t)(gr + 8) * N + gc) = __floats2half2_rn(o1.x, o1.y);
            } else {
                *(float2*)(C + (size_t)gr * N + gc) = o0;
                *(float2*)(C + (size_t)(gr + 8) * N + gc) = o1;
            }
        }
    }
}

// ================= fp16 tensor-core flash attention =================
// qkv16 layout [b][l][h][s][d] halves. 64x64 Q tile, 4 warps.
// Qs/Ps: [64][72] halves (A-operand, ldsm4). Ks: [64(d)][72(key)] (B for S, ldsm2t).
// Vs: [64(key)][72(d)] (B for PV, ldsm2t). All 144B rows -> bank residue 4r, conflict-free.
#define ATSTR 72
#define ATT_SMEM (4 * 64 * ATSTR * 2)   // 36864 B

__global__ __launch_bounds__(128) void attn_kernel(const __half* __restrict__ qkv,
                                                   __half* __restrict__ ctx) {
    extern __shared__ __half smh[];
    __half* Qs = smh;
    __half* Ps = Qs + 64 * ATSTR;
    __half* Ks = Ps + 64 * ATSTR;   // transposed [d][key]
    __half* Vs = Ks + 64 * ATSTR;   // natural [key][d]

    const int qt = blockIdx.x, h = blockIdx.y, b = blockIdx.z;
    const int m0 = qt * 64;
    const int tid  = threadIdx.x;
    const int warp = tid >> 5, lane = tid & 31;
    const int fr = lane >> 2, fc = lane & 3;
    const int w16 = warp * 16;
    const int arow_l = ((lane >> 3) & 1) * 8 + (lane & 7);
    const int acol_l = ((lane >> 4) & 1) * 8;
    const int brow_l = arow_l;
    const float slope = exp2f(-(1.0f + 7.0f * (float)h / 15.0f));
    const __half2 qscale = __floats2half2_rn(0.125f, 0.125f);

    // ---- load Q tile (scaled 1/8), fp16 ----
    for (int i = tid; i < 64 * 16; i += 128) {
        int r = i >> 4, c = (i & 15) << 2;           // 4 halves per chunk
        uint2 v = *(const uint2*)(qkv + ((((size_t)(b * L_ + m0 + r) * H_ + h) * 3 + 0) * D_ + c));
        __half2 q0 = __hmul2(*reinterpret_cast<__half2*>(&v.x), qscale);
        __half2 q1 = __hmul2(*reinterpret_cast<__half2*>(&v.y), qscale);
        *(uint2*)(Qs + r * ATSTR + c) = make_uint2(h2u(q0), h2u(q1));
    }
    __syncthreads();

    const uint32_t qbase = (uint32_t)__cvta_generic_to_shared(Qs + (w16 + arow_l) * ATSTR + acol_l);
    const uint32_t pbase = (uint32_t)__cvta_generic_to_shared(Ps + (w16 + arow_l) * ATSTR + acol_l);
    const uint32_t kbase = (uint32_t)__cvta_generic_to_shared(Ks + brow_l * ATSTR);
    const uint32_t vbase = (uint32_t)__cvta_generic_to_shared(Vs + brow_l * ATSTR);

    uint32_t qf[4][4];
#pragma unroll
    for (int ks = 0; ks < 4; ks++) ldsm4(qf[ks], qbase + ks * 16 * 2);

    float oacc[8][4];
#pragma unroll
    for (int i = 0; i < 8; i++)
#pragma unroll
        for (int j = 0; j < 4; j++) oacc[i][j] = 0.f;
    float mrow0 = -CUDART_INF_F, mrow1 = -CUDART_INF_F;
    float lrow0 = 0.f, lrow1 = 0.f;

    const int gi0 = m0 + w16 + fr;
    const int gi1 = gi0 + 8;

    for (int kt = 0; kt <= qt; kt++) {
        const int n0 = kt * 64;
        __syncthreads();
        // ---- load K (transposed) + V (natural), fp16 ----
        for (int i = tid; i < 64 * 16; i += 128) {
            int r = i >> 4, c = (i & 15) << 2;
            size_t base = ((size_t)(b * L_ + n0 + r) * H_ + h) * 3;
            uint2 kv = *(const uint2*)(qkv + (base + 1) * D_ + c);
            uint2 vv = *(const uint2*)(qkv + (base + 2) * D_ + c);
            const __half* kh = reinterpret_cast<const __half*>(&kv);
            Ks[(c + 0) * ATSTR + r] = kh[0];
            Ks[(c + 1) * ATSTR + r] = kh[1];
            Ks[(c + 2) * ATSTR + r] = kh[2];
            Ks[(c + 3) * ATSTR + r] = kh[3];
            *(uint2*)(Vs + r * ATSTR + c) = vv;
        }
        __syncthreads();

        // ---- S = (Q/8) K^T via m16n8k16 ----
        float sacc[8][4];
#pragma unroll
        for (int i = 0; i < 8; i++)
#pragma unroll
            for (int j = 0; j < 4; j++) sacc[i][j] = 0.f;
#pragma unroll
        for (int ks = 0; ks < 4; ks++) {
            uint32_t bf[8][2];
#pragma unroll
            for (int ni = 0; ni < 8; ni++)
                ldsm2t(bf[ni], kbase + (ks * 16 * ATSTR + ni * 8) * 2);
#pragma unroll
            for (int ni = 0; ni < 8; ni++) mma_f16(sacc[ni], qf[ks], bf[ni]);
        }

        // ---- alibi + causal on fragments ----
#pragma unroll
        for (int ni = 0; ni < 8; ni++) {
            int gj = n0 + ni * 8 + 2 * fc;
            float a0 = slope * (float)(gj - gi0);
            float a1 = slope * (float)(gj + 1 - gi0);
            float a2 = slope * (float)(gj - gi1);
            float a3 = slope * (float)(gj + 1 - gi1);
            sacc[ni][0] = (gj     > gi0) ? -CUDART_INF_F : sacc[ni][0] + a0;
            sacc[ni][1] = (gj + 1 > gi0) ? -CUDART_INF_F : sacc[ni][1] + a1;
            sacc[ni][2] = (gj     > gi1) ? -CUDART_INF_F : sacc[ni][2] + a2;
            sacc[ni][3] = (gj + 1 > gi1) ? -CUDART_INF_F : sacc[ni][3] + a3;
        }

        // ---- online softmax ----
        float mx0 = -CUDART_INF_F, mx1 = -CUDART_INF_F;
#pragma unroll
        for (int ni = 0; ni < 8; ni++) {
            mx0 = fmaxf(mx0, fmaxf(sacc[ni][0], sacc[ni][1]));
            mx1 = fmaxf(mx1, fmaxf(sacc[ni][2], sacc[ni][3]));
        }
        mx0 = fmaxf(mx0, __shfl_xor_sync(0xffffffffu, mx0, 1));
        mx0 = fmaxf(mx0, __shfl_xor_sync(0xffffffffu, mx0, 2));
        mx1 = fmaxf(mx1, __shfl_xor_sync(0xffffffffu, mx1, 1));
        mx1 = fmaxf(mx1, __shfl_xor_sync(0xffffffffu, mx1, 2));
        float mn0 = fmaxf(mrow0, mx0);
        float mn1 = fmaxf(mrow1, mx1);
        float alpha0 = __expf(mrow0 - mn0);
        float alpha1 = __expf(mrow1 - mn1);
        float rs0 = 0.f, rs1 = 0.f;
#pragma unroll
        for (int ni = 0; ni < 8; ni++) {
            sacc[ni][0] = __expf(sacc[ni][0] - mn0);
            sacc[ni][1] = __expf(sacc[ni][1] - mn0);
            sacc[ni][2] = __expf(sacc[ni][2] - mn1);
            sacc[ni][3] = __expf(sacc[ni][3] - mn1);
            rs0 += sacc[ni][0] + sacc[ni][1];
            rs1 += sacc[ni][2] + sacc[ni][3];
        }
        rs0 += __shfl_xor_sync(0xffffffffu, rs0, 1);
        rs0 += __shfl_xor_sync(0xffffffffu, rs0, 2);
        rs1 += __shfl_xor_sync(0xffffffffu, rs1, 1);
        rs1 += __shfl_xor_sync(0xffffffffu, rs1, 2);
        lrow0 = lrow0 * alpha0 + rs0;
        lrow1 = lrow1 * alpha1 + rs1;
        mrow0 = mn0;
        mrow1 = mn1;
#pragma unroll
        for (int ni = 0; ni < 8; ni++) {
            oacc[ni][0] *= alpha0;
            oacc[ni][1] *= alpha0;
            oacc[ni][2] *= alpha1;
            oacc[ni][3] *= alpha1;
        }

        // ---- P fragments -> fp16 smem (warp-private rows) ----
#pragma unroll
        for (int ni = 0; ni < 8; ni++) {
            int c = ni * 8 + 2 * fc;
            *(__half2*)&Ps[(w16 + fr) * ATSTR + c]     = __floats2half2_rn(sacc[ni][0], sacc[ni][1]);
            *(__half2*)&Ps[(w16 + fr + 8) * ATSTR + c] = __floats2half2_rn(sacc[ni][2], sacc[ni][3]);
        }
        __syncwarp();

        // ---- O += P @ V via m16n8k16 ----
#pragma unroll
        for (int ks = 0; ks < 4; ks++) {
            uint32_t af[4];
            ldsm4(af, pbase + ks * 16 * 2);
#pragma unroll
            for (int ni = 0; ni < 8; ni++) {
                uint32_t bf[2];
                ldsm2t(bf, vbase + (ks * 16 * ATSTR + ni * 8) * 2);
                mma_f16(oacc[ni], af, bf);
            }
        }
        __syncwarp();
    }

    float inv0 = 1.0f / lrow0;
    float inv1 = 1.0f / lrow1;
#pragma unroll
    for (int ni = 0; ni < 8; ni++) {
        int c = h * D_ + ni * 8 + 2 * fc;
        *(__half2*)(ctx + (size_t)(b * L_ + gi0) * HD_ + c) =
            __floats2half2_rn(oacc[ni][0] * inv0, oacc[ni][1] * inv0);
        *(__half2*)(ctx + (size_t)(b * L_ + gi1) * HD_ + c) =
            __floats2half2_rn(oacc[ni][2] * inv1, oacc[ni][3] * inv1);
    }
}

// ---------------- launch ----------------
extern "C" void kernel_launch(void* const* d_in, const int* in_sizes, int n_in,
                              void* d_out, int out_size) {
    (void)in_sizes; (void)n_in; (void)out_size;
    const float* X    = (const float*)d_in[0];
    const float* Wqkv = (const float*)d_in[2];
    const float* bqkv = (const float*)d_in[3];
    const float* Wo   = (const float*)d_in[4];
    const float* bo   = (const float*)d_in[5];
    const float* Ww   = (const float*)d_in[12];
    const float* Wv   = (const float*)d_in[13];
    const float* Wout = (const float*)d_in[14];
    float* out = (float*)d_out;

    float *x_p;
    __half *h16, *qkv16, *ctx16, *gate16, *val16, *gg16;
    __half *wqkv16, *wo16, *ww16, *wv16, *wout16;
    cudaGetSymbolAddress((void**)&x_p,    g_x);
    cudaGetSymbolAddress((void**)&h16,    g_h16);
    cudaGetSymbolAddress((void**)&qkv16,  g_qkv16);
    cudaGetSymbolAddress((void**)&ctx16,  g_ctx16);
    cudaGetSymbolAddress((void**)&gate16, g_gate16);
    cudaGetSymbolAddress((void**)&val16,  g_val16);
    cudaGetSymbolAddress((void**)&gg16,   g_gg16);
    cudaGetSymbolAddress((void**)&wqkv16, g_wqkv16);
    cudaGetSymbolAddress((void**)&wo16,   g_wo16);
    cudaGetSymbolAddress((void**)&ww16,   g_ww16);
    cudaGetSymbolAddress((void**)&wv16,   g_wv16);
    cudaGetSymbolAddress((void**)&wout16, g_wout16);

    cudaFuncSetAttribute(attn_kernel, cudaFuncAttributeMaxDynamicSharedMemorySize, ATT_SMEM);
    cudaFuncSetAttribute(hgemm_kernel, cudaFuncAttributeMaxDynamicSharedMemorySize, TG_SMEM);

    // 0. fp16 weight conversions
    f2h_kernel<<<(E_ * 3 * HD_) / 1024, 256>>>(Wqkv, wqkv16);
    f2h_kernel<<<(HD_ * E_) / 1024, 256>>>(Wo, wo16);
    f2h_kernel<<<(E_ * DFF_) / 1024, 256>>>(Ww, ww16);
    f2h_kernel<<<(E_ * DFF_) / 1024, 256>>>(Wv, wv16);
    f2h_kernel<<<(DFF_ * E_) / 1024, 256>>>(Wout, wout16);

    // 1. h16 = rmsnorm(X)
    rmsnorm_kernel<<<M_, 256>>>(X, h16);
    // 2. qkv16 = h16 @ wqkv16 + bqkv   (fp16 out)
    hgemm_kernel<<<dim3(3 * HD_ / BN, M_ / BM), 256, TG_SMEM>>>(
        M_, 3 * HD_, E_, h16, wqkv16, bqkv, nullptr, nullptr, qkv16,
        nullptr, nullptr, nullptr);
    // 3. attention (fp16 mma flash)
    attn_kernel<<<dim3(L_ / 64, H_, B_), 128, ATT_SMEM>>>(qkv16, ctx16);
    // 4. x = X + ctx16 @ wo16 + bo   (fp32 out)
    hgemm_kernel<<<dim3(E_ / BN, M_ / BM), 256, TG_SMEM>>>(
        M_, E_, HD_, ctx16, wo16, bo, X, x_p, nullptr,
        nullptr, nullptr, nullptr);
    // 5+6. x = x + rmsnorm(x); h16 = rmsnorm(x)
    addnorm_kernel<<<M_, 256>>>(x_p, h16);
    // 7. gate16 = h16 @ ww16 ; val16 = h16 @ wv16  (fp16 out, z selects)
    hgemm_kernel<<<dim3(DFF_ / BN, M_ / BM, 2), 256, TG_SMEM>>>(
        M_, DFF_, E_, h16, ww16, nullptr, nullptr, nullptr, gate16,
        wv16, nullptr, val16);
    // 8. gg16 = gelu(gate16) * val16
    geglu_kernel<<<(M_ * DFF_) / 1024, 256>>>(gate16, val16, gg16);
    // 9. out = x + gg16 @ wout16   (fp32 out)
    hgemm_kernel<<<dim3(E_ / BN, M_ / BM), 256, TG_SMEM>>>(
        M_, E_, DFF_, gg16, wout16, nullptr, x_p, out, nullptr,
        nullptr, nullptr, nullptr);
}

// round 11
// speedup vs baseline: 1.6796x; 1.1050x over previous
#include <cuda_runtime.h>
#include <cuda_fp16.h>
#include <math_constants.h>
#include <cstdint>

#define B_   2
#define L_   2048
#define E_   1024
#define H_   16
#define D_   64
#define DFF_ 4096
#define M_   (B_ * L_)   // 4096 tokens
#define HD_  (H_ * D_)   // 1024

// ---------------- scratch (device globals: allocation-guard safe) ----------------
__device__ float  g_x[M_ * E_];
__device__ __half g_h16[M_ * E_];
__device__ __half g_qkv16[(size_t)M_ * 3 * HD_];
__device__ __half g_ctx16[M_ * HD_];
__device__ __half g_gate16[(size_t)M_ * DFF_];
__device__ __half g_val16[(size_t)M_ * DFF_];
__device__ __half g_gg16[(size_t)M_ * DFF_];
// fp16 weights
__device__ __half g_wqkv16[(size_t)E_ * 3 * HD_];
__device__ __half g_wo16[(size_t)HD_ * E_];
__device__ __half g_ww16[(size_t)E_ * DFF_];
__device__ __half g_wv16[(size_t)E_ * DFF_];
__device__ __half g_wout16[(size_t)DFF_ * E_];

__device__ __forceinline__ uint32_t h2u(__half2 h) {
    return *reinterpret_cast<uint32_t*>(&h);
}

// ---------------- fused fp32->fp16 conversion for ALL 5 weight tensors ----------------
// segment sizes in float4 units (compile-time): 786432, 262144, 1048576 x3 = 4194304 total
__global__ __launch_bounds__(256) void f2h_all_kernel(
    const float* __restrict__ s0, __half* __restrict__ d0,
    const float* __restrict__ s1, __half* __restrict__ d1,
    const float* __restrict__ s2, __half* __restrict__ d2,
    const float* __restrict__ s3, __half* __restrict__ d3,
    const float* __restrict__ s4, __half* __restrict__ d4) {
    unsigned i = blockIdx.x * 256 + threadIdx.x;
    const float* s; __half* d; unsigned off;
    if (i < 786432u)       { s = s0; d = d0; off = i; }
    else if (i < 1048576u) { s = s1; d = d1; off = i - 786432u; }
    else if (i < 2097152u) { s = s2; d = d2; off = i - 1048576u; }
    else if (i < 3145728u) { s = s3; d = d3; off = i - 2097152u; }
    else                   { s = s4; d = d4; off = i - 3145728u; }
    float4 v = ((const float4*)s)[off];
    ((uint2*)d)[off] = make_uint2(h2u(__floats2half2_rn(v.x, v.y)),
                                  h2u(__floats2half2_rn(v.z, v.w)));
}

// ---------------- rmsnorm (fp16 out) ----------------
__global__ __launch_bounds__(256) void rmsnorm_kernel(const float* __restrict__ x,
                                                      __half* __restrict__ y) {
    int row = blockIdx.x;
    float4 a = ((const float4*)(x + (size_t)row * E_))[threadIdx.x];
    float ss = a.x * a.x + a.y * a.y + a.z * a.z + a.w * a.w;
    __shared__ float red[8];
    __shared__ float sinv;
#pragma unroll
    for (int o = 16; o > 0; o >>= 1) ss += __shfl_xor_sync(0xffffffffu, ss, o);
    if ((threadIdx.x & 31) == 0) red[threadIdx.x >> 5] = ss;
    __syncthreads();
    if (threadIdx.x == 0) {
        float t = 0.f;
#pragma unroll
        for (int i = 0; i < 8; i++) t += red[i];
        sinv = rsqrtf(t * (1.0f / E_));
    }
    __syncthreads();
    float c = sinv;
    ((uint2*)(y + (size_t)row * E_))[threadIdx.x] =
        make_uint2(h2u(__floats2half2_rn(a.x * c, a.y * c)),
                   h2u(__floats2half2_rn(a.z * c, a.w * c)));
}

// ---------------- fused: x = x + rmsnorm(x); h16 = rmsnorm(x) ----------------
__global__ __launch_bounds__(256) void addnorm_kernel(float* __restrict__ x,
                                                      __half* __restrict__ h) {
    int row = blockIdx.x;
    float4 a = ((const float4*)(x + (size_t)row * E_))[threadIdx.x];
    __shared__ float red[8];
    __shared__ float sval;
    float ss = a.x * a.x + a.y * a.y + a.z * a.z + a.w * a.w;
#pragma unroll
    for (int o = 16; o > 0; o >>= 1) ss += __shfl_xor_sync(0xffffffffu, ss, o);
    if ((threadIdx.x & 31) == 0) red[threadIdx.x >> 5] = ss;
    __syncthreads();
    if (threadIdx.x == 0) {
        float t = 0.f;
#pragma unroll
        for (int i = 0; i < 8; i++) t += red[i];
        sval = 1.0f + rsqrtf(t * (1.0f / E_));
    }
    __syncthreads();
    float c = sval;
    a.x *= c; a.y *= c; a.z *= c; a.w *= c;
    float ss2 = a.x * a.x + a.y * a.y + a.z * a.z + a.w * a.w;
#pragma unroll
    for (int o = 16; o > 0; o >>= 1) ss2 += __shfl_xor_sync(0xffffffffu, ss2, o);
    if ((threadIdx.x & 31) == 0) red[threadIdx.x >> 5] = ss2;
    __syncthreads();
    if (threadIdx.x == 0) {
        float t = 0.f;
#pragma unroll
        for (int i = 0; i < 8; i++) t += red[i];
        sval = rsqrtf(t * (1.0f / E_));
    }
    __syncthreads();
    float inv2 = sval;
    ((float4*)(x + (size_t)row * E_))[threadIdx.x] = a;
    ((uint2*)(h + (size_t)row * E_))[threadIdx.x] =
        make_uint2(h2u(__floats2half2_rn(a.x * inv2, a.y * inv2)),
                   h2u(__floats2half2_rn(a.z * inv2, a.w * inv2)));
}

// ---------------- geglu (fp16 in/out) ----------------
__global__ __launch_bounds__(256) void geglu_kernel(const __half* __restrict__ g,
                                                    const __half* __restrict__ v,
                                                    __half* __restrict__ o) {
    int i = (blockIdx.x * 256 + threadIdx.x) * 4;
    uint2 gu = *(const uint2*)(g + i);
    uint2 vu = *(const uint2*)(v + i);
    float2 g0 = __half22float2(*reinterpret_cast<__half2*>(&gu.x));
    float2 g1 = __half22float2(*reinterpret_cast<__half2*>(&gu.y));
    float2 v0 = __half22float2(*reinterpret_cast<__half2*>(&vu.x));
    float2 v1 = __half22float2(*reinterpret_cast<__half2*>(&vu.y));
    float r0 = 0.5f * g0.x * (1.0f + erff(g0.x * 0.70710678118654752f)) * v0.x;
    float r1 = 0.5f * g0.y * (1.0f + erff(g0.y * 0.70710678118654752f)) * v0.y;
    float r2 = 0.5f * g1.x * (1.0f + erff(g1.x * 0.70710678118654752f)) * v1.x;
    float r3 = 0.5f * g1.y * (1.0f + erff(g1.y * 0.70710678118654752f)) * v1.y;
    *(uint2*)(o + i) = make_uint2(h2u(__floats2half2_rn(r0, r1)),
                                  h2u(__floats2half2_rn(r2, r3)));
}

// ================= mma helpers =================
__device__ __forceinline__ void mma_f16(float* d, const uint32_t* a, const uint32_t* b) {
    asm volatile(
        "mma.sync.aligned.m16n8k16.row.col.f32.f16.f16.f32 "
        "{%0,%1,%2,%3}, {%4,%5,%6,%7}, {%8,%9}, {%0,%1,%2,%3};\n"
        : "+f"(d[0]), "+f"(d[1]), "+f"(d[2]), "+f"(d[3])
        : "r"(a[0]), "r"(a[1]), "r"(a[2]), "r"(a[3]), "r"(b[0]), "r"(b[1]));
}

__device__ __forceinline__ void ldsm4(uint32_t* r, uint32_t saddr) {
    asm volatile("ldmatrix.sync.aligned.m8n8.x4.shared.b16 {%0,%1,%2,%3}, [%4];"
                 : "=r"(r[0]), "=r"(r[1]), "=r"(r[2]), "=r"(r[3]) : "r"(saddr));
}
__device__ __forceinline__ void ldsm2t(uint32_t* r, uint32_t saddr) {
    asm volatile("ldmatrix.sync.aligned.m8n8.x2.trans.shared.b16 {%0,%1}, [%2];"
                 : "=r"(r[0]), "=r"(r[1]) : "r"(saddr));
}
__device__ __forceinline__ void ldsm2(uint32_t* r, uint32_t saddr) {
    asm volatile("ldmatrix.sync.aligned.m8n8.x2.shared.b16 {%0,%1}, [%2];"
                 : "=r"(r[0]), "=r"(r[1]) : "r"(saddr));
}

// ================= fp16 tensor-core GEMM (R10, unchanged) =================
#define BM 128
#define BN 128
#define BK 64
#define ASTR 72
#define BSTR 136
#define ATILE_H (BM * ASTR)
#define BTILE_H (BK * BSTR)
#define STAGE_H (ATILE_H + BTILE_H)
#define TG_SMEM (2 * STAGE_H * 2)  // 71680 B

__global__ __launch_bounds__(256, 2) void hgemm_kernel(
    int M, int N, int K,
    const __half* __restrict__ A, const __half* __restrict__ B,
    const float* __restrict__ bias, const float* __restrict__ res,
    float* __restrict__ C, __half* __restrict__ C16,
    const __half* __restrict__ B2, float* __restrict__ C2, __half* __restrict__ C216) {
    extern __shared__ __half sm[];

    if (blockIdx.z) { B = B2; C = C2; C16 = C216; }

    const int tid  = threadIdx.x;
    const int bm   = blockIdx.y * BM;
    const int bn   = blockIdx.x * BN;
    const int warp = tid >> 5, lane = tid & 31;
    const int wm   = (warp >> 2) * 64;
    const int wn   = (warp & 3) * 32;
    const int fr   = lane >> 2;
    const int fc   = lane & 3;
    const int arow_l = ((lane >> 3) & 1) * 8 + (lane & 7);
    const int acol_l = ((lane >> 4) & 1) * 8;
    const int brow_l = arow_l;

    float acc[4][4][4];
#pragma unroll
    for (int i = 0; i < 4; i++)
#pragma unroll
        for (int j = 0; j < 4; j++)
#pragma unroll
            for (int k = 0; k < 4; k++) acc[i][j][k] = 0.f;

    auto fill = [&](int s, int kt) {
        __half* Ad = sm + s * STAGE_H;
        __half* Bd = Ad + ATILE_H;
#pragma unroll
        for (int p = 0; p < 4; p++) {
            int idx = p * 256 + tid;
            int row = idx & 127, c8 = idx >> 7;
            uint32_t dst = (uint32_t)__cvta_generic_to_shared(Ad + row * ASTR + c8 * 8);
            const __half* src = A + (size_t)(bm + row) * K + kt + c8 * 8;
            asm volatile("cp.async.cg.shared.global [%0], [%1], 16;\n" :: "r"(dst), "l"(src));
        }
#pragma unroll
        for (int p = 0; p < 4; p++) {
            int idx = p * 256 + tid;
            int row = idx >> 4, c16 = idx & 15;
            uint32_t dst = (uint32_t)__cvta_generic_to_shared(Bd + row * BSTR + c16 * 8);
            const __half* src = B + (size_t)(kt + row) * N + bn + c16 * 8;
            asm volatile("cp.async.cg.shared.global [%0], [%1], 16;\n" :: "r"(dst), "l"(src));
        }
        asm volatile("cp.async.commit_group;\n");
    };

    auto compute_tile = [&](int s) {
        const __half* Ab = sm + s * STAGE_H;
        const __half* Bb = Ab + ATILE_H;
        uint32_t abase = (uint32_t)__cvta_generic_to_shared(Ab + (wm + arow_l) * ASTR + acol_l);
        uint32_t bbase = (uint32_t)__cvta_generic_to_shared(Bb + brow_l * BSTR + wn);
#pragma unroll
        for (int ks = 0; ks < 4; ks++) {
            uint32_t af[4][4], bf[4][2];
#pragma unroll
            for (int mi = 0; mi < 4; mi++)
                ldsm4(af[mi], abase + (mi * 16 * ASTR + ks * 16) * 2);
#pragma unroll
            for (int ni = 0; ni < 4; ni++)
                ldsm2t(bf[ni], bbase + (ks * 16 * BSTR + ni * 8) * 2);
#pragma unroll
            for (int mi = 0; mi < 4; mi++)
#pragma unroll
                for (int ni = 0; ni < 4; ni++) mma_f16(acc[mi][ni], af[mi], bf[ni]);
        }
    };

    const int kiters = K / BK;
    fill(0, 0);
    asm volatile("cp.async.wait_group 0;\n");
    __syncthreads();

#pragma unroll 1
    for (int it = 0; it < kiters; ++it) {
        int cur = it & 1;
        if (it + 1 < kiters) fill(cur ^ 1, (it + 1) * BK);
        compute_tile(cur);
        asm volatile("cp.async.wait_group 0;\n");
        __syncthreads();
    }

#pragma unroll
    for (int mi = 0; mi < 4; mi++) {
#pragma unroll
        for (int ni = 0; ni < 4; ni++) {
            int gr = bm + wm + mi * 16 + fr;
            int gc = bn + wn + ni * 8 + fc * 2;
            float2 o0 = make_float2(acc[mi][ni][0], acc[mi][ni][1]);
            float2 o1 = make_float2(acc[mi][ni][2], acc[mi][ni][3]);
            if (bias) {
                float2 bv = *(const float2*)(bias + gc);
                o0.x += bv.x; o0.y += bv.y;
                o1.x += bv.x; o1.y += bv.y;
            }
            if (res) {
                float2 r0 = *(const float2*)(res + (size_t)gr * N + gc);
                float2 r1 = *(const float2*)(res + (size_t)(gr + 8) * N + gc);
                o0.x += r0.x; o0.y += r0.y;
                o1.x += r1.x; o1.y += r1.y;
            }
            if (C16) {
                *(__half2*)(C16 + (size_t)gr * N + gc) = __floats2half2_rn(o0.x, o0.y);
                *(__half2*)(C16 + (size_t)(gr + 8) * N + gc) = __floats2half2_rn(o1.x, o1.y);
            } else {
                *(float2*)(C + (size_t)gr * N + gc) = o0;
                *(float2*)(C + (size_t)(gr + 8) * N + gc) = o1;
            }
        }
    }
}

// ================= fp16 flash attention, cp.async double-buffered K/V =================
// K stored NATURAL [key][d] (cp.async); S B-frags via plain ldsm2 (== trans-ldsm of [d][key]).
// V natural [key][d] = [k][n] for PV, ldsm2t (validated pattern). Double-buffered K/V.
#define ATSTR 72
#define ATT_TILE_H (64 * ATSTR)                 // 4608 halves
#define ATT_SMEM (6 * ATT_TILE_H * 2)           // 55296 B

__global__ __launch_bounds__(128) void attn_kernel(const __half* __restrict__ qkv,
                                                   __half* __restrict__ ctx) {
    extern __shared__ __half smh[];
    __half* Qs = smh;
    __half* Ps = Qs + ATT_TILE_H;
    __half* KV = Ps + ATT_TILE_H;   // [buf][K(4608) | V(4608)]

    const int qt = blockIdx.x, h = blockIdx.y, b = blockIdx.z;
    const int m0 = qt * 64;
    const int tid  = threadIdx.x;
    const int warp = tid >> 5, lane = tid & 31;
    const int fr = lane >> 2, fc = lane & 3;
    const int w16 = warp * 16;
    const int arow_l = ((lane >> 3) & 1) * 8 + (lane & 7);
    const int acol_l = ((lane >> 4) & 1) * 8;
    const int brow_l = arow_l;                   // ldsm2t lanes 0-15 -> k rows 0..15
    const int krow_l = lane & 7;                 // plain ldsm2 lanes: tile row
    const int ksel_l = ((lane >> 3) & 1) * 8;    // tile0/tile1 k offset
    const float slope = exp2f(-(1.0f + 7.0f * (float)h / 15.0f));
    const __half2 qscale = __floats2half2_rn(0.125f, 0.125f);

    // ---- async fill of K+V tile kt into buffer bufsel ----
    auto fill_kv = [&](int kt, int bufsel) {
        __half* Kd = KV + bufsel * 2 * ATT_TILE_H;
        __half* Vd = Kd + ATT_TILE_H;
        const int n0 = kt * 64;
#pragma unroll
        for (int p = 0; p < 4; p++) {
            int i = p * 128 + tid;
            int r = i >> 3, c = (i & 7) * 8;     // 8 halves (16B) per chunk
            size_t base = ((size_t)(b * L_ + n0 + r) * H_ + h) * 3;
            uint32_t kd = (uint32_t)__cvta_generic_to_shared(Kd + r * ATSTR + c);
            uint32_t vd = (uint32_t)__cvta_generic_to_shared(Vd + r * ATSTR + c);
            const __half* ks = qkv + (base + 1) * D_ + c;
            const __half* vs = qkv + (base + 2) * D_ + c;
            asm volatile("cp.async.cg.shared.global [%0], [%1], 16;\n" :: "r"(kd), "l"(ks));
            asm volatile("cp.async.cg.shared.global [%0], [%1], 16;\n" :: "r"(vd), "l"(vs));
        }
        asm volatile("cp.async.commit_group;\n");
    };

    // ---- load Q tile (scaled 1/8) ----
    for (int i = tid; i < 64 * 16; i += 128) {
        int r = i >> 4, c = (i & 15) << 2;
        uint2 v = *(const uint2*)(qkv + ((((size_t)(b * L_ + m0 + r) * H_ + h) * 3 + 0) * D_ + c));
        __half2 q0 = __hmul2(*reinterpret_cast<__half2*>(&v.x), qscale);
        __half2 q1 = __hmul2(*reinterpret_cast<__half2*>(&v.y), qscale);
        *(uint2*)(Qs + r * ATSTR + c) = make_uint2(h2u(q0), h2u(q1));
    }
    fill_kv(0, 0);
    __syncthreads();

    const uint32_t qbase = (uint32_t)__cvta_generic_to_shared(Qs + (w16 + arow_l) * ATSTR + acol_l);
    const uint32_t pbase = (uint32_t)__cvta_generic_to_shared(Ps + (w16 + arow_l) * ATSTR + acol_l);

    uint32_t qf[4][4];
#pragma unroll
    for (int ks = 0; ks < 4; ks++) ldsm4(qf[ks], qbase + ks * 16 * 2);

    float oacc[8][4];
#pragma unroll
    for (int i = 0; i < 8; i++)
#pragma unroll
        for (int j = 0; j < 4; j++) oacc[i][j] = 0.f;
    float mrow0 = -CUDART_INF_F, mrow1 = -CUDART_INF_F;
    float lrow0 = 0.f, lrow1 = 0.f;

    const int gi0 = m0 + w16 + fr;
    const int gi1 = gi0 + 8;

#pragma unroll 1
    for (int kt = 0; kt <= qt; kt++) {
        const int n0 = kt * 64;
        const int bufsel = kt & 1;
        if (kt + 1 <= qt) {
            fill_kv(kt + 1, bufsel ^ 1);
            asm volatile("cp.async.wait_group 1;\n");
        } else {
            asm volatile("cp.async.wait_group 0;\n");
        }
        __syncthreads();   // cp.async data for tile kt visible to all warps

        const __half* Kd = KV + bufsel * 2 * ATT_TILE_H;
        const __half* Vd = Kd + ATT_TILE_H;
        const uint32_t kbase = (uint32_t)__cvta_generic_to_shared(Kd + krow_l * ATSTR + ksel_l);
        const uint32_t vbase = (uint32_t)__cvta_generic_to_shared(Vd + brow_l * ATSTR);

        // ---- S = (Q/8) K^T : B-frags from natural K via plain ldsm2 ----
        float sacc[8][4];
#pragma unroll
        for (int i = 0; i < 8; i++)
#pragma unroll
            for (int j = 0; j < 4; j++) sacc[i][j] = 0.f;
#pragma unroll
        for (int ks = 0; ks < 4; ks++) {
            uint32_t bf[8][2];
#pragma unroll
            for (int ni = 0; ni < 8; ni++)
                ldsm2(bf[ni], kbase + (ni * 8 * ATSTR + ks * 16) * 2);
#pragma unroll
            for (int ni = 0; ni < 8; ni++) mma_f16(sacc[ni], qf[ks], bf[ni]);
        }

        // ---- alibi + causal on fragments ----
#pragma unroll
        for (int ni = 0; ni < 8; ni++) {
            int gj = n0 + ni * 8 + 2 * fc;
            float a0 = slope * (float)(gj - gi0);
            float a1 = slope * (float)(gj + 1 - gi0);
            float a2 = slope * (float)(gj - gi1);
            float a3 = slope * (float)(gj + 1 - gi1);
            sacc[ni][0] = (gj     > gi0) ? -CUDART_INF_F : sacc[ni][0] + a0;
            sacc[ni][1] = (gj + 1 > gi0) ? -CUDART_INF_F : sacc[ni][1] + a1;
            sacc[ni][2] = (gj     > gi1) ? -CUDART_INF_F : sacc[ni][2] + a2;
            sacc[ni][3] = (gj + 1 > gi1) ? -CUDART_INF_F : sacc[ni][3] + a3;
        }

        // ---- online softmax ----
        float mx0 = -CUDART_INF_F, mx1 = -CUDART_INF_F;
#pragma unroll
        for (int ni = 0; ni < 8; ni++) {
            mx0 = fmaxf(mx0, fmaxf(sacc[ni][0], sacc[ni][1]));
            mx1 = fmaxf(mx1, fmaxf(sacc[ni][2], sacc[ni][3]));
        }
        mx0 = fmaxf(mx0, __shfl_xor_sync(0xffffffffu, mx0, 1));
        mx0 = fmaxf(mx0, __shfl_xor_sync(0xffffffffu, mx0, 2));
        mx1 = fmaxf(mx1, __shfl_xor_sync(0xffffffffu, mx1, 1));
        mx1 = fmaxf(mx1, __shfl_xor_sync(0xffffffffu, mx1, 2));
        float mn0 = fmaxf(mrow0, mx0);
        float mn1 = fmaxf(mrow1, mx1);
        float alpha0 = __expf(mrow0 - mn0);
        float alpha1 = __expf(mrow1 - mn1);
        float rs0 = 0.f, rs1 = 0.f;
#pragma unroll
        for (int ni = 0; ni < 8; ni++) {
            sacc[ni][0] = __expf(sacc[ni][0] - mn0);
            sacc[ni][1] = __expf(sacc[ni][1] - mn0);
            sacc[ni][2] = __expf(sacc[ni][2] - mn1);
            sacc[ni][3] = __expf(sacc[ni][3] - mn1);
            rs0 += sacc[ni][0] + sacc[ni][1];
            rs1 += sacc[ni][2] + sacc[ni][3];
        }
        rs0 += __shfl_xor_sync(0xffffffffu, rs0, 1);
        rs0 += __shfl_xor_sync(0xffffffffu, rs0, 2);
        rs1 += __shfl_xor_sync(0xffffffffu, rs1, 1);
        rs1 += __shfl_xor_sync(0xffffffffu, rs1, 2);
        lrow0 = lrow0 * alpha0 + rs0;
        lrow1 = lrow1 * alpha1 + rs1;
        mrow0 = mn0;
        mrow1 = mn1;
#pragma unroll
        for (int ni = 0; ni < 8; ni++) {
            oacc[ni][0] *= alpha0;
            oacc[ni][1] *= alpha0;
            oacc[ni][2] *= alpha1;
            oacc[ni][3] *= alpha1;
        }

        // ---- P fragments -> fp16 smem (warp-private rows) ----
#pragma unroll
        for (int ni = 0; ni < 8; ni++) {
            int c = ni * 8 + 2 * fc;
            *(__half2*)&Ps[(w16 + fr) * ATSTR + c]     = __floats2half2_rn(sacc[ni][0], sacc[ni][1]);
            *(__half2*)&Ps[(w16 + fr + 8) * ATSTR + c] = __floats2half2_rn(sacc[ni][2], sacc[ni][3]);
        }
        __syncwarp();

        // ---- O += P @ V via m16n8k16 (V natural [k][n], ldsm2t) ----
#pragma unroll
        for (int ks = 0; ks < 4; ks++) {
            uint32_t af[4];
            ldsm4(af, pbase + ks * 16 * 2);
#pragma unroll
            for (int ni = 0; ni < 8; ni++) {
                uint32_t bf[2];
                ldsm2t(bf, vbase + (ks * 16 * ATSTR + ni * 8) * 2);
                mma_f16(oacc[ni], af, bf);
            }
        }
        __syncthreads();   // all warps done reading buf before next iter's fill overwrites it
    }

    float inv0 = 1.0f / lrow0;
    float inv1 = 1.0f / lrow1;
#pragma unroll
    for (int ni = 0; ni < 8; ni++) {
        int c = h * D_ + ni * 8 + 2 * fc;
        *(__half2*)(ctx + (size_t)(b * L_ + gi0) * HD_ + c) =
            __floats2half2_rn(oacc[ni][0] * inv0, oacc[ni][1] * inv0);
        *(__half2*)(ctx + (size_t)(b * L_ + gi1) * HD_ + c) =
            __floats2half2_rn(oacc[ni][2] * inv1, oacc[ni][3] * inv1);
    }
}

// ---------------- launch ----------------
extern "C" void kernel_launch(void* const* d_in, const int* in_sizes, int n_in,
                              void* d_out, int out_size) {
    (void)in_sizes; (void)n_in; (void)out_size;
    const float* X    = (const float*)d_in[0];
    const float* Wqkv = (const float*)d_in[2];
    const float* bqkv = (const float*)d_in[3];
    const float* Wo   = (const float*)d_in[4];
    const float* bo   = (const float*)d_in[5];
    const float* Ww   = (const float*)d_in[12];
    const float* Wv   = (const float*)d_in[13];
    const float* Wout = (const float*)d_in[14];
    float* out = (float*)d_out;

    float *x_p;
    __half *h16, *qkv16, *ctx16, *gate16, *val16, *gg16;
    __half *wqkv16, *wo16, *ww16, *wv16, *wout16;
    cudaGetSymbolAddress((void**)&x_p,    g_x);
    cudaGetSymbolAddress((void**)&h16,    g_h16);
    cudaGetSymbolAddress((void**)&qkv16,  g_qkv16);
    cudaGetSymbolAddress((void**)&ctx16,  g_ctx16);
    cudaGetSymbolAddress((void**)&gate16, g_gate16);
    cudaGetSymbolAddress((void**)&val16,  g_val16);
    cudaGetSymbolAddress((void**)&gg16,   g_gg16);
    cudaGetSymbolAddress((void**)&wqkv16, g_wqkv16);
    cudaGetSymbolAddress((void**)&wo16,   g_wo16);
    cudaGetSymbolAddress((void**)&ww16,   g_ww16);
    cudaGetSymbolAddress((void**)&wv16,   g_wv16);
    cudaGetSymbolAddress((void**)&wout16, g_wout16);

    cudaFuncSetAttribute(attn_kernel, cudaFuncAttributeMaxDynamicSharedMemorySize, ATT_SMEM);
    cudaFuncSetAttribute(hgemm_kernel, cudaFuncAttributeMaxDynamicSharedMemorySize, TG_SMEM);

    // 0. all fp16 weight conversions in one launch (4194304 float4 / 256)
    f2h_all_kernel<<<16384, 256>>>(Wqkv, wqkv16, Wo, wo16, Ww, ww16, Wv, wv16, Wout, wout16);

    // 1. h16 = rmsnorm(X)
    rmsnorm_kernel<<<M_, 256>>>(X, h16);
    // 2. qkv16 = h16 @ wqkv16 + bqkv   (fp16 out)
    hgemm_kernel<<<dim3(3 * HD_ / BN, M_ / BM), 256, TG_SMEM>>>(
        M_, 3 * HD_, E_, h16, wqkv16, bqkv, nullptr, nullptr, qkv16,
        nullptr, nullptr, nullptr);
    // 3. attention (fp16 mma flash, cp.async pipelined)
    attn_kernel<<<dim3(L_ / 64, H_, B_), 128, ATT_SMEM>>>(qkv16, ctx16);
    // 4. x = X + ctx16 @ wo16 + bo   (fp32 out)
    hgemm_kernel<<<dim3(E_ / BN, M_ / BM), 256, TG_SMEM>>>(
        M_, E_, HD_, ctx16, wo16, bo, X, x_p, nullptr,
        nullptr, nullptr, nullptr);
    // 5+6. x = x + rmsnorm(x); h16 = rmsnorm(x)
    addnorm_kernel<<<M_, 256>>>(x_p, h16);
    // 7. gate16 = h16 @ ww16 ; val16 = h16 @ wv16  (fp16 out, z selects)
    hgemm_kernel<<<dim3(DFF_ / BN, M_ / BM, 2), 256, TG_SMEM>>>(
        M_, DFF_, E_, h16, ww16, nullptr, nullptr, nullptr, gate16,
        wv16, nullptr, val16);
    // 8. gg16 = gelu(gate16) * val16
    geglu_kernel<<<(M_ * DFF_) / 1024, 256>>>(gate16, val16, gg16);
    // 9. out = x + gg16 @ wout16   (fp32 out)
    hgemm_kernel<<<dim3(E_ / BN, M_ / BM), 256, TG_SMEM>>>(
        M_, E_, DFF_, gg16, wout16, nullptr, x_p, out, nullptr,
        nullptr, nullptr, nullptr);
}

// round 12
// speedup vs baseline: 1.9252x; 1.1463x over previous
#include <cuda_runtime.h>
#include <cuda_fp16.h>
#include <math_constants.h>
#include <cstdint>

#define B_   2
#define L_   2048
#define E_   1024
#define H_   16
#define D_   64
#define DFF_ 4096
#define M_   (B_ * L_)   // 4096 tokens
#define HD_  (H_ * D_)   // 1024

// ---------------- scratch (device globals: allocation-guard safe) ----------------
__device__ float  g_x[M_ * E_];
__device__ __half g_h16[M_ * E_];
__device__ __half g_qkv16[(size_t)M_ * 3 * HD_];
__device__ __half g_ctx16[M_ * HD_];
__device__ __half g_gate16[(size_t)M_ * DFF_];
__device__ __half g_val16[(size_t)M_ * DFF_];
__device__ __half g_gg16[(size_t)M_ * DFF_];
__device__ __half g_wqkv16[(size_t)E_ * 3 * HD_];
__device__ __half g_wo16[(size_t)HD_ * E_];
__device__ __half g_ww16[(size_t)E_ * DFF_];
__device__ __half g_wv16[(size_t)E_ * DFF_];
__device__ __half g_wout16[(size_t)DFF_ * E_];

__device__ __forceinline__ uint32_t h2u(__half2 h) {
    return *reinterpret_cast<uint32_t*>(&h);
}

// ---------------- fused fp32->fp16 conversion for ALL 5 weight tensors ----------------
__global__ __launch_bounds__(256) void f2h_all_kernel(
    const float* __restrict__ s0, __half* __restrict__ d0,
    const float* __restrict__ s1, __half* __restrict__ d1,
    const float* __restrict__ s2, __half* __restrict__ d2,
    const float* __restrict__ s3, __half* __restrict__ d3,
    const float* __restrict__ s4, __half* __restrict__ d4) {
    unsigned i = blockIdx.x * 256 + threadIdx.x;
    const float* s; __half* d; unsigned off;
    if (i < 786432u)       { s = s0; d = d0; off = i; }
    else if (i < 1048576u) { s = s1; d = d1; off = i - 786432u; }
    else if (i < 2097152u) { s = s2; d = d2; off = i - 1048576u; }
    else if (i < 3145728u) { s = s3; d = d3; off = i - 2097152u; }
    else                   { s = s4; d = d4; off = i - 3145728u; }
    float4 v = ((const float4*)s)[off];
    ((uint2*)d)[off] = make_uint2(h2u(__floats2half2_rn(v.x, v.y)),
                                  h2u(__floats2half2_rn(v.z, v.w)));
}

// ---------------- rmsnorm (fp16 out) ----------------
__global__ __launch_bounds__(256) void rmsnorm_kernel(const float* __restrict__ x,
                                                      __half* __restrict__ y) {
    int row = blockIdx.x;
    float4 a = ((const float4*)(x + (size_t)row * E_))[threadIdx.x];
    float ss = a.x * a.x + a.y * a.y + a.z * a.z + a.w * a.w;
    __shared__ float red[8];
    __shared__ float sinv;
#pragma unroll
    for (int o = 16; o > 0; o >>= 1) ss += __shfl_xor_sync(0xffffffffu, ss, o);
    if ((threadIdx.x & 31) == 0) red[threadIdx.x >> 5] = ss;
    __syncthreads();
    if (threadIdx.x == 0) {
        float t = 0.f;
#pragma unroll
        for (int i = 0; i < 8; i++) t += red[i];
        sinv = rsqrtf(t * (1.0f / E_));
    }
    __syncthreads();
    float c = sinv;
    ((uint2*)(y + (size_t)row * E_))[threadIdx.x] =
        make_uint2(h2u(__floats2half2_rn(a.x * c, a.y * c)),
                   h2u(__floats2half2_rn(a.z * c, a.w * c)));
}

// ---------------- fused: x = x + rmsnorm(x); h16 = rmsnorm(x) ----------------
__global__ __launch_bounds__(256) void addnorm_kernel(float* __restrict__ x,
                                                      __half* __restrict__ h) {
    int row = blockIdx.x;
    float4 a = ((const float4*)(x + (size_t)row * E_))[threadIdx.x];
    __shared__ float red[8];
    __shared__ float sval;
    float ss = a.x * a.x + a.y * a.y + a.z * a.z + a.w * a.w;
#pragma unroll
    for (int o = 16; o > 0; o >>= 1) ss += __shfl_xor_sync(0xffffffffu, ss, o);
    if ((threadIdx.x & 31) == 0) red[threadIdx.x >> 5] = ss;
    __syncthreads();
    if (threadIdx.x == 0) {
        float t = 0.f;
#pragma unroll
        for (int i = 0; i < 8; i++) t += red[i];
        sval = 1.0f + rsqrtf(t * (1.0f / E_));
    }
    __syncthreads();
    float c = sval;
    a.x *= c; a.y *= c; a.z *= c; a.w *= c;
    float ss2 = a.x * a.x + a.y * a.y + a.z * a.z + a.w * a.w;
#pragma unroll
    for (int o = 16; o > 0; o >>= 1) ss2 += __shfl_xor_sync(0xffffffffu, ss2, o);
    if ((threadIdx.x & 31) == 0) red[threadIdx.x >> 5] = ss2;
    __syncthreads();
    if (threadIdx.x == 0) {
        float t = 0.f;
#pragma unroll
        for (int i = 0; i < 8; i++) t += red[i];
        sval = rsqrtf(t * (1.0f / E_));
    }
    __syncthreads();
    float inv2 = sval;
    ((float4*)(x + (size_t)row * E_))[threadIdx.x] = a;
    ((uint2*)(h + (size_t)row * E_))[threadIdx.x] =
        make_uint2(h2u(__floats2half2_rn(a.x * inv2, a.y * inv2)),
                   h2u(__floats2half2_rn(a.z * inv2, a.w * inv2)));
}

// ---------------- geglu (fp16 in/out) ----------------
__global__ __launch_bounds__(256) void geglu_kernel(const __half* __restrict__ g,
                                                    const __half* __restrict__ v,
                                                    __half* __restrict__ o) {
    int i = (blockIdx.x * 256 + threadIdx.x) * 4;
    uint2 gu = *(const uint2*)(g + i);
    uint2 vu = *(const uint2*)(v + i);
    float2 g0 = __half22float2(*reinterpret_cast<__half2*>(&gu.x));
    float2 g1 = __half22float2(*reinterpret_cast<__half2*>(&gu.y));
    float2 v0 = __half22float2(*reinterpret_cast<__half2*>(&vu.x));
    float2 v1 = __half22float2(*reinterpret_cast<__half2*>(&vu.y));
    float r0 = 0.5f * g0.x * (1.0f + erff(g0.x * 0.70710678118654752f)) * v0.x;
    float r1 = 0.5f * g0.y * (1.0f + erff(g0.y * 0.70710678118654752f)) * v0.y;
    float r2 = 0.5f * g1.x * (1.0f + erff(g1.x * 0.70710678118654752f)) * v1.x;
    float r3 = 0.5f * g1.y * (1.0f + erff(g1.y * 0.70710678118654752f)) * v1.y;
    *(uint2*)(o + i) = make_uint2(h2u(__floats2half2_rn(r0, r1)),
                                  h2u(__floats2half2_rn(r2, r3)));
}

// ================= mma helpers =================
__device__ __forceinline__ void mma_f16(float* d, const uint32_t* a, const uint32_t* b) {
    asm volatile(
        "mma.sync.aligned.m16n8k16.row.col.f32.f16.f16.f32 "
        "{%0,%1,%2,%3}, {%4,%5,%6,%7}, {%8,%9}, {%0,%1,%2,%3};\n"
        : "+f"(d[0]), "+f"(d[1]), "+f"(d[2]), "+f"(d[3])
        : "r"(a[0]), "r"(a[1]), "r"(a[2]), "r"(a[3]), "r"(b[0]), "r"(b[1]));
}

__device__ __forceinline__ void ldsm4(uint32_t* r, uint32_t saddr) {
    asm volatile("ldmatrix.sync.aligned.m8n8.x4.shared.b16 {%0,%1,%2,%3}, [%4];"
                 : "=r"(r[0]), "=r"(r[1]), "=r"(r[2]), "=r"(r[3]) : "r"(saddr));
}
__device__ __forceinline__ void ldsm2t(uint32_t* r, uint32_t saddr) {
    asm volatile("ldmatrix.sync.aligned.m8n8.x2.trans.shared.b16 {%0,%1}, [%2];"
                 : "=r"(r[0]), "=r"(r[1]) : "r"(saddr));
}
__device__ __forceinline__ void ldsm2(uint32_t* r, uint32_t saddr) {
    asm volatile("ldmatrix.sync.aligned.m8n8.x2.shared.b16 {%0,%1}, [%2];"
                 : "=r"(r[0]), "=r"(r[1]) : "r"(saddr));
}

// ================= fp16 tensor-core GEMM: 64x128 CTA tile, 32x32 warp tile =================
// Smaller tile -> 32 acc regs -> 3 CTAs/SM (24 warps) for latency hiding.
#define BM 64
#define BN 128
#define BK 64
#define ASTR 72
#define BSTR 136
#define ATILE_H (BM * ASTR)         // 4608
#define BTILE_H (BK * BSTR)         // 8704
#define STAGE_H (ATILE_H + BTILE_H) // 13312
#define TG_SMEM (2 * STAGE_H * 2)   // 53248 B

__global__ __launch_bounds__(256, 3) void hgemm_kernel(
    int M, int N, int K,
    const __half* __restrict__ A, const __half* __restrict__ B,
    const float* __restrict__ bias, const float* __restrict__ res,
    float* __restrict__ C, __half* __restrict__ C16,
    const __half* __restrict__ B2, float* __restrict__ C2, __half* __restrict__ C216) {
    extern __shared__ __half sm[];

    if (blockIdx.z) { B = B2; C = C2; C16 = C216; }

    const int tid  = threadIdx.x;
    const int bm   = blockIdx.y * BM;
    const int bn   = blockIdx.x * BN;
    const int warp = tid >> 5, lane = tid & 31;
    const int wm   = (warp >> 2) * 32;            // 0 or 32
    const int wn   = (warp & 3) * 32;             // 0..96
    const int fr   = lane >> 2;
    const int fc   = lane & 3;
    const int arow_l = ((lane >> 3) & 1) * 8 + (lane & 7);
    const int acol_l = ((lane >> 4) & 1) * 8;
    const int brow_l = arow_l;

    float acc[2][4][4];
#pragma unroll
    for (int i = 0; i < 2; i++)
#pragma unroll
        for (int j = 0; j < 4; j++)
#pragma unroll
            for (int k = 0; k < 4; k++) acc[i][j][k] = 0.f;

    auto fill = [&](int s, int kt) {
        __half* Ad = sm + s * STAGE_H;
        __half* Bd = Ad + ATILE_H;
#pragma unroll
        for (int p = 0; p < 2; p++) {              // 512 A-chunks
            int idx = p * 256 + tid;
            int row = idx >> 3, c8 = idx & 7;
            uint32_t dst = (uint32_t)__cvta_generic_to_shared(Ad + row * ASTR + c8 * 8);
            const __half* src = A + (size_t)(bm + row) * K + kt + c8 * 8;
            asm volatile("cp.async.cg.shared.global [%0], [%1], 16;\n" :: "r"(dst), "l"(src));
        }
#pragma unroll
        for (int p = 0; p < 4; p++) {              // 1024 B-chunks
            int idx = p * 256 + tid;
            int row = idx >> 4, c16 = idx & 15;
            uint32_t dst = (uint32_t)__cvta_generic_to_shared(Bd + row * BSTR + c16 * 8);
            const __half* src = B + (size_t)(kt + row) * N + bn + c16 * 8;
            asm volatile("cp.async.cg.shared.global [%0], [%1], 16;\n" :: "r"(dst), "l"(src));
        }
        asm volatile("cp.async.commit_group;\n");
    };

    auto compute_tile = [&](int s) {
        const __half* Ab = sm + s * STAGE_H;
        const __half* Bb = Ab + ATILE_H;
        uint32_t abase = (uint32_t)__cvta_generic_to_shared(Ab + (wm + arow_l) * ASTR + acol_l);
        uint32_t bbase = (uint32_t)__cvta_generic_to_shared(Bb + brow_l * BSTR + wn);
#pragma unroll
        for (int ks = 0; ks < 4; ks++) {
            uint32_t af[2][4], bf[4][2];
#pragma unroll
            for (int mi = 0; mi < 2; mi++)
                ldsm4(af[mi], abase + (mi * 16 * ASTR + ks * 16) * 2);
#pragma unroll
            for (int ni = 0; ni < 4; ni++)
                ldsm2t(bf[ni], bbase + (ks * 16 * BSTR + ni * 8) * 2);
#pragma unroll
            for (int mi = 0; mi < 2; mi++)
#pragma unroll
                for (int ni = 0; ni < 4; ni++) mma_f16(acc[mi][ni], af[mi], bf[ni]);
        }
    };

    const int kiters = K / BK;
    fill(0, 0);
    asm volatile("cp.async.wait_group 0;\n");
    __syncthreads();

#pragma unroll 1
    for (int it = 0; it < kiters; ++it) {
        int cur = it & 1;
        if (it + 1 < kiters) fill(cur ^ 1, (it + 1) * BK);
        compute_tile(cur);
        asm volatile("cp.async.wait_group 0;\n");
        __syncthreads();
    }

#pragma unroll
    for (int mi = 0; mi < 2; mi++) {
#pragma unroll
        for (int ni = 0; ni < 4; ni++) {
            int gr = bm + wm + mi * 16 + fr;
            int gc = bn + wn + ni * 8 + fc * 2;
            float2 o0 = make_float2(acc[mi][ni][0], acc[mi][ni][1]);
            float2 o1 = make_float2(acc[mi][ni][2], acc[mi][ni][3]);
            if (bias) {
                float2 bv = *(const float2*)(bias + gc);
                o0.x += bv.x; o0.y += bv.y;
                o1.x += bv.x; o1.y += bv.y;
            }
            if (res) {
                float2 r0 = *(const float2*)(res + (size_t)gr * N + gc);
                float2 r1 = *(const float2*)(res + (size_t)(gr + 8) * N + gc);
                o0.x += r0.x; o0.y += r0.y;
                o1.x += r1.x; o1.y += r1.y;
            }
            if (C16) {
                *(__half2*)(C16 + (size_t)gr * N + gc) = __floats2half2_rn(o0.x, o0.y);
                *(__half2*)(C16 + (size_t)(gr + 8) * N + gc) = __floats2half2_rn(o1.x, o1.y);
            } else {
                *(float2*)(C + (size_t)gr * N + gc) = o0;
                *(float2*)(C + (size_t)(gr + 8) * N + gc) = o1;
            }
        }
    }
}

// ================= fp16 flash attention (R11 + incremental alibi + diag split) =================
#define ATSTR 72
#define ATT_TILE_H (64 * ATSTR)
#define ATT_SMEM (6 * ATT_TILE_H * 2)   // 55296 B

__global__ __launch_bounds__(128) void attn_kernel(const __half* __restrict__ qkv,
                                                   __half* __restrict__ ctx) {
    extern __shared__ __half smh[];
    __half* Qs = smh;
    __half* Ps = Qs + ATT_TILE_H;
    __half* KV = Ps + ATT_TILE_H;

    const int qt = blockIdx.x, h = blockIdx.y, b = blockIdx.z;
    const int m0 = qt * 64;
    const int tid  = threadIdx.x;
    const int warp = tid >> 5, lane = tid & 31;
    const int fr = lane >> 2, fc = lane & 3;
    const int w16 = warp * 16;
    const int arow_l = ((lane >> 3) & 1) * 8 + (lane & 7);
    const int acol_l = ((lane >> 4) & 1) * 8;
    const int brow_l = arow_l;
    const int krow_l = lane & 7;
    const int ksel_l = ((lane >> 3) & 1) * 8;
    const float slope = exp2f(-(1.0f + 7.0f * (float)h / 15.0f));
    const float step8 = 8.0f * slope;
    const __half2 qscale = __floats2half2_rn(0.125f, 0.125f);

    auto fill_kv = [&](int kt, int bufsel) {
        __half* Kd = KV + bufsel * 2 * ATT_TILE_H;
        __half* Vd = Kd + ATT_TILE_H;
        const int n0 = kt * 64;
#pragma unroll
        for (int p = 0; p < 4; p++) {
            int i = p * 128 + tid;
            int r = i >> 3, c = (i & 7) * 8;
            size_t base = ((size_t)(b * L_ + n0 + r) * H_ + h) * 3;
            uint32_t kd = (uint32_t)__cvta_generic_to_shared(Kd + r * ATSTR + c);
            uint32_t vd = (uint32_t)__cvta_generic_to_shared(Vd + r * ATSTR + c);
            const __half* ks = qkv + (base + 1) * D_ + c;
            const __half* vs = qkv + (base + 2) * D_ + c;
            asm volatile("cp.async.cg.shared.global [%0], [%1], 16;\n" :: "r"(kd), "l"(ks));
            asm volatile("cp.async.cg.shared.global [%0], [%1], 16;\n" :: "r"(vd), "l"(vs));
        }
        asm volatile("cp.async.commit_group;\n");
    };

    for (int i = tid; i < 64 * 16; i += 128) {
        int r = i >> 4, c = (i & 15) << 2;
        uint2 v = *(const uint2*)(qkv + ((((size_t)(b * L_ + m0 + r) * H_ + h) * 3 + 0) * D_ + c));
        __half2 q0 = __hmul2(*reinterpret_cast<__half2*>(&v.x), qscale);
        __half2 q1 = __hmul2(*reinterpret_cast<__half2*>(&v.y), qscale);
        *(uint2*)(Qs + r * ATSTR + c) = make_uint2(h2u(q0), h2u(q1));
    }
    fill_kv(0, 0);
    __syncthreads();

    const uint32_t qbase = (uint32_t)__cvta_generic_to_shared(Qs + (w16 + arow_l) * ATSTR + acol_l);
    const uint32_t pbase = (uint32_t)__cvta_generic_to_shared(Ps + (w16 + arow_l) * ATSTR + acol_l);

    uint32_t qf[4][4];
#pragma unroll
    for (int ks = 0; ks < 4; ks++) ldsm4(qf[ks], qbase + ks * 16 * 2);

    float oacc[8][4];
#pragma unroll
    for (int i = 0; i < 8; i++)
#pragma unroll
        for (int j = 0; j < 4; j++) oacc[i][j] = 0.f;
    float mrow0 = -CUDART_INF_F, mrow1 = -CUDART_INF_F;
    float lrow0 = 0.f, lrow1 = 0.f;

    const int gi0 = m0 + w16 + fr;
    const int gi1 = gi0 + 8;

#pragma unroll 1
    for (int kt = 0; kt <= qt; kt++) {
        const int n0 = kt * 64;
        const int bufsel = kt & 1;
        if (kt + 1 <= qt) {
            fill_kv(kt + 1, bufsel ^ 1);
            asm volatile("cp.async.wait_group 1;\n");
        } else {
            asm volatile("cp.async.wait_group 0;\n");
        }
        __syncthreads();

        const __half* Kd = KV + bufsel * 2 * ATT_TILE_H;
        const __half* Vd = Kd + ATT_TILE_H;
        const uint32_t kbase = (uint32_t)__cvta_generic_to_shared(Kd + krow_l * ATSTR + ksel_l);
        const uint32_t vbase = (uint32_t)__cvta_generic_to_shared(Vd + brow_l * ATSTR);

        float sacc[8][4];
#pragma unroll
        for (int i = 0; i < 8; i++)
#pragma unroll
            for (int j = 0; j < 4; j++) sacc[i][j] = 0.f;
#pragma unroll
        for (int ks = 0; ks < 4; ks++) {
            uint32_t bf[8][2];
#pragma unroll
            for (int ni = 0; ni < 8; ni++)
                ldsm2(bf[ni], kbase + (ni * 8 * ATSTR + ks * 16) * 2);
#pragma unroll
            for (int ni = 0; ni < 8; ni++) mma_f16(sacc[ni], qf[ks], bf[ni]);
        }

        // ---- alibi (incremental) + causal (diag tile only) ----
        {
            float a0 = slope * (float)(n0 + 2 * fc - gi0);
            float a2 = slope * (float)(n0 + 2 * fc - gi1);
            if (kt < qt) {
#pragma unroll
                for (int ni = 0; ni < 8; ni++) {
                    sacc[ni][0] += a0;
                    sacc[ni][1] += a0 + slope;
                    sacc[ni][2] += a2;
                    sacc[ni][3] += a2 + slope;
                    a0 += step8;
                    a2 += step8;
                }
            } else {
#pragma unroll
                for (int ni = 0; ni < 8; ni++) {
                    int gj = n0 + ni * 8 + 2 * fc;
                    sacc[ni][0] = (gj     > gi0) ? -CUDART_INF_F : sacc[ni][0] + a0;
                    sacc[ni][1] = (gj + 1 > gi0) ? -CUDART_INF_F : sacc[ni][1] + a0 + slope;
                    sacc[ni][2] = (gj     > gi1) ? -CUDART_INF_F : sacc[ni][2] + a2;
                    sacc[ni][3] = (gj + 1 > gi1) ? -CUDART_INF_F : sacc[ni][3] + a2 + slope;
                    a0 += step8;
                    a2 += step8;
                }
            }
        }

        float mx0 = -CUDART_INF_F, mx1 = -CUDART_INF_F;
#pragma unroll
        for (int ni = 0; ni < 8; ni++) {
            mx0 = fmaxf(mx0, fmaxf(sacc[ni][0], sacc[ni][1]));
            mx1 = fmaxf(mx1, fmaxf(sacc[ni][2], sacc[ni][3]));
        }
        mx0 = fmaxf(mx0, __shfl_xor_sync(0xffffffffu, mx0, 1));
        mx0 = fmaxf(mx0, __shfl_xor_sync(0xffffffffu, mx0, 2));
        mx1 = fmaxf(mx1, __shfl_xor_sync(0xffffffffu, mx1, 1));
        mx1 = fmaxf(mx1, __shfl_xor_sync(0xffffffffu, mx1, 2));
        float mn0 = fmaxf(mrow0, mx0);
        float mn1 = fmaxf(mrow1, mx1);
        float alpha0 = __expf(mrow0 - mn0);
        float alpha1 = __expf(mrow1 - mn1);
        float rs0 = 0.f, rs1 = 0.f;
#pragma unroll
        for (int ni = 0; ni < 8; ni++) {
            sacc[ni][0] = __expf(sacc[ni][0] - mn0);
            sacc[ni][1] = __expf(sacc[ni][1] - mn0);
            sacc[ni][2] = __expf(sacc[ni][2] - mn1);
            sacc[ni][3] = __expf(sacc[ni][3] - mn1);
            rs0 += sacc[ni][0] + sacc[ni][1];
            rs1 += sacc[ni][2] + sacc[ni][3];
        }
        rs0 += __shfl_xor_sync(0xffffffffu, rs0, 1);
        rs0 += __shfl_xor_sync(0xffffffffu, rs0, 2);
        rs1 += __shfl_xor_sync(0xffffffffu, rs1, 1);
        rs1 += __shfl_xor_sync(0xffffffffu, rs1, 2);
        lrow0 = lrow0 * alpha0 + rs0;
        lrow1 = lrow1 * alpha1 + rs1;
        mrow0 = mn0;
        mrow1 = mn1;
#pragma unroll
        for (int ni = 0; ni < 8; ni++) {
            oacc[ni][0] *= alpha0;
            oacc[ni][1] *= alpha0;
            oacc[ni][2] *= alpha1;
            oacc[ni][3] *= alpha1;
        }

#pragma unroll
        for (int ni = 0; ni < 8; ni++) {
            int c = ni * 8 + 2 * fc;
            *(__half2*)&Ps[(w16 + fr) * ATSTR + c]     = __floats2half2_rn(sacc[ni][0], sacc[ni][1]);
            *(__half2*)&Ps[(w16 + fr + 8) * ATSTR + c] = __floats2half2_rn(sacc[ni][2], sacc[ni][3]);
        }
        __syncwarp();

#pragma unroll
        for (int ks = 0; ks < 4; ks++) {
            uint32_t af[4];
            ldsm4(af, pbase + ks * 16 * 2);
#pragma unroll
            for (int ni = 0; ni < 8; ni++) {
                uint32_t bf[2];
                ldsm2t(bf, vbase + (ks * 16 * ATSTR + ni * 8) * 2);
                mma_f16(oacc[ni], af, bf);
            }
        }
        __syncthreads();
    }

    float inv0 = 1.0f / lrow0;
    float inv1 = 1.0f / lrow1;
#pragma unroll
    for (int ni = 0; ni < 8; ni++) {
        int c = h * D_ + ni * 8 + 2 * fc;
        *(__half2*)(ctx + (size_t)(b * L_ + gi0) * HD_ + c) =
            __floats2half2_rn(oacc[ni][0] * inv0, oacc[ni][1] * inv0);
        *(__half2*)(ctx + (size_t)(b * L_ + gi1) * HD_ + c) =
            __floats2half2_rn(oacc[ni][2] * inv1, oacc[ni][3] * inv1);
    }
}

// ---------------- launch ----------------
extern "C" void kernel_launch(void* const* d_in, const int* in_sizes, int n_in,
                              void* d_out, int out_size) {
    (void)in_sizes; (void)n_in; (void)out_size;
    const float* X    = (const float*)d_in[0];
    const float* Wqkv = (const float*)d_in[2];
    const float* bqkv = (const float*)d_in[3];
    const float* Wo   = (const float*)d_in[4];
    const float* bo   = (const float*)d_in[5];
    const float* Ww   = (const float*)d_in[12];
    const float* Wv   = (const float*)d_in[13];
    const float* Wout = (const float*)d_in[14];
    float* out = (float*)d_out;

    float *x_p;
    __half *h16, *qkv16, *ctx16, *gate16, *val16, *gg16;
    __half *wqkv16, *wo16, *ww16, *wv16, *wout16;
    cudaGetSymbolAddress((void**)&x_p,    g_x);
    cudaGetSymbolAddress((void**)&h16,    g_h16);
    cudaGetSymbolAddress((void**)&qkv16,  g_qkv16);
    cudaGetSymbolAddress((void**)&ctx16,  g_ctx16);
    cudaGetSymbolAddress((void**)&gate16, g_gate16);
    cudaGetSymbolAddress((void**)&val16,  g_val16);
    cudaGetSymbolAddress((void**)&gg16,   g_gg16);
    cudaGetSymbolAddress((void**)&wqkv16, g_wqkv16);
    cudaGetSymbolAddress((void**)&wo16,   g_wo16);
    cudaGetSymbolAddress((void**)&ww16,   g_ww16);
    cudaGetSymbolAddress((void**)&wv16,   g_wv16);
    cudaGetSymbolAddress((void**)&wout16, g_wout16);

    cudaFuncSetAttribute(attn_kernel, cudaFuncAttributeMaxDynamicSharedMemorySize, ATT_SMEM);
    cudaFuncSetAttribute(hgemm_kernel, cudaFuncAttributeMaxDynamicSharedMemorySize, TG_SMEM);

    // 0. all fp16 weight conversions in one launch
    f2h_all_kernel<<<16384, 256>>>(Wqkv, wqkv16, Wo, wo16, Ww, ww16, Wv, wv16, Wout, wout16);

    // 1. h16 = rmsnorm(X)
    rmsnorm_kernel<<<M_, 256>>>(X, h16);
    // 2. qkv16 = h16 @ wqkv16 + bqkv
    hgemm_kernel<<<dim3(3 * HD_ / BN, M_ / BM), 256, TG_SMEM>>>(
        M_, 3 * HD_, E_, h16, wqkv16, bqkv, nullptr, nullptr, qkv16,
        nullptr, nullptr, nullptr);
    // 3. attention
    attn_kernel<<<dim3(L_ / 64, H_, B_), 128, ATT_SMEM>>>(qkv16, ctx16);
    // 4. x = X + ctx16 @ wo16 + bo
    hgemm_kernel<<<dim3(E_ / BN, M_ / BM), 256, TG_SMEM>>>(
        M_, E_, HD_, ctx16, wo16, bo, X, x_p, nullptr,
        nullptr, nullptr, nullptr);
    // 5+6. x = x + rmsnorm(x); h16 = rmsnorm(x)
    addnorm_kernel<<<M_, 256>>>(x_p, h16);
    // 7. gate16 / val16 (dual-output, z selects)
    hgemm_kernel<<<dim3(DFF_ / BN, M_ / BM, 2), 256, TG_SMEM>>>(
        M_, DFF_, E_, h16, ww16, nullptr, nullptr, nullptr, gate16,
        wv16, nullptr, val16);
    // 8. gg16 = gelu(gate16) * val16
    geglu_kernel<<<(M_ * DFF_) / 1024, 256>>>(gate16, val16, gg16);
    // 9. out = x + gg16 @ wout16
    hgemm_kernel<<<dim3(E_ / BN, M_ / BM), 256, TG_SMEM>>>(
        M_, E_, DFF_, gg16, wout16, nullptr, x_p, out, nullptr,
        nullptr, nullptr, nullptr);
}

// round 13
// speedup vs baseline: 1.9674x; 1.0219x over previous
#include <cuda_runtime.h>
#include <cuda_fp16.h>
#include <math_constants.h>
#include <cstdint>

#define B_   2
#define L_   2048
#define E_   1024
#define H_   16
#define D_   64
#define DFF_ 4096
#define M_   (B_ * L_)   // 4096 tokens
#define HD_  (H_ * D_)   // 1024

// ---------------- scratch (device globals: allocation-guard safe) ----------------
__device__ float  g_x[M_ * E_];
__device__ __half g_h16[M_ * E_];
__device__ __half g_qkv16[(size_t)M_ * 3 * HD_];
__device__ __half g_ctx16[M_ * HD_];
__device__ __half g_gate16[(size_t)M_ * DFF_];
__device__ __half g_val16[(size_t)M_ * DFF_];
__device__ __half g_gg16[(size_t)M_ * DFF_];
__device__ __half g_wqkv16[(size_t)E_ * 3 * HD_];
__device__ __half g_wo16[(size_t)HD_ * E_];
__device__ __half g_ww16[(size_t)E_ * DFF_];
__device__ __half g_wv16[(size_t)E_ * DFF_];
__device__ __half g_wout16[(size_t)DFF_ * E_];

__device__ __forceinline__ uint32_t h2u(__half2 h) {
    return *reinterpret_cast<uint32_t*>(&h);
}

// ---------------- fused fp32->fp16 conversion for ALL 5 weight tensors ----------------
__global__ __launch_bounds__(256) void f2h_all_kernel(
    const float* __restrict__ s0, __half* __restrict__ d0,
    const float* __restrict__ s1, __half* __restrict__ d1,
    const float* __restrict__ s2, __half* __restrict__ d2,
    const float* __restrict__ s3, __half* __restrict__ d3,
    const float* __restrict__ s4, __half* __restrict__ d4) {
    unsigned i = blockIdx.x * 256 + threadIdx.x;
    const float* s; __half* d; unsigned off;
    if (i < 786432u)       { s = s0; d = d0; off = i; }
    else if (i < 1048576u) { s = s1; d = d1; off = i - 786432u; }
    else if (i < 2097152u) { s = s2; d = d2; off = i - 1048576u; }
    else if (i < 3145728u) { s = s3; d = d3; off = i - 2097152u; }
    else                   { s = s4; d = d4; off = i - 3145728u; }
    float4 v = ((const float4*)s)[off];
    ((uint2*)d)[off] = make_uint2(h2u(__floats2half2_rn(v.x, v.y)),
                                  h2u(__floats2half2_rn(v.z, v.w)));
}

// ---------------- rmsnorm (fp16 out) ----------------
__global__ __launch_bounds__(256) void rmsnorm_kernel(const float* __restrict__ x,
                                                      __half* __restrict__ y) {
    int row = blockIdx.x;
    float4 a = ((const float4*)(x + (size_t)row * E_))[threadIdx.x];
    float ss = a.x * a.x + a.y * a.y + a.z * a.z + a.w * a.w;
    __shared__ float red[8];
    __shared__ float sinv;
#pragma unroll
    for (int o = 16; o > 0; o >>= 1) ss += __shfl_xor_sync(0xffffffffu, ss, o);
    if ((threadIdx.x & 31) == 0) red[threadIdx.x >> 5] = ss;
    __syncthreads();
    if (threadIdx.x == 0) {
        float t = 0.f;
#pragma unroll
        for (int i = 0; i < 8; i++) t += red[i];
        sinv = rsqrtf(t * (1.0f / E_));
    }
    __syncthreads();
    float c = sinv;
    ((uint2*)(y + (size_t)row * E_))[threadIdx.x] =
        make_uint2(h2u(__floats2half2_rn(a.x * c, a.y * c)),
                   h2u(__floats2half2_rn(a.z * c, a.w * c)));
}

// ---------------- fused: x = x + rmsnorm(x); h16 = rmsnorm(x) ----------------
__global__ __launch_bounds__(256) void addnorm_kernel(float* __restrict__ x,
                                                      __half* __restrict__ h) {
    int row = blockIdx.x;
    float4 a = ((const float4*)(x + (size_t)row * E_))[threadIdx.x];
    __shared__ float red[8];
    __shared__ float sval;
    float ss = a.x * a.x + a.y * a.y + a.z * a.z + a.w * a.w;
#pragma unroll
    for (int o = 16; o > 0; o >>= 1) ss += __shfl_xor_sync(0xffffffffu, ss, o);
    if ((threadIdx.x & 31) == 0) red[threadIdx.x >> 5] = ss;
    __syncthreads();
    if (threadIdx.x == 0) {
        float t = 0.f;
#pragma unroll
        for (int i = 0; i < 8; i++) t += red[i];
        sval = 1.0f + rsqrtf(t * (1.0f / E_));
    }
    __syncthreads();
    float c = sval;
    a.x *= c; a.y *= c; a.z *= c; a.w *= c;
    float ss2 = a.x * a.x + a.y * a.y + a.z * a.z + a.w * a.w;
#pragma unroll
    for (int o = 16; o > 0; o >>= 1) ss2 += __shfl_xor_sync(0xffffffffu, ss2, o);
    if ((threadIdx.x & 31) == 0) red[threadIdx.x >> 5] = ss2;
    __syncthreads();
    if (threadIdx.x == 0) {
        float t = 0.f;
#pragma unroll
        for (int i = 0; i < 8; i++) t += red[i];
        sval = rsqrtf(t * (1.0f / E_));
    }
    __syncthreads();
    float inv2 = sval;
    ((float4*)(x + (size_t)row * E_))[threadIdx.x] = a;
    ((uint2*)(h + (size_t)row * E_))[threadIdx.x] =
        make_uint2(h2u(__floats2half2_rn(a.x * inv2, a.y * inv2)),
                   h2u(__floats2half2_rn(a.z * inv2, a.w * inv2)));
}

// ---------------- geglu (fp16 in/out) ----------------
__global__ __launch_bounds__(256) void geglu_kernel(const __half* __restrict__ g,
                                                    const __half* __restrict__ v,
                                                    __half* __restrict__ o) {
    int i = (blockIdx.x * 256 + threadIdx.x) * 4;
    uint2 gu = *(const uint2*)(g + i);
    uint2 vu = *(const uint2*)(v + i);
    float2 g0 = __half22float2(*reinterpret_cast<__half2*>(&gu.x));
    float2 g1 = __half22float2(*reinterpret_cast<__half2*>(&gu.y));
    float2 v0 = __half22float2(*reinterpret_cast<__half2*>(&vu.x));
    float2 v1 = __half22float2(*reinterpret_cast<__half2*>(&vu.y));
    float r0 = 0.5f * g0.x * (1.0f + erff(g0.x * 0.70710678118654752f)) * v0.x;
    float r1 = 0.5f * g0.y * (1.0f + erff(g0.y * 0.70710678118654752f)) * v0.y;
    float r2 = 0.5f * g1.x * (1.0f + erff(g1.x * 0.70710678118654752f)) * v1.x;
    float r3 = 0.5f * g1.y * (1.0f + erff(g1.y * 0.70710678118654752f)) * v1.y;
    *(uint2*)(o + i) = make_uint2(h2u(__floats2half2_rn(r0, r1)),
                                  h2u(__floats2half2_rn(r2, r3)));
}

// ================= mma helpers =================
__device__ __forceinline__ void mma_f16(float* d, const uint32_t* a, const uint32_t* b) {
    asm volatile(
        "mma.sync.aligned.m16n8k16.row.col.f32.f16.f16.f32 "
        "{%0,%1,%2,%3}, {%4,%5,%6,%7}, {%8,%9}, {%0,%1,%2,%3};\n"
        : "+f"(d[0]), "+f"(d[1]), "+f"(d[2]), "+f"(d[3])
        : "r"(a[0]), "r"(a[1]), "r"(a[2]), "r"(a[3]), "r"(b[0]), "r"(b[1]));
}

__device__ __forceinline__ void ldsm4(uint32_t* r, uint32_t saddr) {
    asm volatile("ldmatrix.sync.aligned.m8n8.x4.shared.b16 {%0,%1,%2,%3}, [%4];"
                 : "=r"(r[0]), "=r"(r[1]), "=r"(r[2]), "=r"(r[3]) : "r"(saddr));
}
__device__ __forceinline__ void ldsm4t(uint32_t* r, uint32_t saddr) {
    asm volatile("ldmatrix.sync.aligned.m8n8.x4.trans.shared.b16 {%0,%1,%2,%3}, [%4];"
                 : "=r"(r[0]), "=r"(r[1]), "=r"(r[2]), "=r"(r[3]) : "r"(saddr));
}
__device__ __forceinline__ void ldsm2t(uint32_t* r, uint32_t saddr) {
    asm volatile("ldmatrix.sync.aligned.m8n8.x2.trans.shared.b16 {%0,%1}, [%2];"
                 : "=r"(r[0]), "=r"(r[1]) : "r"(saddr));
}
__device__ __forceinline__ void ldsm2(uint32_t* r, uint32_t saddr) {
    asm volatile("ldmatrix.sync.aligned.m8n8.x2.shared.b16 {%0,%1}, [%2];"
                 : "=r"(r[0]), "=r"(r[1]) : "r"(saddr));
}

// ================= fp16 tensor-core GEMM: 64x128 CTA tile, 32x32 warp tile =================
#define BM 64
#define BN 128
#define BK 64
#define ASTR 72
#define BSTR 136
#define ATILE_H (BM * ASTR)
#define BTILE_H (BK * BSTR)
#define STAGE_H (ATILE_H + BTILE_H)
#define TG_SMEM (2 * STAGE_H * 2)   // 53248 B

__global__ __launch_bounds__(256, 3) void hgemm_kernel(
    int M, int N, int K,
    const __half* __restrict__ A, const __half* __restrict__ B,
    const float* __restrict__ bias, const float* __restrict__ res,
    float* __restrict__ C, __half* __restrict__ C16,
    const __half* __restrict__ B2, float* __restrict__ C2, __half* __restrict__ C216) {
    extern __shared__ __half sm[];

    if (blockIdx.z) { B = B2; C = C2; C16 = C216; }

    const int tid  = threadIdx.x;
    const int bm   = blockIdx.y * BM;
    const int bn   = blockIdx.x * BN;
    const int warp = tid >> 5, lane = tid & 31;
    const int wm   = (warp >> 2) * 32;
    const int wn   = (warp & 3) * 32;
    const int fr   = lane >> 2;
    const int fc   = lane & 3;
    const int arow_l = ((lane >> 3) & 1) * 8 + (lane & 7);
    const int acol_l = ((lane >> 4) & 1) * 8;
    // ldsm4t B lane map: rows k0..15 x col groups {0,+8}
    const int brow4_l = ((lane >> 3) & 1) * 8 + (lane & 7);
    const int bcol4_l = ((lane >> 4) & 1) * 8;

    float acc[2][4][4];
#pragma unroll
    for (int i = 0; i < 2; i++)
#pragma unroll
        for (int j = 0; j < 4; j++)
#pragma unroll
            for (int k = 0; k < 4; k++) acc[i][j][k] = 0.f;

    auto fill = [&](int s, int kt) {
        __half* Ad = sm + s * STAGE_H;
        __half* Bd = Ad + ATILE_H;
#pragma unroll
        for (int p = 0; p < 2; p++) {
            int idx = p * 256 + tid;
            int row = idx >> 3, c8 = idx & 7;
            uint32_t dst = (uint32_t)__cvta_generic_to_shared(Ad + row * ASTR + c8 * 8);
            const __half* src = A + (size_t)(bm + row) * K + kt + c8 * 8;
            asm volatile("cp.async.cg.shared.global [%0], [%1], 16;\n" :: "r"(dst), "l"(src));
        }
#pragma unroll
        for (int p = 0; p < 4; p++) {
            int idx = p * 256 + tid;
            int row = idx >> 4, c16 = idx & 15;
            uint32_t dst = (uint32_t)__cvta_generic_to_shared(Bd + row * BSTR + c16 * 8);
            const __half* src = B + (size_t)(kt + row) * N + bn + c16 * 8;
            asm volatile("cp.async.cg.shared.global [%0], [%1], 16;\n" :: "r"(dst), "l"(src));
        }
        asm volatile("cp.async.commit_group;\n");
    };

    auto compute_tile = [&](int s) {
        const __half* Ab = sm + s * STAGE_H;
        const __half* Bb = Ab + ATILE_H;
        uint32_t abase = (uint32_t)__cvta_generic_to_shared(Ab + (wm + arow_l) * ASTR + acol_l);
        uint32_t bbase = (uint32_t)__cvta_generic_to_shared(Bb + brow4_l * BSTR + wn + bcol4_l);
#pragma unroll
        for (int ks = 0; ks < 4; ks++) {
            uint32_t af[2][4], bf[4][2];
#pragma unroll
            for (int mi = 0; mi < 2; mi++)
                ldsm4(af[mi], abase + (mi * 16 * ASTR + ks * 16) * 2);
#pragma unroll
            for (int n2 = 0; n2 < 2; n2++) {
                uint32_t r4[4];
                ldsm4t(r4, bbase + (ks * 16 * BSTR + n2 * 16) * 2);
                bf[2 * n2][0] = r4[0]; bf[2 * n2][1] = r4[1];
                bf[2 * n2 + 1][0] = r4[2]; bf[2 * n2 + 1][1] = r4[3];
            }
#pragma unroll
            for (int mi = 0; mi < 2; mi++)
#pragma unroll
                for (int ni = 0; ni < 4; ni++) mma_f16(acc[mi][ni], af[mi], bf[ni]);
        }
    };

    const int kiters = K / BK;
    fill(0, 0);
    asm volatile("cp.async.wait_group 0;\n");
    __syncthreads();

#pragma unroll 1
    for (int it = 0; it < kiters; ++it) {
        int cur = it & 1;
        if (it + 1 < kiters) fill(cur ^ 1, (it + 1) * BK);
        compute_tile(cur);
        asm volatile("cp.async.wait_group 0;\n");
        __syncthreads();
    }

#pragma unroll
    for (int mi = 0; mi < 2; mi++) {
#pragma unroll
        for (int ni = 0; ni < 4; ni++) {
            int gr = bm + wm + mi * 16 + fr;
            int gc = bn + wn + ni * 8 + fc * 2;
            float2 o0 = make_float2(acc[mi][ni][0], acc[mi][ni][1]);
            float2 o1 = make_float2(acc[mi][ni][2], acc[mi][ni][3]);
            if (bias) {
                float2 bv = *(const float2*)(bias + gc);
                o0.x += bv.x; o0.y += bv.y;
                o1.x += bv.x; o1.y += bv.y;
            }
            if (res) {
                float2 r0 = *(const float2*)(res + (size_t)gr * N + gc);
                float2 r1 = *(const float2*)(res + (size_t)(gr + 8) * N + gc);
                o0.x += r0.x; o0.y += r0.y;
                o1.x += r1.x; o1.y += r1.y;
            }
            if (C16) {
                *(__half2*)(C16 + (size_t)gr * N + gc) = __floats2half2_rn(o0.x, o0.y);
                *(__half2*)(C16 + (size_t)(gr + 8) * N + gc) = __floats2half2_rn(o1.x, o1.y);
            } else {
                *(float2*)(C + (size_t)gr * N + gc) = o0;
                *(float2*)(C + (size_t)(gr + 8) * N + gc) = o1;
            }
        }
    }
}

// ================= fp16 flash attention: 128-row Q tile, 8 warps =================
#define ATSTR 72
#define QT_ROWS 128
#define KT_ROWS 64
#define Q_TILE_H (QT_ROWS * ATSTR)      // 9216
#define KV_TILE_H (KT_ROWS * ATSTR)     // 4608
#define ATT_SMEM ((2 * Q_TILE_H + 4 * KV_TILE_H) * 2)   // 73728 B

__global__ __launch_bounds__(256) void attn_kernel(const __half* __restrict__ qkv,
                                                   __half* __restrict__ ctx) {
    extern __shared__ __half smh[];
    __half* Qs = smh;
    __half* Ps = Qs + Q_TILE_H;
    __half* KV = Ps + Q_TILE_H;     // [buf][K | V] each KV_TILE_H

    const int qt = blockIdx.x, h = blockIdx.y, b = blockIdx.z;
    const int m0 = qt * QT_ROWS;
    const int tid  = threadIdx.x;
    const int warp = tid >> 5, lane = tid & 31;
    const int fr = lane >> 2, fc = lane & 3;
    const int w16 = warp * 16;
    const int arow_l = ((lane >> 3) & 1) * 8 + (lane & 7);
    const int acol_l = ((lane >> 4) & 1) * 8;
    const int brow_l = arow_l;
    const int krow_l = lane & 7;
    const int ksel_l = ((lane >> 3) & 1) * 8;
    const float slope = exp2f(-(1.0f + 7.0f * (float)h / 15.0f));
    const float step8 = 8.0f * slope;
    const __half2 qscale = __floats2half2_rn(0.125f, 0.125f);

    auto fill_kv = [&](int kt, int bufsel) {
        __half* Kd = KV + bufsel * 2 * KV_TILE_H;
        __half* Vd = Kd + KV_TILE_H;
        const int n0 = kt * KT_ROWS;
#pragma unroll
        for (int p = 0; p < 2; p++) {
            int i = p * 256 + tid;
            int r = i >> 3, c = (i & 7) * 8;
            size_t base = ((size_t)(b * L_ + n0 + r) * H_ + h) * 3;
            uint32_t kd = (uint32_t)__cvta_generic_to_shared(Kd + r * ATSTR + c);
            uint32_t vd = (uint32_t)__cvta_generic_to_shared(Vd + r * ATSTR + c);
            const __half* ks = qkv + (base + 1) * D_ + c;
            const __half* vs = qkv + (base + 2) * D_ + c;
            asm volatile("cp.async.cg.shared.global [%0], [%1], 16;\n" :: "r"(kd), "l"(ks));
            asm volatile("cp.async.cg.shared.global [%0], [%1], 16;\n" :: "r"(vd), "l"(vs));
        }
        asm volatile("cp.async.commit_group;\n");
    };

    // ---- load Q tile (scaled 1/8) ----
    for (int i = tid; i < QT_ROWS * 16; i += 256) {
        int r = i >> 4, c = (i & 15) << 2;
        uint2 v = *(const uint2*)(qkv + ((((size_t)(b * L_ + m0 + r) * H_ + h) * 3 + 0) * D_ + c));
        __half2 q0 = __hmul2(*reinterpret_cast<__half2*>(&v.x), qscale);
        __half2 q1 = __hmul2(*reinterpret_cast<__half2*>(&v.y), qscale);
        *(uint2*)(Qs + r * ATSTR + c) = make_uint2(h2u(q0), h2u(q1));
    }
    fill_kv(0, 0);
    __syncthreads();

    const uint32_t qbase = (uint32_t)__cvta_generic_to_shared(Qs + (w16 + arow_l) * ATSTR + acol_l);
    const uint32_t pbase = (uint32_t)__cvta_generic_to_shared(Ps + (w16 + arow_l) * ATSTR + acol_l);

    uint32_t qf[4][4];
#pragma unroll
    for (int ks = 0; ks < 4; ks++) ldsm4(qf[ks], qbase + ks * 16 * 2);

    float oacc[8][4];
#pragma unroll
    for (int i = 0; i < 8; i++)
#pragma unroll
        for (int j = 0; j < 4; j++) oacc[i][j] = 0.f;
    float mrow0 = -CUDART_INF_F, mrow1 = -CUDART_INF_F;
    float lrow0 = 0.f, lrow1 = 0.f;

    const int gi0 = m0 + w16 + fr;
    const int gi1 = gi0 + 8;
    const int ktmax = 2 * qt + 1;

#pragma unroll 1
    for (int kt = 0; kt <= ktmax; kt++) {
        const int n0 = kt * KT_ROWS;
        const int bufsel = kt & 1;
        if (kt + 1 <= ktmax) {
            fill_kv(kt + 1, bufsel ^ 1);
            asm volatile("cp.async.wait_group 1;\n");
        } else {
            asm volatile("cp.async.wait_group 0;\n");
        }
        __syncthreads();

        const __half* Kd = KV + bufsel * 2 * KV_TILE_H;
        const __half* Vd = Kd + KV_TILE_H;
        const uint32_t kbase = (uint32_t)__cvta_generic_to_shared(Kd + krow_l * ATSTR + ksel_l);
        const uint32_t vbase = (uint32_t)__cvta_generic_to_shared(Vd + brow_l * ATSTR);

        float sacc[8][4];
#pragma unroll
        for (int i = 0; i < 8; i++)
#pragma unroll
            for (int j = 0; j < 4; j++) sacc[i][j] = 0.f;
#pragma unroll
        for (int ks = 0; ks < 4; ks++) {
            uint32_t bf[8][2];
#pragma unroll
            for (int ni = 0; ni < 8; ni++)
                ldsm2(bf[ni], kbase + (ni * 8 * ATSTR + ks * 16) * 2);
#pragma unroll
            for (int ni = 0; ni < 8; ni++) mma_f16(sacc[ni], qf[ks], bf[ni]);
        }

        // ---- alibi (incremental) + causal (only near-diagonal tiles) ----
        {
            float a0 = slope * (float)(n0 + 2 * fc - gi0);
            float a2 = slope * (float)(n0 + 2 * fc - gi1);
            if (kt < 2 * qt) {
#pragma unroll
                for (int ni = 0; ni < 8; ni++) {
                    sacc[ni][0] += a0;
                    sacc[ni][1] += a0 + slope;
                    sacc[ni][2] += a2;
                    sacc[ni][3] += a2 + slope;
                    a0 += step8;
                    a2 += step8;
                }
            } else {
#pragma unroll
                for (int ni = 0; ni < 8; ni++) {
                    int gj = n0 + ni * 8 + 2 * fc;
                    sacc[ni][0] = (gj     > gi0) ? -CUDART_INF_F : sacc[ni][0] + a0;
                    sacc[ni][1] = (gj + 1 > gi0) ? -CUDART_INF_F : sacc[ni][1] + a0 + slope;
                    sacc[ni][2] = (gj     > gi1) ? -CUDART_INF_F : sacc[ni][2] + a2;
                    sacc[ni][3] = (gj + 1 > gi1) ? -CUDART_INF_F : sacc[ni][3] + a2 + slope;
                    a0 += step8;
                    a2 += step8;
                }
            }
        }

        float mx0 = -CUDART_INF_F, mx1 = -CUDART_INF_F;
#pragma unroll
        for (int ni = 0; ni < 8; ni++) {
            mx0 = fmaxf(mx0, fmaxf(sacc[ni][0], sacc[ni][1]));
            mx1 = fmaxf(mx1, fmaxf(sacc[ni][2], sacc[ni][3]));
        }
        mx0 = fmaxf(mx0, __shfl_xor_sync(0xffffffffu, mx0, 1));
        mx0 = fmaxf(mx0, __shfl_xor_sync(0xffffffffu, mx0, 2));
        mx1 = fmaxf(mx1, __shfl_xor_sync(0xffffffffu, mx1, 1));
        mx1 = fmaxf(mx1, __shfl_xor_sync(0xffffffffu, mx1, 2));
        float mn0 = fmaxf(mrow0, mx0);
        float mn1 = fmaxf(mrow1, mx1);
        float alpha0 = __expf(mrow0 - mn0);
        float alpha1 = __expf(mrow1 - mn1);
        float rs0 = 0.f, rs1 = 0.f;
#pragma unroll
        for (int ni = 0; ni < 8; ni++) {
            sacc[ni][0] = __expf(sacc[ni][0] - mn0);
            sacc[ni][1] = __expf(sacc[ni][1] - mn0);
            sacc[ni][2] = __expf(sacc[ni][2] - mn1);
            sacc[ni][3] = __expf(sacc[ni][3] - mn1);
            rs0 += sacc[ni][0] + sacc[ni][1];
            rs1 += sacc[ni][2] + sacc[ni][3];
        }
        rs0 += __shfl_xor_sync(0xffffffffu, rs0, 1);
        rs0 += __shfl_xor_sync(0xffffffffu, rs0, 2);
        rs1 += __shfl_xor_sync(0xffffffffu, rs1, 1);
        rs1 += __shfl_xor_sync(0xffffffffu, rs1, 2);
        lrow0 = lrow0 * alpha0 + rs0;
        lrow1 = lrow1 * alpha1 + rs1;
        mrow0 = mn0;
        mrow1 = mn1;
#pragma unroll
        for (int ni = 0; ni < 8; ni++) {
            oacc[ni][0] *= alpha0;
            oacc[ni][1] *= alpha0;
            oacc[ni][2] *= alpha1;
            oacc[ni][3] *= alpha1;
        }

#pragma unroll
        for (int ni = 0; ni < 8; ni++) {
            int c = ni * 8 + 2 * fc;
            *(__half2*)&Ps[(w16 + fr) * ATSTR + c]     = __floats2half2_rn(sacc[ni][0], sacc[ni][1]);
            *(__half2*)&Ps[(w16 + fr + 8) * ATSTR + c] = __floats2half2_rn(sacc[ni][2], sacc[ni][3]);
        }
        __syncwarp();

#pragma unroll
        for (int ks = 0; ks < 4; ks++) {
            uint32_t af[4];
            ldsm4(af, pbase + ks * 16 * 2);
#pragma unroll
            for (int ni = 0; ni < 8; ni++) {
                uint32_t bf[2];
                ldsm2t(bf, vbase + (ks * 16 * ATSTR + ni * 8) * 2);
                mma_f16(oacc[ni], af, bf);
            }
        }
        __syncthreads();
    }

    float inv0 = 1.0f / lrow0;
    float inv1 = 1.0f / lrow1;
#pragma unroll
    for (int ni = 0; ni < 8; ni++) {
        int c = h * D_ + ni * 8 + 2 * fc;
        *(__half2*)(ctx + (size_t)(b * L_ + gi0) * HD_ + c) =
            __floats2half2_rn(oacc[ni][0] * inv0, oacc[ni][1] * inv0);
        *(__half2*)(ctx + (size_t)(b * L_ + gi1) * HD_ + c) =
            __floats2half2_rn(oacc[ni][2] * inv1, oacc[ni][3] * inv1);
    }
}

// ---------------- launch ----------------
extern "C" void kernel_launch(void* const* d_in, const int* in_sizes, int n_in,
                              void* d_out, int out_size) {
    (void)in_sizes; (void)n_in; (void)out_size;
    const float* X    = (const float*)d_in[0];
    const float* Wqkv = (const float*)d_in[2];
    const float* bqkv = (const float*)d_in[3];
    const float* Wo   = (const float*)d_in[4];
    const float* bo   = (const float*)d_in[5];
    const float* Ww   = (const float*)d_in[12];
    const float* Wv   = (const float*)d_in[13];
    const float* Wout = (const float*)d_in[14];
    float* out = (float*)d_out;

    float *x_p;
    __half *h16, *qkv16, *ctx16, *gate16, *val16, *gg16;
    __half *wqkv16, *wo16, *ww16, *wv16, *wout16;
    cudaGetSymbolAddress((void**)&x_p,    g_x);
    cudaGetSymbolAddress((void**)&h16,    g_h16);
    cudaGetSymbolAddress((void**)&qkv16,  g_qkv16);
    cudaGetSymbolAddress((void**)&ctx16,  g_ctx16);
    cudaGetSymbolAddress((void**)&gate16, g_gate16);
    cudaGetSymbolAddress((void**)&val16,  g_val16);
    cudaGetSymbolAddress((void**)&gg16,   g_gg16);
    cudaGetSymbolAddress((void**)&wqkv16, g_wqkv16);
    cudaGetSymbolAddress((void**)&wo16,   g_wo16);
    cudaGetSymbolAddress((void**)&ww16,   g_ww16);
    cudaGetSymbolAddress((void**)&wv16,   g_wv16);
    cudaGetSymbolAddress((void**)&wout16, g_wout16);

    cudaFuncSetAttribute(attn_kernel, cudaFuncAttributeMaxDynamicSharedMemorySize, ATT_SMEM);
    cudaFuncSetAttribute(hgemm_kernel, cudaFuncAttributeMaxDynamicSharedMemorySize, TG_SMEM);

    // 0. all fp16 weight conversions in one launch
    f2h_all_kernel<<<16384, 256>>>(Wqkv, wqkv16, Wo, wo16, Ww, ww16, Wv, wv16, Wout, wout16);

    // 1. h16 = rmsnorm(X)
    rmsnorm_kernel<<<M_, 256>>>(X, h16);
    // 2. qkv16 = h16 @ wqkv16 + bqkv
    hgemm_kernel<<<dim3(3 * HD_ / BN, M_ / BM), 256, TG_SMEM>>>(
        M_, 3 * HD_, E_, h16, wqkv16, bqkv, nullptr, nullptr, qkv16,
        nullptr, nullptr, nullptr);
    // 3. attention (128-row Q tiles)
    attn_kernel<<<dim3(L_ / QT_ROWS, H_, B_), 256, ATT_SMEM>>>(qkv16, ctx16);
    // 4. x = X + ctx16 @ wo16 + bo
    hgemm_kernel<<<dim3(E_ / BN, M_ / BM), 256, TG_SMEM>>>(
        M_, E_, HD_, ctx16, wo16, bo, X, x_p, nullptr,
        nullptr, nullptr, nullptr);
    // 5+6. x = x + rmsnorm(x); h16 = rmsnorm(x)
    addnorm_kernel<<<M_, 256>>>(x_p, h16);
    // 7. gate16 / val16 (dual-output, z selects)
    hgemm_kernel<<<dim3(DFF_ / BN, M_ / BM, 2), 256, TG_SMEM>>>(
        M_, DFF_, E_, h16, ww16, nullptr, nullptr, nullptr, gate16,
        wv16, nullptr, val16);
    // 8. gg16 = gelu(gate16) * val16
    geglu_kernel<<<(M_ * DFF_) / 1024, 256>>>(gate16, val16, gg16);
    // 9. out = x + gg16 @ wout16
    hgemm_kernel<<<dim3(E_ / BN, M_ / BM), 256, TG_SMEM>>>(
        M_, E_, DFF_, gg16, wout16, nullptr, x_p, out, nullptr,
        nullptr, nullptr, nullptr);
}

// round 14
// speedup vs baseline: 1.9986x; 1.0159x over previous
#include <cuda_runtime.h>
#include <cuda_fp16.h>
#include <math_constants.h>
#include <cstdint>

#define B_   2
#define L_   2048
#define E_   1024
#define H_   16
#define D_   64
#define DFF_ 4096
#define M_   (B_ * L_)   // 4096 tokens
#define HD_  (H_ * D_)   // 1024

// ---------------- scratch (device globals: allocation-guard safe) ----------------
__device__ float  g_x[M_ * E_];
__device__ __half g_h16[M_ * E_];
__device__ __half g_qkv16[(size_t)M_ * 3 * HD_];
__device__ __half g_ctx16[M_ * HD_];
__device__ __half g_gate16[(size_t)M_ * DFF_];
__device__ __half g_val16[(size_t)M_ * DFF_];
__device__ __half g_gg16[(size_t)M_ * DFF_];
__device__ __half g_wqkv16[(size_t)E_ * 3 * HD_];
__device__ __half g_wo16[(size_t)HD_ * E_];
__device__ __half g_ww16[(size_t)E_ * DFF_];
__device__ __half g_wv16[(size_t)E_ * DFF_];
__device__ __half g_wout16[(size_t)DFF_ * E_];

__device__ __forceinline__ uint32_t h2u(__half2 h) {
    return *reinterpret_cast<uint32_t*>(&h);
}

// ---------------- fused fp32->fp16 conversion for ALL 5 weight tensors ----------------
__global__ __launch_bounds__(256) void f2h_all_kernel(
    const float* __restrict__ s0, __half* __restrict__ d0,
    const float* __restrict__ s1, __half* __restrict__ d1,
    const float* __restrict__ s2, __half* __restrict__ d2,
    const float* __restrict__ s3, __half* __restrict__ d3,
    const float* __restrict__ s4, __half* __restrict__ d4) {
    unsigned i = blockIdx.x * 256 + threadIdx.x;
    const float* s; __half* d; unsigned off;
    if (i < 786432u)       { s = s0; d = d0; off = i; }
    else if (i < 1048576u) { s = s1; d = d1; off = i - 786432u; }
    else if (i < 2097152u) { s = s2; d = d2; off = i - 1048576u; }
    else if (i < 3145728u) { s = s3; d = d3; off = i - 2097152u; }
    else                   { s = s4; d = d4; off = i - 3145728u; }
    float4 v = ((const float4*)s)[off];
    ((uint2*)d)[off] = make_uint2(h2u(__floats2half2_rn(v.x, v.y)),
                                  h2u(__floats2half2_rn(v.z, v.w)));
}

// ---------------- rmsnorm (fp16 out) ----------------
__global__ __launch_bounds__(256) void rmsnorm_kernel(const float* __restrict__ x,
                                                      __half* __restrict__ y) {
    int row = blockIdx.x;
    float4 a = ((const float4*)(x + (size_t)row * E_))[threadIdx.x];
    float ss = a.x * a.x + a.y * a.y + a.z * a.z + a.w * a.w;
    __shared__ float red[8];
    __shared__ float sinv;
#pragma unroll
    for (int o = 16; o > 0; o >>= 1) ss += __shfl_xor_sync(0xffffffffu, ss, o);
    if ((threadIdx.x & 31) == 0) red[threadIdx.x >> 5] = ss;
    __syncthreads();
    if (threadIdx.x == 0) {
        float t = 0.f;
#pragma unroll
        for (int i = 0; i < 8; i++) t += red[i];
        sinv = rsqrtf(t * (1.0f / E_));
    }
    __syncthreads();
    float c = sinv;
    ((uint2*)(y + (size_t)row * E_))[threadIdx.x] =
        make_uint2(h2u(__floats2half2_rn(a.x * c, a.y * c)),
                   h2u(__floats2half2_rn(a.z * c, a.w * c)));
}

// ---------------- fused: x = x + rmsnorm(x); h16 = rmsnorm(x) ----------------
__global__ __launch_bounds__(256) void addnorm_kernel(float* __restrict__ x,
                                                      __half* __restrict__ h) {
    int row = blockIdx.x;
    float4 a = ((const float4*)(x + (size_t)row * E_))[threadIdx.x];
    __shared__ float red[8];
    __shared__ float sval;
    float ss = a.x * a.x + a.y * a.y + a.z * a.z + a.w * a.w;
#pragma unroll
    for (int o = 16; o > 0; o >>= 1) ss += __shfl_xor_sync(0xffffffffu, ss, o);
    if ((threadIdx.x & 31) == 0) red[threadIdx.x >> 5] = ss;
    __syncthreads();
    if (threadIdx.x == 0) {
        float t = 0.f;
#pragma unroll
        for (int i = 0; i < 8; i++) t += red[i];
        sval = 1.0f + rsqrtf(t * (1.0f / E_));
    }
    __syncthreads();
    float c = sval;
    a.x *= c; a.y *= c; a.z *= c; a.w *= c;
    float ss2 = a.x * a.x + a.y * a.y + a.z * a.z + a.w * a.w;
#pragma unroll
    for (int o = 16; o > 0; o >>= 1) ss2 += __shfl_xor_sync(0xffffffffu, ss2, o);
    if ((threadIdx.x & 31) == 0) red[threadIdx.x >> 5] = ss2;
    __syncthreads();
    if (threadIdx.x == 0) {
        float t = 0.f;
#pragma unroll
        for (int i = 0; i < 8; i++) t += red[i];
        sval = rsqrtf(t * (1.0f / E_));
    }
    __syncthreads();
    float inv2 = sval;
    ((float4*)(x + (size_t)row * E_))[threadIdx.x] = a;
    ((uint2*)(h + (size_t)row * E_))[threadIdx.x] =
        make_uint2(h2u(__floats2half2_rn(a.x * inv2, a.y * inv2)),
                   h2u(__floats2half2_rn(a.z * inv2, a.w * inv2)));
}

// ---------------- geglu (fp16 in/out) ----------------
__global__ __launch_bounds__(256) void geglu_kernel(const __half* __restrict__ g,
                                                    const __half* __restrict__ v,
                                                    __half* __restrict__ o) {
    int i = (blockIdx.x * 256 + threadIdx.x) * 4;
    uint2 gu = *(const uint2*)(g + i);
    uint2 vu = *(const uint2*)(v + i);
    float2 g0 = __half22float2(*reinterpret_cast<__half2*>(&gu.x));
    float2 g1 = __half22float2(*reinterpret_cast<__half2*>(&gu.y));
    float2 v0 = __half22float2(*reinterpret_cast<__half2*>(&vu.x));
    float2 v1 = __half22float2(*reinterpret_cast<__half2*>(&vu.y));
    float r0 = 0.5f * g0.x * (1.0f + erff(g0.x * 0.70710678118654752f)) * v0.x;
    float r1 = 0.5f * g0.y * (1.0f + erff(g0.y * 0.70710678118654752f)) * v0.y;
    float r2 = 0.5f * g1.x * (1.0f + erff(g1.x * 0.70710678118654752f)) * v1.x;
    float r3 = 0.5f * g1.y * (1.0f + erff(g1.y * 0.70710678118654752f)) * v1.y;
    *(uint2*)(o + i) = make_uint2(h2u(__floats2half2_rn(r0, r1)),
                                  h2u(__floats2half2_rn(r2, r3)));
}

// ================= mma helpers =================
__device__ __forceinline__ void mma_f16(float* d, const uint32_t* a, const uint32_t* b) {
    asm volatile(
        "mma.sync.aligned.m16n8k16.row.col.f32.f16.f16.f32 "
        "{%0,%1,%2,%3}, {%4,%5,%6,%7}, {%8,%9}, {%0,%1,%2,%3};\n"
        : "+f"(d[0]), "+f"(d[1]), "+f"(d[2]), "+f"(d[3])
        : "r"(a[0]), "r"(a[1]), "r"(a[2]), "r"(a[3]), "r"(b[0]), "r"(b[1]));
}

__device__ __forceinline__ void ldsm4(uint32_t* r, uint32_t saddr) {
    asm volatile("ldmatrix.sync.aligned.m8n8.x4.shared.b16 {%0,%1,%2,%3}, [%4];"
                 : "=r"(r[0]), "=r"(r[1]), "=r"(r[2]), "=r"(r[3]) : "r"(saddr));
}
__device__ __forceinline__ void ldsm4t(uint32_t* r, uint32_t saddr) {
    asm volatile("ldmatrix.sync.aligned.m8n8.x4.trans.shared.b16 {%0,%1,%2,%3}, [%4];"
                 : "=r"(r[0]), "=r"(r[1]), "=r"(r[2]), "=r"(r[3]) : "r"(saddr));
}
__device__ __forceinline__ void ldsm2t(uint32_t* r, uint32_t saddr) {
    asm volatile("ldmatrix.sync.aligned.m8n8.x2.trans.shared.b16 {%0,%1}, [%2];"
                 : "=r"(r[0]), "=r"(r[1]) : "r"(saddr));
}
__device__ __forceinline__ void ldsm2(uint32_t* r, uint32_t saddr) {
    asm volatile("ldmatrix.sync.aligned.m8n8.x2.shared.b16 {%0,%1}, [%2];"
                 : "=r"(r[0]), "=r"(r[1]) : "r"(saddr));
}

// ================= fp16 tensor-core GEMM: 64x128 CTA tile, 32x32 warp tile, ldsm4t B =================
#define BM 64
#define BN 128
#define BK 64
#define ASTR 72
#define BSTR 136
#define ATILE_H (BM * ASTR)
#define BTILE_H (BK * BSTR)
#define STAGE_H (ATILE_H + BTILE_H)
#define TG_SMEM (2 * STAGE_H * 2)   // 53248 B

__global__ __launch_bounds__(256, 3) void hgemm_kernel(
    int M, int N, int K,
    const __half* __restrict__ A, const __half* __restrict__ B,
    const float* __restrict__ bias, const float* __restrict__ res,
    float* __restrict__ C, __half* __restrict__ C16,
    const __half* __restrict__ B2, float* __restrict__ C2, __half* __restrict__ C216) {
    extern __shared__ __half sm[];

    if (blockIdx.z) { B = B2; C = C2; C16 = C216; }

    const int tid  = threadIdx.x;
    const int bm   = blockIdx.y * BM;
    const int bn   = blockIdx.x * BN;
    const int warp = tid >> 5, lane = tid & 31;
    const int wm   = (warp >> 2) * 32;
    const int wn   = (warp & 3) * 32;
    const int fr   = lane >> 2;
    const int fc   = lane & 3;
    const int arow_l = ((lane >> 3) & 1) * 8 + (lane & 7);
    const int acol_l = ((lane >> 4) & 1) * 8;
    const int brow4_l = ((lane >> 3) & 1) * 8 + (lane & 7);
    const int bcol4_l = ((lane >> 4) & 1) * 8;

    float acc[2][4][4];
#pragma unroll
    for (int i = 0; i < 2; i++)
#pragma unroll
        for (int j = 0; j < 4; j++)
#pragma unroll
            for (int k = 0; k < 4; k++) acc[i][j][k] = 0.f;

    auto fill = [&](int s, int kt) {
        __half* Ad = sm + s * STAGE_H;
        __half* Bd = Ad + ATILE_H;
#pragma unroll
        for (int p = 0; p < 2; p++) {
            int idx = p * 256 + tid;
            int row = idx >> 3, c8 = idx & 7;
            uint32_t dst = (uint32_t)__cvta_generic_to_shared(Ad + row * ASTR + c8 * 8);
            const __half* src = A + (size_t)(bm + row) * K + kt + c8 * 8;
            asm volatile("cp.async.cg.shared.global [%0], [%1], 16;\n" :: "r"(dst), "l"(src));
        }
#pragma unroll
        for (int p = 0; p < 4; p++) {
            int idx = p * 256 + tid;
            int row = idx >> 4, c16 = idx & 15;
            uint32_t dst = (uint32_t)__cvta_generic_to_shared(Bd + row * BSTR + c16 * 8);
            const __half* src = B + (size_t)(kt + row) * N + bn + c16 * 8;
            asm volatile("cp.async.cg.shared.global [%0], [%1], 16;\n" :: "r"(dst), "l"(src));
        }
        asm volatile("cp.async.commit_group;\n");
    };

    auto compute_tile = [&](int s) {
        const __half* Ab = sm + s * STAGE_H;
        const __half* Bb = Ab + ATILE_H;
        uint32_t abase = (uint32_t)__cvta_generic_to_shared(Ab + (wm + arow_l) * ASTR + acol_l);
        uint32_t bbase = (uint32_t)__cvta_generic_to_shared(Bb + brow4_l * BSTR + wn + bcol4_l);
#pragma unroll
        for (int ks = 0; ks < 4; ks++) {
            uint32_t af[2][4], bf[4][2];
#pragma unroll
            for (int mi = 0; mi < 2; mi++)
                ldsm4(af[mi], abase + (mi * 16 * ASTR + ks * 16) * 2);
#pragma unroll
            for (int n2 = 0; n2 < 2; n2++) {
                uint32_t r4[4];
                ldsm4t(r4, bbase + (ks * 16 * BSTR + n2 * 16) * 2);
                bf[2 * n2][0] = r4[0]; bf[2 * n2][1] = r4[1];
                bf[2 * n2 + 1][0] = r4[2]; bf[2 * n2 + 1][1] = r4[3];
            }
#pragma unroll
            for (int mi = 0; mi < 2; mi++)
#pragma unroll
                for (int ni = 0; ni < 4; ni++) mma_f16(acc[mi][ni], af[mi], bf[ni]);
        }
    };

    const int kiters = K / BK;
    fill(0, 0);
    asm volatile("cp.async.wait_group 0;\n");
    __syncthreads();

#pragma unroll 1
    for (int it = 0; it < kiters; ++it) {
        int cur = it & 1;
        if (it + 1 < kiters) fill(cur ^ 1, (it + 1) * BK);
        compute_tile(cur);
        asm volatile("cp.async.wait_group 0;\n");
        __syncthreads();
    }

#pragma unroll
    for (int mi = 0; mi < 2; mi++) {
#pragma unroll
        for (int ni = 0; ni < 4; ni++) {
            int gr = bm + wm + mi * 16 + fr;
            int gc = bn + wn + ni * 8 + fc * 2;
            float2 o0 = make_float2(acc[mi][ni][0], acc[mi][ni][1]);
            float2 o1 = make_float2(acc[mi][ni][2], acc[mi][ni][3]);
            if (bias) {
                float2 bv = *(const float2*)(bias + gc);
                o0.x += bv.x; o0.y += bv.y;
                o1.x += bv.x; o1.y += bv.y;
            }
            if (res) {
                float2 r0 = *(const float2*)(res + (size_t)gr * N + gc);
                float2 r1 = *(const float2*)(res + (size_t)(gr + 8) * N + gc);
                o0.x += r0.x; o0.y += r0.y;
                o1.x += r1.x; o1.y += r1.y;
            }
            if (C16) {
                *(__half2*)(C16 + (size_t)gr * N + gc) = __floats2half2_rn(o0.x, o0.y);
                *(__half2*)(C16 + (size_t)(gr + 8) * N + gc) = __floats2half2_rn(o1.x, o1.y);
            } else {
                *(float2*)(C + (size_t)gr * N + gc) = o0;
                *(float2*)(C + (size_t)(gr + 8) * N + gc) = o1;
            }
        }
    }
}

// ================= fp16 flash attention (R12 config: 64-row Q tile, 128 threads) =================
#define ATSTR 72
#define ATT_TILE_H (64 * ATSTR)
#define ATT_SMEM (6 * ATT_TILE_H * 2)   // 55296 B

__global__ __launch_bounds__(128) void attn_kernel(const __half* __restrict__ qkv,
                                                   __half* __restrict__ ctx) {
    extern __shared__ __half smh[];
    __half* Qs = smh;
    __half* Ps = Qs + ATT_TILE_H;
    __half* KV = Ps + ATT_TILE_H;

    const int qt = blockIdx.x, h = blockIdx.y, b = blockIdx.z;
    const int m0 = qt * 64;
    const int tid  = threadIdx.x;
    const int warp = tid >> 5, lane = tid & 31;
    const int fr = lane >> 2, fc = lane & 3;
    const int w16 = warp * 16;
    const int arow_l = ((lane >> 3) & 1) * 8 + (lane & 7);
    const int acol_l = ((lane >> 4) & 1) * 8;
    const int brow_l = arow_l;
    const int krow_l = lane & 7;
    const int ksel_l = ((lane >> 3) & 1) * 8;
    const float slope = exp2f(-(1.0f + 7.0f * (float)h / 15.0f));
    const float step8 = 8.0f * slope;
    const __half2 qscale = __floats2half2_rn(0.125f, 0.125f);

    auto fill_kv = [&](int kt, int bufsel) {
        __half* Kd = KV + bufsel * 2 * ATT_TILE_H;
        __half* Vd = Kd + ATT_TILE_H;
        const int n0 = kt * 64;
#pragma unroll
        for (int p = 0; p < 4; p++) {
            int i = p * 128 + tid;
            int r = i >> 3, c = (i & 7) * 8;
            size_t base = ((size_t)(b * L_ + n0 + r) * H_ + h) * 3;
            uint32_t kd = (uint32_t)__cvta_generic_to_shared(Kd + r * ATSTR + c);
            uint32_t vd = (uint32_t)__cvta_generic_to_shared(Vd + r * ATSTR + c);
            const __half* ks = qkv + (base + 1) * D_ + c;
            const __half* vs = qkv + (base + 2) * D_ + c;
            asm volatile("cp.async.cg.shared.global [%0], [%1], 16;\n" :: "r"(kd), "l"(ks));
            asm volatile("cp.async.cg.shared.global [%0], [%1], 16;\n" :: "r"(vd), "l"(vs));
        }
        asm volatile("cp.async.commit_group;\n");
    };

    for (int i = tid; i < 64 * 16; i += 128) {
        int r = i >> 4, c = (i & 15) << 2;
        uint2 v = *(const uint2*)(qkv + ((((size_t)(b * L_ + m0 + r) * H_ + h) * 3 + 0) * D_ + c));
        __half2 q0 = __hmul2(*reinterpret_cast<__half2*>(&v.x), qscale);
        __half2 q1 = __hmul2(*reinterpret_cast<__half2*>(&v.y), qscale);
        *(uint2*)(Qs + r * ATSTR + c) = make_uint2(h2u(q0), h2u(q1));
    }
    fill_kv(0, 0);
    __syncthreads();

    const uint32_t qbase = (uint32_t)__cvta_generic_to_shared(Qs + (w16 + arow_l) * ATSTR + acol_l);
    const uint32_t pbase = (uint32_t)__cvta_generic_to_shared(Ps + (w16 + arow_l) * ATSTR + acol_l);

    uint32_t qf[4][4];
#pragma unroll
    for (int ks = 0; ks < 4; ks++) ldsm4(qf[ks], qbase + ks * 16 * 2);

    float oacc[8][4];
#pragma unroll
    for (int i = 0; i < 8; i++)
#pragma unroll
        for (int j = 0; j < 4; j++) oacc[i][j] = 0.f;
    float mrow0 = -CUDART_INF_F, mrow1 = -CUDART_INF_F;
    float lrow0 = 0.f, lrow1 = 0.f;

    const int gi0 = m0 + w16 + fr;
    const int gi1 = gi0 + 8;

#pragma unroll 1
    for (int kt = 0; kt <= qt; kt++) {
        const int n0 = kt * 64;
        const int bufsel = kt & 1;
        if (kt + 1 <= qt) {
            fill_kv(kt + 1, bufsel ^ 1);
            asm volatile("cp.async.wait_group 1;\n");
        } else {
            asm volatile("cp.async.wait_group 0;\n");
        }
        __syncthreads();

        const __half* Kd = KV + bufsel * 2 * ATT_TILE_H;
        const __half* Vd = Kd + ATT_TILE_H;
        const uint32_t kbase = (uint32_t)__cvta_generic_to_shared(Kd + krow_l * ATSTR + ksel_l);
        const uint32_t vbase = (uint32_t)__cvta_generic_to_shared(Vd + brow_l * ATSTR);

        float sacc[8][4];
#pragma unroll
        for (int i = 0; i < 8; i++)
#pragma unroll
            for (int j = 0; j < 4; j++) sacc[i][j] = 0.f;
#pragma unroll
        for (int ks = 0; ks < 4; ks++) {
            uint32_t bf[8][2];
#pragma unroll
            for (int ni = 0; ni < 8; ni++)
                ldsm2(bf[ni], kbase + (ni * 8 * ATSTR + ks * 16) * 2);
#pragma unroll
            for (int ni = 0; ni < 8; ni++) mma_f16(sacc[ni], qf[ks], bf[ni]);
        }

        {
            float a0 = slope * (float)(n0 + 2 * fc - gi0);
            float a2 = slope * (float)(n0 + 2 * fc - gi1);
            if (kt < qt) {
#pragma unroll
                for (int ni = 0; ni < 8; ni++) {
                    sacc[ni][0] += a0;
                    sacc[ni][1] += a0 + slope;
                    sacc[ni][2] += a2;
                    sacc[ni][3] += a2 + slope;
                    a0 += step8;
                    a2 += step8;
                }
            } else {
#pragma unroll
                for (int ni = 0; ni < 8; ni++) {
                    int gj = n0 + ni * 8 + 2 * fc;
                    sacc[ni][0] = (gj     > gi0) ? -CUDART_INF_F : sacc[ni][0] + a0;
                    sacc[ni][1] = (gj + 1 > gi0) ? -CUDART_INF_F : sacc[ni][1] + a0 + slope;
                    sacc[ni][2] = (gj     > gi1) ? -CUDART_INF_F : sacc[ni][2] + a2;
                    sacc[ni][3] = (gj + 1 > gi1) ? -CUDART_INF_F : sacc[ni][3] + a2 + slope;
                    a0 += step8;
                    a2 += step8;
                }
            }
        }

        float mx0 = -CUDART_INF_F, mx1 = -CUDART_INF_F;
#pragma unroll
        for (int ni = 0; ni < 8; ni++) {
            mx0 = fmaxf(mx0, fmaxf(sacc[ni][0], sacc[ni][1]));
            mx1 = fmaxf(mx1, fmaxf(sacc[ni][2], sacc[ni][3]));
        }
        mx0 = fmaxf(mx0, __shfl_xor_sync(0xffffffffu, mx0, 1));
        mx0 = fmaxf(mx0, __shfl_xor_sync(0xffffffffu, mx0, 2));
        mx1 = fmaxf(mx1, __shfl_xor_sync(0xffffffffu, mx1, 1));
        mx1 = fmaxf(mx1, __shfl_xor_sync(0xffffffffu, mx1, 2));
        float mn0 = fmaxf(mrow0, mx0);
        float mn1 = fmaxf(mrow1, mx1);
        float alpha0 = __expf(mrow0 - mn0);
        float alpha1 = __expf(mrow1 - mn1);
        float rs0 = 0.f, rs1 = 0.f;
#pragma unroll
        for (int ni = 0; ni < 8; ni++) {
            sacc[ni][0] = __expf(sacc[ni][0] - mn0);
            sacc[ni][1] = __expf(sacc[ni][1] - mn0);
            sacc[ni][2] = __expf(sacc[ni][2] - mn1);
            sacc[ni][3] = __expf(sacc[ni][3] - mn1);
            rs0 += sacc[ni][0] + sacc[ni][1];
            rs1 += sacc[ni][2] + sacc[ni][3];
        }
        rs0 += __shfl_xor_sync(0xffffffffu, rs0, 1);
        rs0 += __shfl_xor_sync(0xffffffffu, rs0, 2);
        rs1 += __shfl_xor_sync(0xffffffffu, rs1, 1);
        rs1 += __shfl_xor_sync(0xffffffffu, rs1, 2);
        lrow0 = lrow0 * alpha0 + rs0;
        lrow1 = lrow1 * alpha1 + rs1;
        mrow0 = mn0;
        mrow1 = mn1;
#pragma unroll
        for (int ni = 0; ni < 8; ni++) {
            oacc[ni][0] *= alpha0;
            oacc[ni][1] *= alpha0;
            oacc[ni][2] *= alpha1;
            oacc[ni][3] *= alpha1;
        }

#pragma unroll
        for (int ni = 0; ni < 8; ni++) {
            int c = ni * 8 + 2 * fc;
            *(__half2*)&Ps[(w16 + fr) * ATSTR + c]     = __floats2half2_rn(sacc[ni][0], sacc[ni][1]);
            *(__half2*)&Ps[(w16 + fr + 8) * ATSTR + c] = __floats2half2_rn(sacc[ni][2], sacc[ni][3]);
        }
        __syncwarp();

#pragma unroll
        for (int ks = 0; ks < 4; ks++) {
            uint32_t af[4];
            ldsm4(af, pbase + ks * 16 * 2);
#pragma unroll
            for (int ni = 0; ni < 8; ni++) {
                uint32_t bf[2];
                ldsm2t(bf, vbase + (ks * 16 * ATSTR + ni * 8) * 2);
                mma_f16(oacc[ni], af, bf);
            }
        }
        __syncthreads();
    }

    float inv0 = 1.0f / lrow0;
    float inv1 = 1.0f / lrow1;
#pragma unroll
    for (int ni = 0; ni < 8; ni++) {
        int c = h * D_ + ni * 8 + 2 * fc;
        *(__half2*)(ctx + (size_t)(b * L_ + gi0) * HD_ + c) =
            __floats2half2_rn(oacc[ni][0] * inv0, oacc[ni][1] * inv0);
        *(__half2*)(ctx + (size_t)(b * L_ + gi1) * HD_ + c) =
            __floats2half2_rn(oacc[ni][2] * inv1, oacc[ni][3] * inv1);
    }
}

// ---------------- launch ----------------
extern "C" void kernel_launch(void* const* d_in, const int* in_sizes, int n_in,
                              void* d_out, int out_size) {
    (void)in_sizes; (void)n_in; (void)out_size;
    const float* X    = (const float*)d_in[0];
    const float* Wqkv = (const float*)d_in[2];
    const float* bqkv = (const float*)d_in[3];
    const float* Wo   = (const float*)d_in[4];
    const float* bo   = (const float*)d_in[5];
    const float* Ww   = (const float*)d_in[12];
    const float* Wv   = (const float*)d_in[13];
    const float* Wout = (const float*)d_in[14];
    float* out = (float*)d_out;

    float *x_p;
    __half *h16, *qkv16, *ctx16, *gate16, *val16, *gg16;
    __half *wqkv16, *wo16, *ww16, *wv16, *wout16;
    cudaGetSymbolAddress((void**)&x_p,    g_x);
    cudaGetSymbolAddress((void**)&h16,    g_h16);
    cudaGetSymbolAddress((void**)&qkv16,  g_qkv16);
    cudaGetSymbolAddress((void**)&ctx16,  g_ctx16);
    cudaGetSymbolAddress((void**)&gate16, g_gate16);
    cudaGetSymbolAddress((void**)&val16,  g_val16);
    cudaGetSymbolAddress((void**)&gg16,   g_gg16);
    cudaGetSymbolAddress((void**)&wqkv16, g_wqkv16);
    cudaGetSymbolAddress((void**)&wo16,   g_wo16);
    cudaGetSymbolAddress((void**)&ww16,   g_ww16);
    cudaGetSymbolAddress((void**)&wv16,   g_wv16);
    cudaGetSymbolAddress((void**)&wout16, g_wout16);

    cudaFuncSetAttribute(attn_kernel, cudaFuncAttributeMaxDynamicSharedMemorySize, ATT_SMEM);
    cudaFuncSetAttribute(hgemm_kernel, cudaFuncAttributeMaxDynamicSharedMemorySize, TG_SMEM);

    // 0. all fp16 weight conversions in one launch
    f2h_all_kernel<<<16384, 256>>>(Wqkv, wqkv16, Wo, wo16, Ww, ww16, Wv, wv16, Wout, wout16);

    // 1. h16 = rmsnorm(X)
    rmsnorm_kernel<<<M_, 256>>>(X, h16);
    // 2. qkv16 = h16 @ wqkv16 + bqkv
    hgemm_kernel<<<dim3(3 * HD_ / BN, M_ / BM), 256, TG_SMEM>>>(
        M_, 3 * HD_, E_, h16, wqkv16, bqkv, nullptr, nullptr, qkv16,
        nullptr, nullptr, nullptr);
    // 3. attention (64-row Q tiles, R12 config)
    attn_kernel<<<dim3(L_ / 64, H_, B_), 128, ATT_SMEM>>>(qkv16, ctx16);
    // 4. x = X + ctx16 @ wo16 + bo
    hgemm_kernel<<<dim3(E_ / BN, M_ / BM), 256, TG_SMEM>>>(
        M_, E_, HD_, ctx16, wo16, bo, X, x_p, nullptr,
        nullptr, nullptr, nullptr);
    // 5+6. x = x + rmsnorm(x); h16 = rmsnorm(x)
    addnorm_kernel<<<M_, 256>>>(x_p, h16);
    // 7. gate16 / val16 (dual-output, z selects)
    hgemm_kernel<<<dim3(DFF_ / BN, M_ / BM, 2), 256, TG_SMEM>>>(
        M_, DFF_, E_, h16, ww16, nullptr, nullptr, nullptr, gate16,
        wv16, nullptr, val16);
    // 8. gg16 = gelu(gate16) * val16
    geglu_kernel<<<(M_ * DFF_) / 1024, 256>>>(gate16, val16, gg16);
    // 9. out = x + gg16 @ wout16
    hgemm_kernel<<<dim3(E_ / BN, M_ / BM), 256, TG_SMEM>>>(
        M_, E_, DFF_, gg16, wout16, nullptr, x_p, out, nullptr,
        nullptr, nullptr, nullptr);
}

// round 15
// speedup vs baseline: 2.0373x; 1.0194x over previous
#include <cuda_runtime.h>
#include <cuda_fp16.h>
#include <math_constants.h>
#include <cstdint>

#define B_   2
#define L_   2048
#define E_   1024
#define H_   16
#define D_   64
#define DFF_ 4096
#define M_   (B_ * L_)   // 4096 tokens
#define HD_  (H_ * D_)   // 1024

// ---------------- scratch (device globals: allocation-guard safe) ----------------
__device__ float  g_x[M_ * E_];
__device__ __half g_h16[M_ * E_];
__device__ __half g_qkv16[(size_t)M_ * 3 * HD_];
__device__ __half g_ctx16[M_ * HD_];
__device__ __half g_gate16[(size_t)M_ * DFF_];
__device__ __half g_val16[(size_t)M_ * DFF_];
__device__ __half g_gg16[(size_t)M_ * DFF_];
__device__ __half g_wqkv16[(size_t)E_ * 3 * HD_];
__device__ __half g_wo16[(size_t)HD_ * E_];
__device__ __half g_ww16[(size_t)E_ * DFF_];
__device__ __half g_wv16[(size_t)E_ * DFF_];
__device__ __half g_wout16[(size_t)DFF_ * E_];

__device__ __forceinline__ uint32_t h2u(__half2 h) {
    return *reinterpret_cast<uint32_t*>(&h);
}

// ---------------- fused fp32->fp16 conversion for ALL 5 weight tensors ----------------
__global__ __launch_bounds__(256) void f2h_all_kernel(
    const float* __restrict__ s0, __half* __restrict__ d0,
    const float* __restrict__ s1, __half* __restrict__ d1,
    const float* __restrict__ s2, __half* __restrict__ d2,
    const float* __restrict__ s3, __half* __restrict__ d3,
    const float* __restrict__ s4, __half* __restrict__ d4) {
    unsigned i = blockIdx.x * 256 + threadIdx.x;
    const float* s; __half* d; unsigned off;
    if (i < 786432u)       { s = s0; d = d0; off = i; }
    else if (i < 1048576u) { s = s1; d = d1; off = i - 786432u; }
    else if (i < 2097152u) { s = s2; d = d2; off = i - 1048576u; }
    else if (i < 3145728u) { s = s3; d = d3; off = i - 2097152u; }
    else                   { s = s4; d = d4; off = i - 3145728u; }
    float4 v = ((const float4*)s)[off];
    ((uint2*)d)[off] = make_uint2(h2u(__floats2half2_rn(v.x, v.y)),
                                  h2u(__floats2half2_rn(v.z, v.w)));
}

// ---------------- rmsnorm (fp16 out) ----------------
__global__ __launch_bounds__(256) void rmsnorm_kernel(const float* __restrict__ x,
                                                      __half* __restrict__ y) {
    int row = blockIdx.x;
    float4 a = ((const float4*)(x + (size_t)row * E_))[threadIdx.x];
    float ss = a.x * a.x + a.y * a.y + a.z * a.z + a.w * a.w;
    __shared__ float red[8];
    __shared__ float sinv;
#pragma unroll
    for (int o = 16; o > 0; o >>= 1) ss += __shfl_xor_sync(0xffffffffu, ss, o);
    if ((threadIdx.x & 31) == 0) red[threadIdx.x >> 5] = ss;
    __syncthreads();
    if (threadIdx.x == 0) {
        float t = 0.f;
#pragma unroll
        for (int i = 0; i < 8; i++) t += red[i];
        sinv = rsqrtf(t * (1.0f / E_));
    }
    __syncthreads();
    float c = sinv;
    ((uint2*)(y + (size_t)row * E_))[threadIdx.x] =
        make_uint2(h2u(__floats2half2_rn(a.x * c, a.y * c)),
                   h2u(__floats2half2_rn(a.z * c, a.w * c)));
}

// ---------------- fused: x = x + rmsnorm(x); h16 = rmsnorm(x) ----------------
__global__ __launch_bounds__(256) void addnorm_kernel(float* __restrict__ x,
                                                      __half* __restrict__ h) {
    int row = blockIdx.x;
    float4 a = ((const float4*)(x + (size_t)row * E_))[threadIdx.x];
    __shared__ float red[8];
    __shared__ float sval;
    float ss = a.x * a.x + a.y * a.y + a.z * a.z + a.w * a.w;
#pragma unroll
    for (int o = 16; o > 0; o >>= 1) ss += __shfl_xor_sync(0xffffffffu, ss, o);
    if ((threadIdx.x & 31) == 0) red[threadIdx.x >> 5] = ss;
    __syncthreads();
    if (threadIdx.x == 0) {
        float t = 0.f;
#pragma unroll
        for (int i = 0; i < 8; i++) t += red[i];
        sval = 1.0f + rsqrtf(t * (1.0f / E_));
    }
    __syncthreads();
    float c = sval;
    a.x *= c; a.y *= c; a.z *= c; a.w *= c;
    float ss2 = a.x * a.x + a.y * a.y + a.z * a.z + a.w * a.w;
#pragma unroll
    for (int o = 16; o > 0; o >>= 1) ss2 += __shfl_xor_sync(0xffffffffu, ss2, o);
    if ((threadIdx.x & 31) == 0) red[threadIdx.x >> 5] = ss2;
    __syncthreads();
    if (threadIdx.x == 0) {
        float t = 0.f;
#pragma unroll
        for (int i = 0; i < 8; i++) t += red[i];
        sval = rsqrtf(t * (1.0f / E_));
    }
    __syncthreads();
    float inv2 = sval;
    ((float4*)(x + (size_t)row * E_))[threadIdx.x] = a;
    ((uint2*)(h + (size_t)row * E_))[threadIdx.x] =
        make_uint2(h2u(__floats2half2_rn(a.x * inv2, a.y * inv2)),
                   h2u(__floats2half2_rn(a.z * inv2, a.w * inv2)));
}

// ---------------- geglu (fp16 in/out) ----------------
__global__ __launch_bounds__(256) void geglu_kernel(const __half* __restrict__ g,
                                                    const __half* __restrict__ v,
                                                    __half* __restrict__ o) {
    int i = (blockIdx.x * 256 + threadIdx.x) * 4;
    uint2 gu = *(const uint2*)(g + i);
    uint2 vu = *(const uint2*)(v + i);
    float2 g0 = __half22float2(*reinterpret_cast<__half2*>(&gu.x));
    float2 g1 = __half22float2(*reinterpret_cast<__half2*>(&gu.y));
    float2 v0 = __half22float2(*reinterpret_cast<__half2*>(&vu.x));
    float2 v1 = __half22float2(*reinterpret_cast<__half2*>(&vu.y));
    float r0 = 0.5f * g0.x * (1.0f + erff(g0.x * 0.70710678118654752f)) * v0.x;
    float r1 = 0.5f * g0.y * (1.0f + erff(g0.y * 0.70710678118654752f)) * v0.y;
    float r2 = 0.5f * g1.x * (1.0f + erff(g1.x * 0.70710678118654752f)) * v1.x;
    float r3 = 0.5f * g1.y * (1.0f + erff(g1.y * 0.70710678118654752f)) * v1.y;
    *(uint2*)(o + i) = make_uint2(h2u(__floats2half2_rn(r0, r1)),
                                  h2u(__floats2half2_rn(r2, r3)));
}

// ================= mma helpers =================
__device__ __forceinline__ void mma_f16(float* d, const uint32_t* a, const uint32_t* b) {
    asm volatile(
        "mma.sync.aligned.m16n8k16.row.col.f32.f16.f16.f32 "
        "{%0,%1,%2,%3}, {%4,%5,%6,%7}, {%8,%9}, {%0,%1,%2,%3};\n"
        : "+f"(d[0]), "+f"(d[1]), "+f"(d[2]), "+f"(d[3])
        : "r"(a[0]), "r"(a[1]), "r"(a[2]), "r"(a[3]), "r"(b[0]), "r"(b[1]));
}

__device__ __forceinline__ void ldsm4(uint32_t* r, uint32_t saddr) {
    asm volatile("ldmatrix.sync.aligned.m8n8.x4.shared.b16 {%0,%1,%2,%3}, [%4];"
                 : "=r"(r[0]), "=r"(r[1]), "=r"(r[2]), "=r"(r[3]) : "r"(saddr));
}
__device__ __forceinline__ void ldsm4t(uint32_t* r, uint32_t saddr) {
    asm volatile("ldmatrix.sync.aligned.m8n8.x4.trans.shared.b16 {%0,%1,%2,%3}, [%4];"
                 : "=r"(r[0]), "=r"(r[1]), "=r"(r[2]), "=r"(r[3]) : "r"(saddr));
}
__device__ __forceinline__ void ldsm2t(uint32_t* r, uint32_t saddr) {
    asm volatile("ldmatrix.sync.aligned.m8n8.x2.trans.shared.b16 {%0,%1}, [%2];"
                 : "=r"(r[0]), "=r"(r[1]) : "r"(saddr));
}
__device__ __forceinline__ void ldsm2(uint32_t* r, uint32_t saddr) {
    asm volatile("ldmatrix.sync.aligned.m8n8.x2.shared.b16 {%0,%1}, [%2];"
                 : "=r"(r[0]), "=r"(r[1]) : "r"(saddr));
}

// ================= fp16 tensor-core GEMM (R14, unchanged) =================
#define BM 64
#define BN 128
#define BK 64
#define ASTR 72
#define BSTR 136
#define ATILE_H (BM * ASTR)
#define BTILE_H (BK * BSTR)
#define STAGE_H (ATILE_H + BTILE_H)
#define TG_SMEM (2 * STAGE_H * 2)   // 53248 B

__global__ __launch_bounds__(256, 3) void hgemm_kernel(
    int M, int N, int K,
    const __half* __restrict__ A, const __half* __restrict__ B,
    const float* __restrict__ bias, const float* __restrict__ res,
    float* __restrict__ C, __half* __restrict__ C16,
    const __half* __restrict__ B2, float* __restrict__ C2, __half* __restrict__ C216) {
    extern __shared__ __half sm[];

    if (blockIdx.z) { B = B2; C = C2; C16 = C216; }

    const int tid  = threadIdx.x;
    const int bm   = blockIdx.y * BM;
    const int bn   = blockIdx.x * BN;
    const int warp = tid >> 5, lane = tid & 31;
    const int wm   = (warp >> 2) * 32;
    const int wn   = (warp & 3) * 32;
    const int fr   = lane >> 2;
    const int fc   = lane & 3;
    const int arow_l = ((lane >> 3) & 1) * 8 + (lane & 7);
    const int acol_l = ((lane >> 4) & 1) * 8;
    const int brow4_l = ((lane >> 3) & 1) * 8 + (lane & 7);
    const int bcol4_l = ((lane >> 4) & 1) * 8;

    float acc[2][4][4];
#pragma unroll
    for (int i = 0; i < 2; i++)
#pragma unroll
        for (int j = 0; j < 4; j++)
#pragma unroll
            for (int k = 0; k < 4; k++) acc[i][j][k] = 0.f;

    auto fill = [&](int s, int kt) {
        __half* Ad = sm + s * STAGE_H;
        __half* Bd = Ad + ATILE_H;
#pragma unroll
        for (int p = 0; p < 2; p++) {
            int idx = p * 256 + tid;
            int row = idx >> 3, c8 = idx & 7;
            uint32_t dst = (uint32_t)__cvta_generic_to_shared(Ad + row * ASTR + c8 * 8);
            const __half* src = A + (size_t)(bm + row) * K + kt + c8 * 8;
            asm volatile("cp.async.cg.shared.global [%0], [%1], 16;\n" :: "r"(dst), "l"(src));
        }
#pragma unroll
        for (int p = 0; p < 4; p++) {
            int idx = p * 256 + tid;
            int row = idx >> 4, c16 = idx & 15;
            uint32_t dst = (uint32_t)__cvta_generic_to_shared(Bd + row * BSTR + c16 * 8);
            const __half* src = B + (size_t)(kt + row) * N + bn + c16 * 8;
            asm volatile("cp.async.cg.shared.global [%0], [%1], 16;\n" :: "r"(dst), "l"(src));
        }
        asm volatile("cp.async.commit_group;\n");
    };

    auto compute_tile = [&](int s) {
        const __half* Ab = sm + s * STAGE_H;
        const __half* Bb = Ab + ATILE_H;
        uint32_t abase = (uint32_t)__cvta_generic_to_shared(Ab + (wm + arow_l) * ASTR + acol_l);
        uint32_t bbase = (uint32_t)__cvta_generic_to_shared(Bb + brow4_l * BSTR + wn + bcol4_l);
#pragma unroll
        for (int ks = 0; ks < 4; ks++) {
            uint32_t af[2][4], bf[4][2];
#pragma unroll
            for (int mi = 0; mi < 2; mi++)
                ldsm4(af[mi], abase + (mi * 16 * ASTR + ks * 16) * 2);
#pragma unroll
            for (int n2 = 0; n2 < 2; n2++) {
                uint32_t r4[4];
                ldsm4t(r4, bbase + (ks * 16 * BSTR + n2 * 16) * 2);
                bf[2 * n2][0] = r4[0]; bf[2 * n2][1] = r4[1];
                bf[2 * n2 + 1][0] = r4[2]; bf[2 * n2 + 1][1] = r4[3];
            }
#pragma unroll
            for (int mi = 0; mi < 2; mi++)
#pragma unroll
                for (int ni = 0; ni < 4; ni++) mma_f16(acc[mi][ni], af[mi], bf[ni]);
        }
    };

    const int kiters = K / BK;
    fill(0, 0);
    asm volatile("cp.async.wait_group 0;\n");
    __syncthreads();

#pragma unroll 1
    for (int it = 0; it < kiters; ++it) {
        int cur = it & 1;
        if (it + 1 < kiters) fill(cur ^ 1, (it + 1) * BK);
        compute_tile(cur);
        asm volatile("cp.async.wait_group 0;\n");
        __syncthreads();
    }

#pragma unroll
    for (int mi = 0; mi < 2; mi++) {
#pragma unroll
        for (int ni = 0; ni < 4; ni++) {
            int gr = bm + wm + mi * 16 + fr;
            int gc = bn + wn + ni * 8 + fc * 2;
            float2 o0 = make_float2(acc[mi][ni][0], acc[mi][ni][1]);
            float2 o1 = make_float2(acc[mi][ni][2], acc[mi][ni][3]);
            if (bias) {
                float2 bv = *(const float2*)(bias + gc);
                o0.x += bv.x; o0.y += bv.y;
                o1.x += bv.x; o1.y += bv.y;
            }
            if (res) {
                float2 r0 = *(const float2*)(res + (size_t)gr * N + gc);
                float2 r1 = *(const float2*)(res + (size_t)(gr + 8) * N + gc);
                o0.x += r0.x; o0.y += r0.y;
                o1.x += r1.x; o1.y += r1.y;
            }
            if (C16) {
                *(__half2*)(C16 + (size_t)gr * N + gc) = __floats2half2_rn(o0.x, o0.y);
                *(__half2*)(C16 + (size_t)(gr + 8) * N + gc) = __floats2half2_rn(o1.x, o1.y);
            } else {
                *(float2*)(C + (size_t)gr * N + gc) = o0;
                *(float2*)(C + (size_t)(gr + 8) * N + gc) = o1;
            }
        }
    }
}

// ================= fp16 flash attention: log2-domain softmax, frag-direct P, no Ps =================
// S accumulator fragment == PV A-fragment layout (rows fr/fr+8, cols 2fc,2fc+1 per 8-col tile),
// so P never touches smem. Softmax in log2 domain (log2e folded into Q scale + alibi slope).
#define ATSTR 72
#define ATT_TILE_H (64 * ATSTR)
#define ATT_SMEM (5 * ATT_TILE_H * 2)   // Qs + 2 x (K|V) = 46080 B

__global__ __launch_bounds__(128) void attn_kernel(const __half* __restrict__ qkv,
                                                   __half* __restrict__ ctx) {
    extern __shared__ __half smh[];
    __half* Qs = smh;
    __half* KV = Qs + ATT_TILE_H;

    // reversed mapping: longest causal chains launch first
    const int qt = (int)(gridDim.x - 1 - blockIdx.x);
    const int h = blockIdx.y, b = blockIdx.z;
    const int m0 = qt * 64;
    const int tid  = threadIdx.x;
    const int warp = tid >> 5, lane = tid & 31;
    const int fr = lane >> 2, fc = lane & 3;
    const int w16 = warp * 16;
    const int arow_l = ((lane >> 3) & 1) * 8 + (lane & 7);
    const int acol_l = ((lane >> 4) & 1) * 8;
    const int brow_l = arow_l;
    const int krow_l = lane & 7;
    const int ksel_l = ((lane >> 3) & 1) * 8;
    const float LOG2E = 1.44269504088896341f;
    const float slope2 = exp2f(-(1.0f + 7.0f * (float)h / 15.0f)) * LOG2E;  // log2-domain alibi
    const float step8 = 8.0f * slope2;
    const __half2 qscale = __floats2half2_rn(0.125f * LOG2E, 0.125f * LOG2E);

    auto fill_kv = [&](int kt, int bufsel) {
        __half* Kd = KV + bufsel * 2 * ATT_TILE_H;
        __half* Vd = Kd + ATT_TILE_H;
        const int n0 = kt * 64;
#pragma unroll
        for (int p = 0; p < 4; p++) {
            int i = p * 128 + tid;
            int r = i >> 3, c = (i & 7) * 8;
            size_t base = ((size_t)(b * L_ + n0 + r) * H_ + h) * 3;
            uint32_t kd = (uint32_t)__cvta_generic_to_shared(Kd + r * ATSTR + c);
            uint32_t vd = (uint32_t)__cvta_generic_to_shared(Vd + r * ATSTR + c);
            const __half* ks = qkv + (base + 1) * D_ + c;
            const __half* vs = qkv + (base + 2) * D_ + c;
            asm volatile("cp.async.cg.shared.global [%0], [%1], 16;\n" :: "r"(kd), "l"(ks));
            asm volatile("cp.async.cg.shared.global [%0], [%1], 16;\n" :: "r"(vd), "l"(vs));
        }
        asm volatile("cp.async.commit_group;\n");
    };

    for (int i = tid; i < 64 * 16; i += 128) {
        int r = i >> 4, c = (i & 15) << 2;
        uint2 v = *(const uint2*)(qkv + ((((size_t)(b * L_ + m0 + r) * H_ + h) * 3 + 0) * D_ + c));
        __half2 q0 = __hmul2(*reinterpret_cast<__half2*>(&v.x), qscale);
        __half2 q1 = __hmul2(*reinterpret_cast<__half2*>(&v.y), qscale);
        *(uint2*)(Qs + r * ATSTR + c) = make_uint2(h2u(q0), h2u(q1));
    }
    fill_kv(0, 0);
    __syncthreads();

    const uint32_t qbase = (uint32_t)__cvta_generic_to_shared(Qs + (w16 + arow_l) * ATSTR + acol_l);

    uint32_t qf[4][4];
#pragma unroll
    for (int ks = 0; ks < 4; ks++) ldsm4(qf[ks], qbase + ks * 16 * 2);

    float oacc[8][4];
#pragma unroll
    for (int i = 0; i < 8; i++)
#pragma unroll
        for (int j = 0; j < 4; j++) oacc[i][j] = 0.f;
    float mrow0 = -CUDART_INF_F, mrow1 = -CUDART_INF_F;
    float lrow0 = 0.f, lrow1 = 0.f;

    const int gi0 = m0 + w16 + fr;
    const int gi1 = gi0 + 8;

#pragma unroll 1
    for (int kt = 0; kt <= qt; kt++) {
        const int n0 = kt * 64;
        const int bufsel = kt & 1;
        if (kt + 1 <= qt) {
            fill_kv(kt + 1, bufsel ^ 1);
            asm volatile("cp.async.wait_group 1;\n");
        } else {
            asm volatile("cp.async.wait_group 0;\n");
        }
        __syncthreads();

        const __half* Kd = KV + bufsel * 2 * ATT_TILE_H;
        const __half* Vd = Kd + ATT_TILE_H;
        const uint32_t kbase = (uint32_t)__cvta_generic_to_shared(Kd + krow_l * ATSTR + ksel_l);
        const uint32_t vbase = (uint32_t)__cvta_generic_to_shared(Vd + brow_l * ATSTR);

        float sacc[8][4];
#pragma unroll
        for (int i = 0; i < 8; i++)
#pragma unroll
            for (int j = 0; j < 4; j++) sacc[i][j] = 0.f;
#pragma unroll
        for (int ks = 0; ks < 4; ks++) {
            uint32_t bf[8][2];
#pragma unroll
            for (int ni = 0; ni < 8; ni++)
                ldsm2(bf[ni], kbase + (ni * 8 * ATSTR + ks * 16) * 2);
#pragma unroll
            for (int ni = 0; ni < 8; ni++) mma_f16(sacc[ni], qf[ks], bf[ni]);
        }

        // ---- alibi (incremental, log2-domain) + causal (diag tile only) ----
        {
            float a0 = slope2 * (float)(n0 + 2 * fc - gi0);
            float a2 = slope2 * (float)(n0 + 2 * fc - gi1);
            if (kt < qt) {
#pragma unroll
                for (int ni = 0; ni < 8; ni++) {
                    sacc[ni][0] += a0;
                    sacc[ni][1] += a0 + slope2;
                    sacc[ni][2] += a2;
                    sacc[ni][3] += a2 + slope2;
                    a0 += step8;
                    a2 += step8;
                }
            } else {
#pragma unroll
                for (int ni = 0; ni < 8; ni++) {
                    int gj = n0 + ni * 8 + 2 * fc;
                    sacc[ni][0] = (gj     > gi0) ? -CUDART_INF_F : sacc[ni][0] + a0;
                    sacc[ni][1] = (gj + 1 > gi0) ? -CUDART_INF_F : sacc[ni][1] + a0 + slope2;
                    sacc[ni][2] = (gj     > gi1) ? -CUDART_INF_F : sacc[ni][2] + a2;
                    sacc[ni][3] = (gj + 1 > gi1) ? -CUDART_INF_F : sacc[ni][3] + a2 + slope2;
                    a0 += step8;
                    a2 += step8;
                }
            }
        }

        // ---- online softmax (log2 domain: exp2 only) ----
        float mx0 = -CUDART_INF_F, mx1 = -CUDART_INF_F;
#pragma unroll
        for (int ni = 0; ni < 8; ni++) {
            mx0 = fmaxf(mx0, fmaxf(sacc[ni][0], sacc[ni][1]));
            mx1 = fmaxf(mx1, fmaxf(sacc[ni][2], sacc[ni][3]));
        }
        mx0 = fmaxf(mx0, __shfl_xor_sync(0xffffffffu, mx0, 1));
        mx0 = fmaxf(mx0, __shfl_xor_sync(0xffffffffu, mx0, 2));
        mx1 = fmaxf(mx1, __shfl_xor_sync(0xffffffffu, mx1, 1));
        mx1 = fmaxf(mx1, __shfl_xor_sync(0xffffffffu, mx1, 2));
        float mn0 = fmaxf(mrow0, mx0);
        float mn1 = fmaxf(mrow1, mx1);
        float alpha0 = exp2f(mrow0 - mn0);
        float alpha1 = exp2f(mrow1 - mn1);
        float rs0 = 0.f, rs1 = 0.f;
#pragma unroll
        for (int ni = 0; ni < 8; ni++) {
            sacc[ni][0] = exp2f(sacc[ni][0] - mn0);
            sacc[ni][1] = exp2f(sacc[ni][1] - mn0);
            sacc[ni][2] = exp2f(sacc[ni][2] - mn1);
            sacc[ni][3] = exp2f(sacc[ni][3] - mn1);
            rs0 += sacc[ni][0] + sacc[ni][1];
            rs1 += sacc[ni][2] + sacc[ni][3];
        }
        rs0 += __shfl_xor_sync(0xffffffffu, rs0, 1);
        rs0 += __shfl_xor_sync(0xffffffffu, rs0, 2);
        rs1 += __shfl_xor_sync(0xffffffffu, rs1, 1);
        rs1 += __shfl_xor_sync(0xffffffffu, rs1, 2);
        lrow0 = lrow0 * alpha0 + rs0;
        lrow1 = lrow1 * alpha1 + rs1;
        mrow0 = mn0;
        mrow1 = mn1;
#pragma unroll
        for (int ni = 0; ni < 8; ni++) {
            oacc[ni][0] *= alpha0;
            oacc[ni][1] *= alpha0;
            oacc[ni][2] *= alpha1;
            oacc[ni][3] *= alpha1;
        }

        // ---- O += P @ V : P fragments built DIRECTLY from sacc (layout identity) ----
#pragma unroll
        for (int ks = 0; ks < 4; ks++) {
            uint32_t af[4];
            af[0] = h2u(__floats2half2_rn(sacc[2 * ks][0],     sacc[2 * ks][1]));
            af[1] = h2u(__floats2half2_rn(sacc[2 * ks][2],     sacc[2 * ks][3]));
            af[2] = h2u(__floats2half2_rn(sacc[2 * ks + 1][0], sacc[2 * ks + 1][1]));
            af[3] = h2u(__floats2half2_rn(sacc[2 * ks + 1][2], sacc[2 * ks + 1][3]));
#pragma unroll
            for (int ni = 0; ni < 8; ni++) {
                uint32_t bf[2];
                ldsm2t(bf, vbase + (ks * 16 * ATSTR + ni * 8) * 2);
                mma_f16(oacc[ni], af, bf);
            }
        }
        __syncthreads();
    }

    float inv0 = 1.0f / lrow0;
    float inv1 = 1.0f / lrow1;
#pragma unroll
    for (int ni = 0; ni < 8; ni++) {
        int c = h * D_ + ni * 8 + 2 * fc;
        *(__half2*)(ctx + (size_t)(b * L_ + gi0) * HD_ + c) =
            __floats2half2_rn(oacc[ni][0] * inv0, oacc[ni][1] * inv0);
        *(__half2*)(ctx + (size_t)(b * L_ + gi1) * HD_ + c) =
            __floats2half2_rn(oacc[ni][2] * inv1, oacc[ni][3] * inv1);
    }
}

// ---------------- launch ----------------
extern "C" void kernel_launch(void* const* d_in, const int* in_sizes, int n_in,
                              void* d_out, int out_size) {
    (void)in_sizes; (void)n_in; (void)out_size;
    const float* X    = (const float*)d_in[0];
    const float* Wqkv = (const float*)d_in[2];
    const float* bqkv = (const float*)d_in[3];
    const float* Wo   = (const float*)d_in[4];
    const float* bo   = (const float*)d_in[5];
    const float* Ww   = (const float*)d_in[12];
    const float* Wv   = (const float*)d_in[13];
    const float* Wout = (const float*)d_in[14];
    float* out = (float*)d_out;

    float *x_p;
    __half *h16, *qkv16, *ctx16, *gate16, *val16, *gg16;
    __half *wqkv16, *wo16, *ww16, *wv16, *wout16;
    cudaGetSymbolAddress((void**)&x_p,    g_x);
    cudaGetSymbolAddress((void**)&h16,    g_h16);
    cudaGetSymbolAddress((void**)&qkv16,  g_qkv16);
    cudaGetSymbolAddress((void**)&ctx16,  g_ctx16);
    cudaGetSymbolAddress((void**)&gate16, g_gate16);
    cudaGetSymbolAddress((void**)&val16,  g_val16);
    cudaGetSymbolAddress((void**)&gg16,   g_gg16);
    cudaGetSymbolAddress((void**)&wqkv16, g_wqkv16);
    cudaGetSymbolAddress((void**)&wo16,   g_wo16);
    cudaGetSymbolAddress((void**)&ww16,   g_ww16);
    cudaGetSymbolAddress((void**)&wv16,   g_wv16);
    cudaGetSymbolAddress((void**)&wout16, g_wout16);

    cudaFuncSetAttribute(attn_kernel, cudaFuncAttributeMaxDynamicSharedMemorySize, ATT_SMEM);
    cudaFuncSetAttribute(hgemm_kernel, cudaFuncAttributeMaxDynamicSharedMemorySize, TG_SMEM);

    // 0. all fp16 weight conversions in one launch
    f2h_all_kernel<<<16384, 256>>>(Wqkv, wqkv16, Wo, wo16, Ww, ww16, Wv, wv16, Wout, wout16);

    // 1. h16 = rmsnorm(X)
    rmsnorm_kernel<<<M_, 256>>>(X, h16);
    // 2. qkv16 = h16 @ wqkv16 + bqkv
    hgemm_kernel<<<dim3(3 * HD_ / BN, M_ / BM), 256, TG_SMEM>>>(
        M_, 3 * HD_, E_, h16, wqkv16, bqkv, nullptr, nullptr, qkv16,
        nullptr, nullptr, nullptr);
    // 3. attention
    attn_kernel<<<dim3(L_ / 64, H_, B_), 128, ATT_SMEM>>>(qkv16, ctx16);
    // 4. x = X + ctx16 @ wo16 + bo
    hgemm_kernel<<<dim3(E_ / BN, M_ / BM), 256, TG_SMEM>>>(
        M_, E_, HD_, ctx16, wo16, bo, X, x_p, nullptr,
        nullptr, nullptr, nullptr);
    // 5+6. x = x + rmsnorm(x); h16 = rmsnorm(x)
    addnorm_kernel<<<M_, 256>>>(x_p, h16);
    // 7. gate16 / val16 (dual-output, z selects)
    hgemm_kernel<<<dim3(DFF_ / BN, M_ / BM, 2), 256, TG_SMEM>>>(
        M_, DFF_, E_, h16, ww16, nullptr, nullptr, nullptr, gate16,
        wv16, nullptr, val16);
    // 8. gg16 = gelu(gate16) * val16
    geglu_kernel<<<(M_ * DFF_) / 1024, 256>>>(gate16, val16, gg16);
    // 9. out = x + gg16 @ wout16
    hgemm_kernel<<<dim3(E_ / BN, M_ / BM), 256, TG_SMEM>>>(
        M_, E_, DFF_, gg16, wout16, nullptr, x_p, out, nullptr,
        nullptr, nullptr, nullptr);
}